// round 1
// baseline (speedup 1.0000x reference)
#include <cuda_runtime.h>
#include <math.h>

// ---------------------------------------------------------------------------
// Problem constants
// ---------------------------------------------------------------------------
namespace {
constexpr int Bk = 4;       // batch
constexpr int Tk = 1024;    // seq len
constexpr int INk = 256;    // input dim
constexpr int Dk = 1024;    // model dim
constexpr int Hk = 16;      // heads
constexpr int HDk = 64;     // head dim
constexpr int FFk = 4096;   // ff dim
constexpr int Ck = 10;      // classes
constexpr int Lk = 6;       // layers
constexpr int D3k = 3 * Dk;
constexpr float EPSk = 1e-5f;
}

// ---------------------------------------------------------------------------
// Scratch buffers (static device globals — no allocations allowed)
// ---------------------------------------------------------------------------
__device__ float g_h[Bk * Tk * Dk];            // hidden state (16 MB)
__device__ float g_o[Bk * Tk * Dk];            // attn output concat (16 MB)
__device__ float g_tmp[Bk * Tk * Dk];          // proj output / ff2 output (16 MB)
__device__ float g_qkv[Bk * Tk * D3k];         // qkv (48 MB)
__device__ float g_ff[Bk * Tk * FFk];          // ff intermediate (64 MB)
__device__ float g_scores[(size_t)Bk * Hk * Tk * Tk];  // attn scores (256 MB)

// ---------------------------------------------------------------------------
// Generic NT GEMM: C[M,N] = A[M,K] * W[N,K]^T + bias[N]   (optional ReLU)
// Both operands K-contiguous. M,N multiples of 128, K multiple of 8.
// 256 threads, 128x128 block tile, 8x8 per-thread microtile.
// ---------------------------------------------------------------------------
__global__ __launch_bounds__(256) void gemm_nt_kernel(
    const float* __restrict__ A, int lda,
    const float* __restrict__ W, int ldb,
    const float* __restrict__ bias,
    float* __restrict__ Cc, int ldc,
    int K, int relu)
{
    constexpr int BM = 128, BN = 128, BK = 8;
    __shared__ float As[BK][BM + 4];
    __shared__ float Bs[BK][BN + 4];

    const int tid  = threadIdx.x;
    const int row0 = blockIdx.y * BM;
    const int col0 = blockIdx.x * BN;

    const int lr = tid >> 1;          // 0..127
    const int lc = (tid & 1) * 4;     // 0 or 4
    const float* Ap = A + (size_t)(row0 + lr) * lda + lc;
    const float* Bp = W + (size_t)(col0 + lr) * ldb + lc;

    const int tx = tid & 15;          // 0..15
    const int ty = tid >> 4;          // 0..15

    float acc[8][8] = {};

    for (int k0 = 0; k0 < K; k0 += BK) {
        float4 av = *(const float4*)(Ap + k0);
        float4 bv = *(const float4*)(Bp + k0);
        As[lc + 0][lr] = av.x; As[lc + 1][lr] = av.y;
        As[lc + 2][lr] = av.z; As[lc + 3][lr] = av.w;
        Bs[lc + 0][lr] = bv.x; Bs[lc + 1][lr] = bv.y;
        Bs[lc + 2][lr] = bv.z; Bs[lc + 3][lr] = bv.w;
        __syncthreads();
#pragma unroll
        for (int kk = 0; kk < BK; kk++) {
            float a[8], b[8];
            *(float4*)&a[0] = *(const float4*)&As[kk][ty * 8];
            *(float4*)&a[4] = *(const float4*)&As[kk][ty * 8 + 4];
            *(float4*)&b[0] = *(const float4*)&Bs[kk][tx * 8];
            *(float4*)&b[4] = *(const float4*)&Bs[kk][tx * 8 + 4];
#pragma unroll
            for (int i = 0; i < 8; i++)
#pragma unroll
                for (int j = 0; j < 8; j++)
                    acc[i][j] += a[i] * b[j];
        }
        __syncthreads();
    }

#pragma unroll
    for (int i = 0; i < 8; i++) {
        int r = row0 + ty * 8 + i;
#pragma unroll
        for (int j = 0; j < 8; j += 4) {
            int c = col0 + tx * 8 + j;
            float4 v;
            v.x = acc[i][j + 0] + bias[c + 0];
            v.y = acc[i][j + 1] + bias[c + 1];
            v.z = acc[i][j + 2] + bias[c + 2];
            v.w = acc[i][j + 3] + bias[c + 3];
            if (relu) {
                v.x = fmaxf(v.x, 0.f); v.y = fmaxf(v.y, 0.f);
                v.z = fmaxf(v.z, 0.f); v.w = fmaxf(v.w, 0.f);
            }
            *(float4*)(Cc + (size_t)r * ldc + c) = v;
        }
    }
}

// ---------------------------------------------------------------------------
// Batched QK^T with fused scale + ALiBi epilogue.
// grid: (T/128, T/128, B*H). scores[bh, t, s] = q.k * 0.125 - slope*|t-s|
// ---------------------------------------------------------------------------
__global__ __launch_bounds__(256) void qk_scores_kernel(const float* __restrict__ qkv)
{
    constexpr int BM = 128, BN = 128, BK = 8;
    __shared__ float As[BK][BM + 4];
    __shared__ float Bs[BK][BN + 4];

    const int bh = blockIdx.z;
    const int b = bh / Hk, h = bh % Hk;
    const float* Qb = qkv + (size_t)b * Tk * D3k + h * HDk;
    const float* Kb = Qb + Dk;

    const int tid  = threadIdx.x;
    const int row0 = blockIdx.y * BM;
    const int col0 = blockIdx.x * BN;

    const int lr = tid >> 1;
    const int lc = (tid & 1) * 4;
    const float* Ap = Qb + (size_t)(row0 + lr) * D3k + lc;
    const float* Bp = Kb + (size_t)(col0 + lr) * D3k + lc;

    const int tx = tid & 15;
    const int ty = tid >> 4;

    float acc[8][8] = {};

    for (int k0 = 0; k0 < HDk; k0 += BK) {
        float4 av = *(const float4*)(Ap + k0);
        float4 bv = *(const float4*)(Bp + k0);
        As[lc + 0][lr] = av.x; As[lc + 1][lr] = av.y;
        As[lc + 2][lr] = av.z; As[lc + 3][lr] = av.w;
        Bs[lc + 0][lr] = bv.x; Bs[lc + 1][lr] = bv.y;
        Bs[lc + 2][lr] = bv.z; Bs[lc + 3][lr] = bv.w;
        __syncthreads();
#pragma unroll
        for (int kk = 0; kk < BK; kk++) {
            float a[8], bb[8];
            *(float4*)&a[0]  = *(const float4*)&As[kk][ty * 8];
            *(float4*)&a[4]  = *(const float4*)&As[kk][ty * 8 + 4];
            *(float4*)&bb[0] = *(const float4*)&Bs[kk][tx * 8];
            *(float4*)&bb[4] = *(const float4*)&Bs[kk][tx * 8 + 4];
#pragma unroll
            for (int i = 0; i < 8; i++)
#pragma unroll
                for (int j = 0; j < 8; j++)
                    acc[i][j] += a[i] * bb[j];
        }
        __syncthreads();
    }

    // mean ALiBi slope (matches reference fp32 computation)
    float slope = 0.f;
#pragma unroll
    for (int i = 1; i <= Hk; i++) slope += exp2f(-8.f * (float)i / (float)Hk);
    slope *= (1.f / (float)Hk);
    const float scale = 0.125f;   // 1/sqrt(64)

    float* Sb = g_scores + (size_t)bh * Tk * Tk;
#pragma unroll
    for (int i = 0; i < 8; i++) {
        int r = row0 + ty * 8 + i;
#pragma unroll
        for (int j = 0; j < 8; j += 4) {
            int c = col0 + tx * 8 + j;
            float4 v;
            v.x = acc[i][j + 0] * scale - slope * fabsf((float)(r - (c + 0)));
            v.y = acc[i][j + 1] * scale - slope * fabsf((float)(r - (c + 1)));
            v.z = acc[i][j + 2] * scale - slope * fabsf((float)(r - (c + 2)));
            v.w = acc[i][j + 3] * scale - slope * fabsf((float)(r - (c + 3)));
            *(float4*)(Sb + (size_t)r * Tk + c) = v;
        }
    }
}

// ---------------------------------------------------------------------------
// Row softmax over T=1024. One block (256 threads) per row, 4 elems/thread.
// ---------------------------------------------------------------------------
__global__ __launch_bounds__(256) void softmax_kernel()
{
    __shared__ float red[8];
    const size_t row = blockIdx.x;
    float* p = g_scores + row * (size_t)Tk;
    const int tid = threadIdx.x;

    float4 v = ((const float4*)p)[tid];
    float m = fmaxf(fmaxf(v.x, v.y), fmaxf(v.z, v.w));
#pragma unroll
    for (int o = 16; o; o >>= 1) m = fmaxf(m, __shfl_xor_sync(~0u, m, o));
    if ((tid & 31) == 0) red[tid >> 5] = m;
    __syncthreads();
    m = red[0];
#pragma unroll
    for (int i = 1; i < 8; i++) m = fmaxf(m, red[i]);
    __syncthreads();

    float4 e;
    e.x = expf(v.x - m); e.y = expf(v.y - m);
    e.z = expf(v.z - m); e.w = expf(v.w - m);
    float s = e.x + e.y + e.z + e.w;
#pragma unroll
    for (int o = 16; o; o >>= 1) s += __shfl_xor_sync(~0u, s, o);
    if ((tid & 31) == 0) red[tid >> 5] = s;
    __syncthreads();
    float tot = 0.f;
#pragma unroll
    for (int i = 0; i < 8; i++) tot += red[i];

    float inv = 1.f / tot;
    e.x *= inv; e.y *= inv; e.z *= inv; e.w *= inv;
    ((float4*)p)[tid] = e;
}

// ---------------------------------------------------------------------------
// o[b,t,h*64+n] = sum_s attn[bh,t,s] * v[b,s,h,n].  grid: (T/64, B*H)
// 64x64 tile, BK=16, 256 threads, 4x4 microtile.
// ---------------------------------------------------------------------------
__global__ __launch_bounds__(256) void av_kernel(const float* __restrict__ qkv,
                                                 float* __restrict__ outp)
{
    constexpr int BM = 64, BN = 64, BK = 16;
    __shared__ float As[BK][BM + 4];
    __shared__ float Bs[BK][BN + 4];

    const int bh = blockIdx.y;
    const int b = bh / Hk, h = bh % Hk;
    const int row0 = blockIdx.x * BM;

    const float* Sb = g_scores + (size_t)bh * Tk * Tk;
    const float* Vb = qkv + (size_t)b * Tk * D3k + 2 * Dk + h * HDk;

    const int tid = threadIdx.x;
    const int ar = tid >> 2, ac = (tid & 3) * 4;    // A: 64 rows x 16 cols
    const int br = tid >> 4, bc = (tid & 15) * 4;   // B: 16 rows x 64 cols
    const int tx = tid & 15, ty = tid >> 4;

    float acc[4][4] = {};

    for (int k0 = 0; k0 < Tk; k0 += BK) {
        float4 av = *(const float4*)(Sb + (size_t)(row0 + ar) * Tk + k0 + ac);
        float4 bv = *(const float4*)(Vb + (size_t)(k0 + br) * D3k + bc);
        As[ac + 0][ar] = av.x; As[ac + 1][ar] = av.y;
        As[ac + 2][ar] = av.z; As[ac + 3][ar] = av.w;
        *(float4*)&Bs[br][bc] = bv;
        __syncthreads();
#pragma unroll
        for (int kk = 0; kk < BK; kk++) {
            float a[4], bb[4];
            *(float4*)a  = *(const float4*)&As[kk][ty * 4];
            *(float4*)bb = *(const float4*)&Bs[kk][tx * 4];
#pragma unroll
            for (int i = 0; i < 4; i++)
#pragma unroll
                for (int j = 0; j < 4; j++)
                    acc[i][j] += a[i] * bb[j];
        }
        __syncthreads();
    }

#pragma unroll
    for (int i = 0; i < 4; i++) {
        int t = row0 + ty * 4 + i;
        float4 v = make_float4(acc[i][0], acc[i][1], acc[i][2], acc[i][3]);
        *(float4*)(outp + (size_t)b * Tk * Dk + (size_t)t * Dk + h * HDk + tx * 4) = v;
    }
}

// ---------------------------------------------------------------------------
// h = LN(h + o) * g + b.  One block (256 threads) per row of D=1024.
// ---------------------------------------------------------------------------
__global__ __launch_bounds__(256) void ln_residual_kernel(
    float* __restrict__ h, const float* __restrict__ o,
    const float* __restrict__ gam, const float* __restrict__ bet)
{
    __shared__ float rs[8], rs2[8];
    const size_t row = blockIdx.x;
    float* hp = h + row * Dk;
    const float* op = o + row * Dk;
    const int tid = threadIdx.x;

    float4 hv = ((const float4*)hp)[tid];
    float4 ov = ((const float4*)op)[tid];
    float r0 = hv.x + ov.x, r1 = hv.y + ov.y, r2 = hv.z + ov.z, r3 = hv.w + ov.w;

    float s  = r0 + r1 + r2 + r3;
    float s2 = r0 * r0 + r1 * r1 + r2 * r2 + r3 * r3;
#pragma unroll
    for (int of = 16; of; of >>= 1) {
        s  += __shfl_xor_sync(~0u, s,  of);
        s2 += __shfl_xor_sync(~0u, s2, of);
    }
    if ((tid & 31) == 0) { rs[tid >> 5] = s; rs2[tid >> 5] = s2; }
    __syncthreads();
    float S = 0.f, S2 = 0.f;
#pragma unroll
    for (int i = 0; i < 8; i++) { S += rs[i]; S2 += rs2[i]; }

    const float mu  = S * (1.f / (float)Dk);
    const float var = S2 * (1.f / (float)Dk) - mu * mu;
    const float inv = rsqrtf(var + EPSk);

    float4 gg = ((const float4*)gam)[tid];
    float4 bb = ((const float4*)bet)[tid];
    float4 out;
    out.x = (r0 - mu) * inv * gg.x + bb.x;
    out.y = (r1 - mu) * inv * gg.y + bb.y;
    out.z = (r2 - mu) * inv * gg.z + bb.z;
    out.w = (r3 - mu) * inv * gg.w + bb.w;
    ((float4*)hp)[tid] = out;
}

// ---------------------------------------------------------------------------
// head: out[b,c] = dot(h[b, T-1, :], head_w[c, :]) + head_b[c]. 1 warp each.
// ---------------------------------------------------------------------------
__global__ void head_kernel(const float* __restrict__ h,
                            const float* __restrict__ hw,
                            const float* __restrict__ hb,
                            float* __restrict__ outp)
{
    const int idx = blockIdx.x;     // 0..B*C-1
    const int b = idx / Ck, c = idx % Ck;
    const float* hp = h + ((size_t)b * Tk + (Tk - 1)) * Dk;
    const float* wp = hw + (size_t)c * Dk;
    const int lane = threadIdx.x;
    float s = 0.f;
    for (int i = lane; i < Dk; i += 32) s += hp[i] * wp[i];
#pragma unroll
    for (int o = 16; o; o >>= 1) s += __shfl_xor_sync(~0u, s, o);
    if (lane == 0) outp[idx] = s + hb[c];
}

// ---------------------------------------------------------------------------
// Host orchestration
// ---------------------------------------------------------------------------
extern "C" void kernel_launch(void* const* d_in, const int* in_sizes, int n_in,
                              void* d_out, int out_size)
{
    (void)in_sizes; (void)n_in; (void)out_size;
    const float* x       = (const float*)d_in[0];
    const float* input_w = (const float*)d_in[1];
    const float* input_b = (const float*)d_in[2];
    const float* Wqkv    = (const float*)d_in[3];
    const float* bqkv    = (const float*)d_in[4];
    const float* Wo      = (const float*)d_in[5];
    const float* bo      = (const float*)d_in[6];
    const float* ln1_g   = (const float*)d_in[7];
    const float* ln1_b   = (const float*)d_in[8];
    const float* ln2_g   = (const float*)d_in[9];
    const float* ln2_b   = (const float*)d_in[10];
    const float* W1      = (const float*)d_in[11];
    const float* b1      = (const float*)d_in[12];
    const float* W2      = (const float*)d_in[13];
    const float* b2      = (const float*)d_in[14];
    const float* head_w  = (const float*)d_in[15];
    const float* head_b  = (const float*)d_in[16];
    float* outp = (float*)d_out;

    float *h, *o, *tmp, *qkv, *ffb;
    cudaGetSymbolAddress((void**)&h,   g_h);
    cudaGetSymbolAddress((void**)&o,   g_o);
    cudaGetSymbolAddress((void**)&tmp, g_tmp);
    cudaGetSymbolAddress((void**)&qkv, g_qkv);
    cudaGetSymbolAddress((void**)&ffb, g_ff);

    const int M = Bk * Tk;  // 4096
    dim3 blk(256);

    // input projection: h = x @ input_w^T + input_b
    gemm_nt_kernel<<<dim3(Dk / 128, M / 128), blk>>>(
        x, INk, input_w, INk, input_b, h, Dk, INk, 0);

    for (int l = 0; l < Lk; l++) {
        // qkv
        gemm_nt_kernel<<<dim3(D3k / 128, M / 128), blk>>>(
            h, Dk, Wqkv + (size_t)l * D3k * Dk, Dk, bqkv + (size_t)l * D3k,
            qkv, D3k, Dk, 0);
        // scores = qk^T * scale + alibi
        qk_scores_kernel<<<dim3(Tk / 128, Tk / 128, Bk * Hk), blk>>>(qkv);
        // softmax
        softmax_kernel<<<Bk * Hk * Tk, 256>>>();
        // o = attn @ v
        av_kernel<<<dim3(Tk / 64, Bk * Hk), blk>>>(qkv, o);
        // proj: tmp = o @ Wo^T + bo
        gemm_nt_kernel<<<dim3(Dk / 128, M / 128), blk>>>(
            o, Dk, Wo + (size_t)l * Dk * Dk, Dk, bo + (size_t)l * Dk,
            tmp, Dk, Dk, 0);
        // h = LN(h + tmp)
        ln_residual_kernel<<<M, 256>>>(h, tmp, ln1_g + (size_t)l * Dk, ln1_b + (size_t)l * Dk);
        // ff1 (relu)
        gemm_nt_kernel<<<dim3(FFk / 128, M / 128), blk>>>(
            h, Dk, W1 + (size_t)l * FFk * Dk, Dk, b1 + (size_t)l * FFk,
            ffb, FFk, Dk, 1);
        // ff2
        gemm_nt_kernel<<<dim3(Dk / 128, M / 128), blk>>>(
            ffb, FFk, W2 + (size_t)l * Dk * FFk, FFk, b2 + (size_t)l * Dk,
            tmp, Dk, FFk, 0);
        // h = LN(h + tmp)
        ln_residual_kernel<<<M, 256>>>(h, tmp, ln2_g + (size_t)l * Dk, ln2_b + (size_t)l * Dk);
    }

    head_kernel<<<Bk * Ck, 32>>>(h, head_w, head_b, outp);
}

// round 5
// speedup vs baseline: 1.8413x; 1.8413x over previous
#include <cuda_runtime.h>
#include <cuda_bf16.h>
#include <math.h>
#include <stdint.h>

// ---------------------------------------------------------------------------
// Problem constants
// ---------------------------------------------------------------------------
namespace {
constexpr int Bk = 4;       // batch
constexpr int Tk = 1024;    // seq len
constexpr int INk = 256;    // input dim
constexpr int Dk = 1024;    // model dim
constexpr int Hk = 16;      // heads
constexpr int HDk = 64;     // head dim
constexpr int FFk = 4096;   // ff dim
constexpr int Ck = 10;      // classes
constexpr int Lk = 6;       // layers
constexpr int D3k = 3 * Dk;
constexpr float EPSk = 1e-5f;
}

// ---------------------------------------------------------------------------
// Scratch buffers (static device globals — no allocations allowed)
// ---------------------------------------------------------------------------
__device__ float g_h[Bk * Tk * Dk];
__device__ float g_o[Bk * Tk * Dk];
__device__ float g_tmp[Bk * Tk * Dk];
__device__ float g_qkv[Bk * Tk * D3k];
__device__ float g_ff[Bk * Tk * FFk];
__device__ float g_scores[(size_t)Bk * Hk * Tk * Tk];

// ---------------------------------------------------------------------------
// PTX helpers (sm_80-era features only: ldmatrix + mma.sync — base sm_100 OK)
// ---------------------------------------------------------------------------
__device__ __forceinline__ uint32_t smem_u32(const void* p) {
    uint32_t a;
    asm("{ .reg .u64 t; cvta.to.shared.u64 t, %1; cvt.u32.u64 %0, t; }"
        : "=r"(a) : "l"(p));
    return a;
}

__device__ __forceinline__ void ldmat_x4(uint32_t* r, uint32_t addr) {
    asm volatile("ldmatrix.sync.aligned.m8n8.x4.shared.b16 {%0,%1,%2,%3}, [%4];"
                 : "=r"(r[0]), "=r"(r[1]), "=r"(r[2]), "=r"(r[3]) : "r"(addr));
}

__device__ __forceinline__ void mma16816(float* c, const uint32_t* a,
                                         uint32_t b0, uint32_t b1) {
    asm volatile(
        "mma.sync.aligned.m16n8k16.row.col.f32.bf16.bf16.f32 "
        "{%0,%1,%2,%3}, {%4,%5,%6,%7}, {%8,%9}, {%0,%1,%2,%3};"
        : "+f"(c[0]), "+f"(c[1]), "+f"(c[2]), "+f"(c[3])
        : "r"(a[0]), "r"(a[1]), "r"(a[2]), "r"(a[3]), "r"(b0), "r"(b1));
}

__device__ __forceinline__ void sts128(uint32_t addr, uint4 v) {
    asm volatile("st.shared.v4.b32 [%0], {%1,%2,%3,%4};"
                 :: "r"(addr), "r"(v.x), "r"(v.y), "r"(v.z), "r"(v.w) : "memory");
}

// split 2 floats into bf16 hi pair + bf16 lo pair (packed u32 each)
__device__ __forceinline__ void cvt_hilo2(float a, float b, uint32_t& hi, uint32_t& lo) {
    __nv_bfloat162 h = __floats2bfloat162_rn(a, b);
    float2 hf = __bfloat1622float2(h);
    __nv_bfloat162 l = __floats2bfloat162_rn(a - hf.x, b - hf.y);
    hi = *reinterpret_cast<uint32_t*>(&h);
    lo = *reinterpret_cast<uint32_t*>(&l);
}

// convert 8 floats (two float4, consecutive k) -> 4 hi u32 + 4 lo u32
__device__ __forceinline__ void cvt_hilo8(float4 a, float4 b, uint4& hi, uint4& lo) {
    cvt_hilo2(a.x, a.y, hi.x, lo.x);
    cvt_hilo2(a.z, a.w, hi.y, lo.y);
    cvt_hilo2(b.x, b.y, hi.z, lo.z);
    cvt_hilo2(b.z, b.w, hi.w, lo.w);
}

// ---------------------------------------------------------------------------
// Tensor-core NT GEMM: C[M,N] = A[M,K] * W[N,K]^T + bias (optional ReLU)
// 128x128 tile, BK=32, bf16 hi/lo 3-term split, fp32 register accumulators.
// 8 warps; warp tile 32(m) x 64(n) = 2 x 8 m16n8k16 tiles.
// smem rows stride 40 bf16 (80 B) -> ldmatrix conflict-free.
// ---------------------------------------------------------------------------
namespace { constexpr int SST = 40; }   // smem row stride in bf16

__global__ __launch_bounds__(256) void mma_gemm_nt(
    const float* __restrict__ A, int lda,
    const float* __restrict__ W, int ldb,
    const float* __restrict__ bias,
    float* __restrict__ Cc, int ldc,
    int K, int relu)
{
    __shared__ __align__(16) __nv_bfloat16 sAhi[128 * SST];
    __shared__ __align__(16) __nv_bfloat16 sAlo[128 * SST];
    __shared__ __align__(16) __nv_bfloat16 sBhi[128 * SST];
    __shared__ __align__(16) __nv_bfloat16 sBlo[128 * SST];

    const int tid  = threadIdx.x;
    const int lane = tid & 31;
    const int wid  = tid >> 5;
    const int wm   = wid & 3;        // warp row  (32 rows each)
    const int wn   = wid >> 2;       // warp col  (64 cols each)
    const int row0 = blockIdx.y * 128;
    const int col0 = blockIdx.x * 128;

    const uint32_t aHi = smem_u32(sAhi), aLo = smem_u32(sAlo);
    const uint32_t bHi = smem_u32(sBhi), bLo = smem_u32(sBlo);

    // ---- global load mapping: thread -> one half-row (16 floats) of A and B
    const int grow = tid >> 1;             // 0..127
    const int gcol = (tid & 1) * 16;       // 0 or 16
    const float* Ap = A + (size_t)(row0 + grow) * lda + gcol;
    const float* Bp = W + (size_t)(col0 + grow) * ldb + gcol;
    // smem byte offsets for the two 8-bf16 groups this thread writes
    const uint32_t so0 = (grow * SST + gcol) * 2;
    const uint32_t so1 = so0 + 16;

    // ---- ldmatrix per-lane base offsets (bytes)
    // A: row = wm*32 + (lane&15), k-offset = (lane>>4)*8 bf16
    const uint32_t aRowOff = (uint32_t)((wm * 32 + (lane & 15)) * SST * 2 + (lane >> 4) * 16);
    // B: n = wn*64 + ((lane>>4)<<3) + (lane&7), k-offset = ((lane>>3)&1)*8 bf16
    const uint32_t bRowOff = (uint32_t)(((wn * 64 + ((lane >> 4) << 3) + (lane & 7)) * SST) * 2
                                        + ((lane >> 3) & 1) * 16);

    float acc[2][8][4];
#pragma unroll
    for (int i = 0; i < 2; i++)
#pragma unroll
        for (int j = 0; j < 8; j++)
#pragma unroll
            for (int q = 0; q < 4; q++) acc[i][j][q] = 0.f;

    const int nc = K >> 5;          // K-chunks of 32
    float4 ra[4], rb[4];
#pragma unroll
    for (int i = 0; i < 4; i++) {
        ra[i] = *(const float4*)(Ap + i * 4);
        rb[i] = *(const float4*)(Bp + i * 4);
    }

    for (int c = 0; c < nc; c++) {
        __syncthreads();            // previous chunk's mma reads done
        {
            uint4 hi, lo;
            cvt_hilo8(ra[0], ra[1], hi, lo);
            sts128(aHi + so0, hi); sts128(aLo + so0, lo);
            cvt_hilo8(ra[2], ra[3], hi, lo);
            sts128(aHi + so1, hi); sts128(aLo + so1, lo);
            cvt_hilo8(rb[0], rb[1], hi, lo);
            sts128(bHi + so0, hi); sts128(bLo + so0, lo);
            cvt_hilo8(rb[2], rb[3], hi, lo);
            sts128(bHi + so1, hi); sts128(bLo + so1, lo);
        }
        __syncthreads();

        // prefetch next chunk (overlaps with mma below)
        if (c + 1 < nc) {
            const float* Ap2 = Ap + (c + 1) * 32;
            const float* Bp2 = Bp + (c + 1) * 32;
#pragma unroll
            for (int i = 0; i < 4; i++) {
                ra[i] = *(const float4*)(Ap2 + i * 4);
                rb[i] = *(const float4*)(Bp2 + i * 4);
            }
        }

#pragma unroll
        for (int ks = 0; ks < 2; ks++) {
            const uint32_t kb = ks * 32;        // 16 bf16 = 32 bytes
            uint32_t Ah[2][4], Al[2][4];
#pragma unroll
            for (int mt = 0; mt < 2; mt++) {
                ldmat_x4(Ah[mt], aHi + aRowOff + mt * (16 * SST * 2) + kb);
                ldmat_x4(Al[mt], aLo + aRowOff + mt * (16 * SST * 2) + kb);
            }
#pragma unroll
            for (int pr = 0; pr < 4; pr++) {    // pairs of n-tiles
                uint32_t Bh[4], Bl[4];
                ldmat_x4(Bh, bHi + bRowOff + pr * (16 * SST * 2) + kb);
                ldmat_x4(Bl, bLo + bRowOff + pr * (16 * SST * 2) + kb);
#pragma unroll
                for (int sb = 0; sb < 2; sb++) {
                    const int nt = pr * 2 + sb;
#pragma unroll
                    for (int mt = 0; mt < 2; mt++) {
                        mma16816(acc[mt][nt], Ah[mt], Bh[sb * 2], Bh[sb * 2 + 1]);
                        mma16816(acc[mt][nt], Ah[mt], Bl[sb * 2], Bl[sb * 2 + 1]);
                        mma16816(acc[mt][nt], Al[mt], Bh[sb * 2], Bh[sb * 2 + 1]);
                    }
                }
            }
        }
    }

    // ---- epilogue
    const int erow = lane >> 2;
    const int ecol = (lane & 3) * 2;
#pragma unroll
    for (int mt = 0; mt < 2; mt++) {
        const int r = row0 + wm * 32 + mt * 16 + erow;
#pragma unroll
        for (int nt = 0; nt < 8; nt++) {
            const int cc = col0 + wn * 64 + nt * 8 + ecol;
            float2 bv = *(const float2*)(bias + cc);
            float2 v0, v1;
            v0.x = acc[mt][nt][0] + bv.x;  v0.y = acc[mt][nt][1] + bv.y;
            v1.x = acc[mt][nt][2] + bv.x;  v1.y = acc[mt][nt][3] + bv.y;
            if (relu) {
                v0.x = fmaxf(v0.x, 0.f); v0.y = fmaxf(v0.y, 0.f);
                v1.x = fmaxf(v1.x, 0.f); v1.y = fmaxf(v1.y, 0.f);
            }
            *(float2*)(Cc + (size_t)r * ldc + cc)       = v0;
            *(float2*)(Cc + (size_t)(r + 8) * ldc + cc) = v1;
        }
    }
}

// ---------------------------------------------------------------------------
// Batched QK^T with fused scale + ALiBi epilogue (fp32 FFMA)
// ---------------------------------------------------------------------------
__global__ __launch_bounds__(256) void qk_scores_kernel(const float* __restrict__ qkv)
{
    constexpr int BM = 128, BN = 128, BK = 8;
    __shared__ float As[BK][BM + 4];
    __shared__ float Bs[BK][BN + 4];

    const int bh = blockIdx.z;
    const int b = bh / Hk, h = bh % Hk;
    const float* Qb = qkv + (size_t)b * Tk * D3k + h * HDk;
    const float* Kb = Qb + Dk;

    const int tid  = threadIdx.x;
    const int row0 = blockIdx.y * BM;
    const int col0 = blockIdx.x * BN;

    const int lr = tid >> 1;
    const int lc = (tid & 1) * 4;
    const float* Ap = Qb + (size_t)(row0 + lr) * D3k + lc;
    const float* Bp = Kb + (size_t)(col0 + lr) * D3k + lc;

    const int tx = tid & 15;
    const int ty = tid >> 4;

    float acc[8][8] = {};

    for (int k0 = 0; k0 < HDk; k0 += BK) {
        float4 av = *(const float4*)(Ap + k0);
        float4 bv = *(const float4*)(Bp + k0);
        As[lc + 0][lr] = av.x; As[lc + 1][lr] = av.y;
        As[lc + 2][lr] = av.z; As[lc + 3][lr] = av.w;
        Bs[lc + 0][lr] = bv.x; Bs[lc + 1][lr] = bv.y;
        Bs[lc + 2][lr] = bv.z; Bs[lc + 3][lr] = bv.w;
        __syncthreads();
#pragma unroll
        for (int kk = 0; kk < BK; kk++) {
            float a[8], bb[8];
            *(float4*)&a[0]  = *(const float4*)&As[kk][ty * 8];
            *(float4*)&a[4]  = *(const float4*)&As[kk][ty * 8 + 4];
            *(float4*)&bb[0] = *(const float4*)&Bs[kk][tx * 8];
            *(float4*)&bb[4] = *(const float4*)&Bs[kk][tx * 8 + 4];
#pragma unroll
            for (int i = 0; i < 8; i++)
#pragma unroll
                for (int j = 0; j < 8; j++)
                    acc[i][j] += a[i] * bb[j];
        }
        __syncthreads();
    }

    float slope = 0.f;
#pragma unroll
    for (int i = 1; i <= Hk; i++) slope += exp2f(-8.f * (float)i / (float)Hk);
    slope *= (1.f / (float)Hk);
    const float scale = 0.125f;

    float* Sb = g_scores + (size_t)bh * Tk * Tk;
#pragma unroll
    for (int i = 0; i < 8; i++) {
        int r = row0 + ty * 8 + i;
#pragma unroll
        for (int j = 0; j < 8; j += 4) {
            int c = col0 + tx * 8 + j;
            float4 v;
            v.x = acc[i][j + 0] * scale - slope * fabsf((float)(r - (c + 0)));
            v.y = acc[i][j + 1] * scale - slope * fabsf((float)(r - (c + 1)));
            v.z = acc[i][j + 2] * scale - slope * fabsf((float)(r - (c + 2)));
            v.w = acc[i][j + 3] * scale - slope * fabsf((float)(r - (c + 3)));
            *(float4*)(Sb + (size_t)r * Tk + c) = v;
        }
    }
}

// ---------------------------------------------------------------------------
// Row softmax over T=1024
// ---------------------------------------------------------------------------
__global__ __launch_bounds__(256) void softmax_kernel()
{
    __shared__ float red[8];
    const size_t row = blockIdx.x;
    float* p = g_scores + row * (size_t)Tk;
    const int tid = threadIdx.x;

    float4 v = ((const float4*)p)[tid];
    float m = fmaxf(fmaxf(v.x, v.y), fmaxf(v.z, v.w));
#pragma unroll
    for (int o = 16; o; o >>= 1) m = fmaxf(m, __shfl_xor_sync(~0u, m, o));
    if ((tid & 31) == 0) red[tid >> 5] = m;
    __syncthreads();
    m = red[0];
#pragma unroll
    for (int i = 1; i < 8; i++) m = fmaxf(m, red[i]);
    __syncthreads();

    float4 e;
    e.x = expf(v.x - m); e.y = expf(v.y - m);
    e.z = expf(v.z - m); e.w = expf(v.w - m);
    float s = e.x + e.y + e.z + e.w;
#pragma unroll
    for (int o = 16; o; o >>= 1) s += __shfl_xor_sync(~0u, s, o);
    if ((tid & 31) == 0) red[tid >> 5] = s;
    __syncthreads();
    float tot = 0.f;
#pragma unroll
    for (int i = 0; i < 8; i++) tot += red[i];

    float inv = 1.f / tot;
    e.x *= inv; e.y *= inv; e.z *= inv; e.w *= inv;
    ((float4*)p)[tid] = e;
}

// ---------------------------------------------------------------------------
// o = attn @ v   (fp32 FFMA)
// ---------------------------------------------------------------------------
__global__ __launch_bounds__(256) void av_kernel(const float* __restrict__ qkv,
                                                 float* __restrict__ outp)
{
    constexpr int BM = 64, BN = 64, BK = 16;
    __shared__ float As[BK][BM + 4];
    __shared__ float Bs[BK][BN + 4];

    const int bh = blockIdx.y;
    const int b = bh / Hk, h = bh % Hk;
    const int row0 = blockIdx.x * BM;

    const float* Sb = g_scores + (size_t)bh * Tk * Tk;
    const float* Vb = qkv + (size_t)b * Tk * D3k + 2 * Dk + h * HDk;

    const int tid = threadIdx.x;
    const int ar = tid >> 2, ac = (tid & 3) * 4;
    const int br = tid >> 4, bc = (tid & 15) * 4;
    const int tx = tid & 15, ty = tid >> 4;

    float acc[4][4] = {};

    for (int k0 = 0; k0 < Tk; k0 += BK) {
        float4 av = *(const float4*)(Sb + (size_t)(row0 + ar) * Tk + k0 + ac);
        float4 bv = *(const float4*)(Vb + (size_t)(k0 + br) * D3k + bc);
        As[ac + 0][ar] = av.x; As[ac + 1][ar] = av.y;
        As[ac + 2][ar] = av.z; As[ac + 3][ar] = av.w;
        *(float4*)&Bs[br][bc] = bv;
        __syncthreads();
#pragma unroll
        for (int kk = 0; kk < BK; kk++) {
            float a[4], bb[4];
            *(float4*)a  = *(const float4*)&As[kk][ty * 4];
            *(float4*)bb = *(const float4*)&Bs[kk][tx * 4];
#pragma unroll
            for (int i = 0; i < 4; i++)
#pragma unroll
                for (int j = 0; j < 4; j++)
                    acc[i][j] += a[i] * bb[j];
        }
        __syncthreads();
    }

#pragma unroll
    for (int i = 0; i < 4; i++) {
        int t = row0 + ty * 4 + i;
        float4 v = make_float4(acc[i][0], acc[i][1], acc[i][2], acc[i][3]);
        *(float4*)(outp + (size_t)b * Tk * Dk + (size_t)t * Dk + h * HDk + tx * 4) = v;
    }
}

// ---------------------------------------------------------------------------
// h = LN(h + o) * g + b
// ---------------------------------------------------------------------------
__global__ __launch_bounds__(256) void ln_residual_kernel(
    float* __restrict__ h, const float* __restrict__ o,
    const float* __restrict__ gam, const float* __restrict__ bet)
{
    __shared__ float rs[8], rs2[8];
    const size_t row = blockIdx.x;
    float* hp = h + row * Dk;
    const float* op = o + row * Dk;
    const int tid = threadIdx.x;

    float4 hv = ((const float4*)hp)[tid];
    float4 ov = ((const float4*)op)[tid];
    float r0 = hv.x + ov.x, r1 = hv.y + ov.y, r2 = hv.z + ov.z, r3 = hv.w + ov.w;

    float s  = r0 + r1 + r2 + r3;
    float s2 = r0 * r0 + r1 * r1 + r2 * r2 + r3 * r3;
#pragma unroll
    for (int of = 16; of; of >>= 1) {
        s  += __shfl_xor_sync(~0u, s,  of);
        s2 += __shfl_xor_sync(~0u, s2, of);
    }
    if ((tid & 31) == 0) { rs[tid >> 5] = s; rs2[tid >> 5] = s2; }
    __syncthreads();
    float S = 0.f, S2 = 0.f;
#pragma unroll
    for (int i = 0; i < 8; i++) { S += rs[i]; S2 += rs2[i]; }

    const float mu  = S * (1.f / (float)Dk);
    const float var = S2 * (1.f / (float)Dk) - mu * mu;
    const float inv = rsqrtf(var + EPSk);

    float4 gg = ((const float4*)gam)[tid];
    float4 bb = ((const float4*)bet)[tid];
    float4 out;
    out.x = (r0 - mu) * inv * gg.x + bb.x;
    out.y = (r1 - mu) * inv * gg.y + bb.y;
    out.z = (r2 - mu) * inv * gg.z + bb.z;
    out.w = (r3 - mu) * inv * gg.w + bb.w;
    ((float4*)hp)[tid] = out;
}

// ---------------------------------------------------------------------------
// head
// ---------------------------------------------------------------------------
__global__ void head_kernel(const float* __restrict__ h,
                            const float* __restrict__ hw,
                            const float* __restrict__ hb,
                            float* __restrict__ outp)
{
    const int idx = blockIdx.x;
    const int b = idx / Ck, c = idx % Ck;
    const float* hp = h + ((size_t)b * Tk + (Tk - 1)) * Dk;
    const float* wp = hw + (size_t)c * Dk;
    const int lane = threadIdx.x;
    float s = 0.f;
    for (int i = lane; i < Dk; i += 32) s += hp[i] * wp[i];
#pragma unroll
    for (int o = 16; o; o >>= 1) s += __shfl_xor_sync(~0u, s, o);
    if (lane == 0) outp[idx] = s + hb[c];
}

// ---------------------------------------------------------------------------
// Host orchestration
// ---------------------------------------------------------------------------
extern "C" void kernel_launch(void* const* d_in, const int* in_sizes, int n_in,
                              void* d_out, int out_size)
{
    (void)in_sizes; (void)n_in; (void)out_size;
    const float* x       = (const float*)d_in[0];
    const float* input_w = (const float*)d_in[1];
    const float* input_b = (const float*)d_in[2];
    const float* Wqkv    = (const float*)d_in[3];
    const float* bqkv    = (const float*)d_in[4];
    const float* Wo      = (const float*)d_in[5];
    const float* bo      = (const float*)d_in[6];
    const float* ln1_g   = (const float*)d_in[7];
    const float* ln1_b   = (const float*)d_in[8];
    const float* ln2_g   = (const float*)d_in[9];
    const float* ln2_b   = (const float*)d_in[10];
    const float* W1      = (const float*)d_in[11];
    const float* b1      = (const float*)d_in[12];
    const float* W2      = (const float*)d_in[13];
    const float* b2      = (const float*)d_in[14];
    const float* head_w  = (const float*)d_in[15];
    const float* head_b  = (const float*)d_in[16];
    float* outp = (float*)d_out;

    float *h, *o, *tmp, *qkv, *ffb;
    cudaGetSymbolAddress((void**)&h,   g_h);
    cudaGetSymbolAddress((void**)&o,   g_o);
    cudaGetSymbolAddress((void**)&tmp, g_tmp);
    cudaGetSymbolAddress((void**)&qkv, g_qkv);
    cudaGetSymbolAddress((void**)&ffb, g_ff);

    const int M = Bk * Tk;  // 4096
    dim3 blk(256);

    // input projection
    mma_gemm_nt<<<dim3(Dk / 128, M / 128), blk>>>(
        x, INk, input_w, INk, input_b, h, Dk, INk, 0);

    for (int l = 0; l < Lk; l++) {
        mma_gemm_nt<<<dim3(D3k / 128, M / 128), blk>>>(
            h, Dk, Wqkv + (size_t)l * D3k * Dk, Dk, bqkv + (size_t)l * D3k,
            qkv, D3k, Dk, 0);
        qk_scores_kernel<<<dim3(Tk / 128, Tk / 128, Bk * Hk), blk>>>(qkv);
        softmax_kernel<<<Bk * Hk * Tk, 256>>>();
        av_kernel<<<dim3(Tk / 64, Bk * Hk), blk>>>(qkv, o);
        mma_gemm_nt<<<dim3(Dk / 128, M / 128), blk>>>(
            o, Dk, Wo + (size_t)l * Dk * Dk, Dk, bo + (size_t)l * Dk,
            tmp, Dk, Dk, 0);
        ln_residual_kernel<<<M, 256>>>(h, tmp, ln1_g + (size_t)l * Dk, ln1_b + (size_t)l * Dk);
        mma_gemm_nt<<<dim3(FFk / 128, M / 128), blk>>>(
            h, Dk, W1 + (size_t)l * FFk * Dk, Dk, b1 + (size_t)l * FFk,
            ffb, FFk, Dk, 1);
        mma_gemm_nt<<<dim3(Dk / 128, M / 128), blk>>>(
            ffb, FFk, W2 + (size_t)l * Dk * FFk, FFk, b2 + (size_t)l * Dk,
            tmp, Dk, FFk, 0);
        ln_residual_kernel<<<M, 256>>>(h, tmp, ln2_g + (size_t)l * Dk, ln2_b + (size_t)l * Dk);
    }

    head_kernel<<<Bk * Ck, 32>>>(h, head_w, head_b, outp);
}

// round 6
// speedup vs baseline: 2.2714x; 1.2336x over previous
#include <cuda_runtime.h>
#include <cuda_bf16.h>
#include <math.h>
#include <stdint.h>

// ---------------------------------------------------------------------------
// Problem constants
// ---------------------------------------------------------------------------
namespace {
constexpr int Bk = 4;       // batch
constexpr int Tk = 1024;    // seq len
constexpr int INk = 256;    // input dim
constexpr int Dk = 1024;    // model dim
constexpr int Hk = 16;      // heads
constexpr int HDk = 64;     // head dim
constexpr int FFk = 4096;   // ff dim
constexpr int Ck = 10;      // classes
constexpr int Lk = 6;       // layers
constexpr int D3k = 3 * Dk;
constexpr float EPSk = 1e-5f;
}

// ---------------------------------------------------------------------------
// Scratch buffers (static device globals — no allocations allowed)
// ---------------------------------------------------------------------------
__device__ float g_h[Bk * Tk * Dk];
__device__ float g_o[Bk * Tk * Dk];
__device__ float g_tmp[Bk * Tk * Dk];
__device__ float g_qkv[Bk * Tk * D3k];
__device__ float g_ff[Bk * Tk * FFk];

// ---------------------------------------------------------------------------
// PTX helpers (sm_80-era features only: ldmatrix + mma.sync — base sm_100 OK)
// ---------------------------------------------------------------------------
__device__ __forceinline__ uint32_t smem_u32(const void* p) {
    uint32_t a;
    asm("{ .reg .u64 t; cvta.to.shared.u64 t, %1; cvt.u32.u64 %0, t; }"
        : "=r"(a) : "l"(p));
    return a;
}

__device__ __forceinline__ void ldmat_x4(uint32_t* r, uint32_t addr) {
    asm volatile("ldmatrix.sync.aligned.m8n8.x4.shared.b16 {%0,%1,%2,%3}, [%4];"
                 : "=r"(r[0]), "=r"(r[1]), "=r"(r[2]), "=r"(r[3]) : "r"(addr));
}

__device__ __forceinline__ void ldmat_x4_t(uint32_t* r, uint32_t addr) {
    asm volatile("ldmatrix.sync.aligned.m8n8.x4.trans.shared.b16 {%0,%1,%2,%3}, [%4];"
                 : "=r"(r[0]), "=r"(r[1]), "=r"(r[2]), "=r"(r[3]) : "r"(addr));
}

__device__ __forceinline__ void mma16816(float* c, const uint32_t* a,
                                         uint32_t b0, uint32_t b1) {
    asm volatile(
        "mma.sync.aligned.m16n8k16.row.col.f32.bf16.bf16.f32 "
        "{%0,%1,%2,%3}, {%4,%5,%6,%7}, {%8,%9}, {%0,%1,%2,%3};"
        : "+f"(c[0]), "+f"(c[1]), "+f"(c[2]), "+f"(c[3])
        : "r"(a[0]), "r"(a[1]), "r"(a[2]), "r"(a[3]), "r"(b0), "r"(b1));
}

__device__ __forceinline__ void sts128(uint32_t addr, uint4 v) {
    asm volatile("st.shared.v4.b32 [%0], {%1,%2,%3,%4};"
                 :: "r"(addr), "r"(v.x), "r"(v.y), "r"(v.z), "r"(v.w) : "memory");
}

// split 2 floats into bf16 hi pair + bf16 lo pair (packed u32 each)
__device__ __forceinline__ void cvt_hilo2(float a, float b, uint32_t& hi, uint32_t& lo) {
    __nv_bfloat162 h = __floats2bfloat162_rn(a, b);
    float2 hf = __bfloat1622float2(h);
    __nv_bfloat162 l = __floats2bfloat162_rn(a - hf.x, b - hf.y);
    hi = *reinterpret_cast<uint32_t*>(&h);
    lo = *reinterpret_cast<uint32_t*>(&l);
}

// convert 8 floats (two float4, consecutive k) -> 4 hi u32 + 4 lo u32
__device__ __forceinline__ void cvt_hilo8(float4 a, float4 b, uint4& hi, uint4& lo) {
    cvt_hilo2(a.x, a.y, hi.x, lo.x);
    cvt_hilo2(a.z, a.w, hi.y, lo.y);
    cvt_hilo2(b.x, b.y, hi.z, lo.z);
    cvt_hilo2(b.z, b.w, hi.w, lo.w);
}

// ---------------------------------------------------------------------------
// Tensor-core NT GEMM: C[M,N] = A[M,K] * W[N,K]^T + bias (optional ReLU)
// 128x128 tile, BK=32, bf16 hi/lo 3-term split, fp32 register accumulators.
// ---------------------------------------------------------------------------
namespace { constexpr int SST = 40; }   // smem row stride in bf16

__global__ __launch_bounds__(256) void mma_gemm_nt(
    const float* __restrict__ A, int lda,
    const float* __restrict__ W, int ldb,
    const float* __restrict__ bias,
    float* __restrict__ Cc, int ldc,
    int K, int relu)
{
    __shared__ __align__(16) __nv_bfloat16 sAhi[128 * SST];
    __shared__ __align__(16) __nv_bfloat16 sAlo[128 * SST];
    __shared__ __align__(16) __nv_bfloat16 sBhi[128 * SST];
    __shared__ __align__(16) __nv_bfloat16 sBlo[128 * SST];

    const int tid  = threadIdx.x;
    const int lane = tid & 31;
    const int wid  = tid >> 5;
    const int wm   = wid & 3;
    const int wn   = wid >> 2;
    const int row0 = blockIdx.y * 128;
    const int col0 = blockIdx.x * 128;

    const uint32_t aHi = smem_u32(sAhi), aLo = smem_u32(sAlo);
    const uint32_t bHi = smem_u32(sBhi), bLo = smem_u32(sBlo);

    const int grow = tid >> 1;
    const int gcol = (tid & 1) * 16;
    const float* Ap = A + (size_t)(row0 + grow) * lda + gcol;
    const float* Bp = W + (size_t)(col0 + grow) * ldb + gcol;
    const uint32_t so0 = (grow * SST + gcol) * 2;
    const uint32_t so1 = so0 + 16;

    const uint32_t aRowOff = (uint32_t)((wm * 32 + (lane & 15)) * SST * 2 + (lane >> 4) * 16);
    const uint32_t bRowOff = (uint32_t)(((wn * 64 + ((lane >> 4) << 3) + (lane & 7)) * SST) * 2
                                        + ((lane >> 3) & 1) * 16);

    float acc[2][8][4];
#pragma unroll
    for (int i = 0; i < 2; i++)
#pragma unroll
        for (int j = 0; j < 8; j++)
#pragma unroll
            for (int q = 0; q < 4; q++) acc[i][j][q] = 0.f;

    const int nc = K >> 5;
    float4 ra[4], rb[4];
#pragma unroll
    for (int i = 0; i < 4; i++) {
        ra[i] = *(const float4*)(Ap + i * 4);
        rb[i] = *(const float4*)(Bp + i * 4);
    }

    for (int c = 0; c < nc; c++) {
        __syncthreads();
        {
            uint4 hi, lo;
            cvt_hilo8(ra[0], ra[1], hi, lo);
            sts128(aHi + so0, hi); sts128(aLo + so0, lo);
            cvt_hilo8(ra[2], ra[3], hi, lo);
            sts128(aHi + so1, hi); sts128(aLo + so1, lo);
            cvt_hilo8(rb[0], rb[1], hi, lo);
            sts128(bHi + so0, hi); sts128(bLo + so0, lo);
            cvt_hilo8(rb[2], rb[3], hi, lo);
            sts128(bHi + so1, hi); sts128(bLo + so1, lo);
        }
        __syncthreads();

        if (c + 1 < nc) {
            const float* Ap2 = Ap + (c + 1) * 32;
            const float* Bp2 = Bp + (c + 1) * 32;
#pragma unroll
            for (int i = 0; i < 4; i++) {
                ra[i] = *(const float4*)(Ap2 + i * 4);
                rb[i] = *(const float4*)(Bp2 + i * 4);
            }
        }

#pragma unroll
        for (int ks = 0; ks < 2; ks++) {
            const uint32_t kb = ks * 32;
            uint32_t Ah[2][4], Al[2][4];
#pragma unroll
            for (int mt = 0; mt < 2; mt++) {
                ldmat_x4(Ah[mt], aHi + aRowOff + mt * (16 * SST * 2) + kb);
                ldmat_x4(Al[mt], aLo + aRowOff + mt * (16 * SST * 2) + kb);
            }
#pragma unroll
            for (int pr = 0; pr < 4; pr++) {
                uint32_t Bh[4], Bl[4];
                ldmat_x4(Bh, bHi + bRowOff + pr * (16 * SST * 2) + kb);
                ldmat_x4(Bl, bLo + bRowOff + pr * (16 * SST * 2) + kb);
#pragma unroll
                for (int sb = 0; sb < 2; sb++) {
                    const int nt = pr * 2 + sb;
#pragma unroll
                    for (int mt = 0; mt < 2; mt++) {
                        mma16816(acc[mt][nt], Ah[mt], Bh[sb * 2], Bh[sb * 2 + 1]);
                        mma16816(acc[mt][nt], Ah[mt], Bl[sb * 2], Bl[sb * 2 + 1]);
                        mma16816(acc[mt][nt], Al[mt], Bh[sb * 2], Bh[sb * 2 + 1]);
                    }
                }
            }
        }
    }

    const int erow = lane >> 2;
    const int ecol = (lane & 3) * 2;
#pragma unroll
    for (int mt = 0; mt < 2; mt++) {
        const int r = row0 + wm * 32 + mt * 16 + erow;
#pragma unroll
        for (int nt = 0; nt < 8; nt++) {
            const int cc = col0 + wn * 64 + nt * 8 + ecol;
            float2 bv = *(const float2*)(bias + cc);
            float2 v0, v1;
            v0.x = acc[mt][nt][0] + bv.x;  v0.y = acc[mt][nt][1] + bv.y;
            v1.x = acc[mt][nt][2] + bv.x;  v1.y = acc[mt][nt][3] + bv.y;
            if (relu) {
                v0.x = fmaxf(v0.x, 0.f); v0.y = fmaxf(v0.y, 0.f);
                v1.x = fmaxf(v1.x, 0.f); v1.y = fmaxf(v1.y, 0.f);
            }
            *(float2*)(Cc + (size_t)r * ldc + cc)       = v0;
            *(float2*)(Cc + (size_t)(r + 8) * ldc + cc) = v1;
        }
    }
}

// ---------------------------------------------------------------------------
// Fused flash attention: QK^T * scale + alibi -> online softmax -> P·V.
// One CTA = 128 q-rows of one (b,h). 8 warps, warp = 16 q rows.
// K-blocks of 128 keys. All MMAs bf16 hi/lo 3-term.
// smem: Khi/Klo/Vhi/Vlo, each 128 x 72 bf16 (stride 144 B).
// ---------------------------------------------------------------------------
namespace { constexpr int KST = 72; }
static constexpr int FLASH_SMEM = 4 * 128 * KST * 2;   // 73728 B

__global__ __launch_bounds__(256) void flash_attn_kernel(
    const float* __restrict__ qkv, float* __restrict__ outp)
{
    extern __shared__ __align__(16) char fsm[];
    const uint32_t kHi = smem_u32(fsm);
    const uint32_t kLo = kHi + 128 * KST * 2;
    const uint32_t vHi = kLo + 128 * KST * 2;
    const uint32_t vLo = vHi + 128 * KST * 2;

    const int tid  = threadIdx.x;
    const int lane = tid & 31;
    const int w    = tid >> 5;
    const int bh = blockIdx.y;
    const int b = bh >> 4, h = bh & 15;
    const int qrow0 = blockIdx.x * 128;

    const float* Qbase = qkv + (size_t)b * Tk * D3k + h * HDk;
    const float* Kbase = Qbase + Dk;
    const float* Vbase = Qbase + 2 * Dk;

    float slope = 0.f;
#pragma unroll
    for (int i = 1; i <= Hk; i++) slope += exp2f(-0.5f * (float)i);
    slope *= (1.f / (float)Hk);
    const float scale = 0.125f;

    // ---- stage Q (hi/lo) into K smem, pull fragments to registers
    const int grow = tid >> 1;
    const int gcol = (tid & 1) * 32;
    const uint32_t gso = grow * (KST * 2) + gcol * 2;
    {
        const float* qp = Qbase + (size_t)(qrow0 + grow) * D3k + gcol;
#pragma unroll
        for (int j = 0; j < 4; j++) {
            float4 f0 = *(const float4*)(qp + j * 8);
            float4 f1 = *(const float4*)(qp + j * 8 + 4);
            uint4 hi, lo;
            cvt_hilo8(f0, f1, hi, lo);
            sts128(kHi + gso + j * 16, hi);
            sts128(kLo + gso + j * 16, lo);
        }
    }
    __syncthreads();

    uint32_t Qh[4][4], Ql[4][4];
    const uint32_t qOff = (w * 16 + (lane & 15)) * (KST * 2) + (lane >> 4) * 16;
#pragma unroll
    for (int kc = 0; kc < 4; kc++) {
        ldmat_x4(Qh[kc], kHi + qOff + kc * 32);
        ldmat_x4(Ql[kc], kLo + qOff + kc * 32);
    }
    __syncthreads();

    // B-operand offset (K tiles): n-half from lane>>4, k-half from (lane>>3)&1
    const uint32_t bOff = (((lane >> 4) << 3) + (lane & 7)) * (KST * 2) + ((lane >> 3) & 1) * 16;
    // V-operand offset (trans ldmatrix): rows = key, k-half (lane>>3)&1, n-half lane>>4
    const uint32_t vOff = ((lane & 7) + ((lane >> 3) & 1) * 8) * (KST * 2) + (lane >> 4) * 16;

    float Of[8][4];
#pragma unroll
    for (int i = 0; i < 8; i++)
#pragma unroll
        for (int q = 0; q < 4; q++) Of[i][q] = 0.f;
    float m0 = -1e30f, m1 = -1e30f, l0 = 0.f, l1 = 0.f;

    const float r0f = (float)(qrow0 + w * 16 + (lane >> 2));
    const float r1f = r0f + 8.f;

    for (int kb = 0; kb < Tk / 128; kb++) {
        // ---- load K/V block (hi/lo)
        {
            const float* kp = Kbase + (size_t)(kb * 128 + grow) * D3k + gcol;
            const float* vp = Vbase + (size_t)(kb * 128 + grow) * D3k + gcol;
#pragma unroll
            for (int j = 0; j < 4; j++) {
                float4 f0 = *(const float4*)(kp + j * 8);
                float4 f1 = *(const float4*)(kp + j * 8 + 4);
                uint4 hi, lo;
                cvt_hilo8(f0, f1, hi, lo);
                sts128(kHi + gso + j * 16, hi);
                sts128(kLo + gso + j * 16, lo);
                f0 = *(const float4*)(vp + j * 8);
                f1 = *(const float4*)(vp + j * 8 + 4);
                cvt_hilo8(f0, f1, hi, lo);
                sts128(vHi + gso + j * 16, hi);
                sts128(vLo + gso + j * 16, lo);
            }
        }
        __syncthreads();

        // ---- S = Q K^T  (16 n8-tiles of keys)
        float Sf[16][4];
#pragma unroll
        for (int ntp = 0; ntp < 8; ntp++) {
#pragma unroll
            for (int q = 0; q < 4; q++) { Sf[2 * ntp][q] = 0.f; Sf[2 * ntp + 1][q] = 0.f; }
#pragma unroll
            for (int kc = 0; kc < 4; kc++) {
                uint32_t Bh4[4], Bl4[4];
                ldmat_x4(Bh4, kHi + bOff + ntp * (16 * KST * 2) + kc * 32);
                ldmat_x4(Bl4, kLo + bOff + ntp * (16 * KST * 2) + kc * 32);
                mma16816(Sf[2 * ntp],     Qh[kc], Bh4[0], Bh4[1]);
                mma16816(Sf[2 * ntp],     Qh[kc], Bl4[0], Bl4[1]);
                mma16816(Sf[2 * ntp],     Ql[kc], Bh4[0], Bh4[1]);
                mma16816(Sf[2 * ntp + 1], Qh[kc], Bh4[2], Bh4[3]);
                mma16816(Sf[2 * ntp + 1], Qh[kc], Bl4[2], Bl4[3]);
                mma16816(Sf[2 * ntp + 1], Ql[kc], Bh4[2], Bh4[3]);
            }
        }

        // ---- scale + alibi + block max
        float bm0 = -1e30f, bm1 = -1e30f;
#pragma unroll
        for (int t = 0; t < 16; t++) {
            const float c0f = (float)(kb * 128 + t * 8 + (lane & 3) * 2);
            const float c1f = c0f + 1.f;
            Sf[t][0] = Sf[t][0] * scale - slope * fabsf(r0f - c0f);
            Sf[t][1] = Sf[t][1] * scale - slope * fabsf(r0f - c1f);
            Sf[t][2] = Sf[t][2] * scale - slope * fabsf(r1f - c0f);
            Sf[t][3] = Sf[t][3] * scale - slope * fabsf(r1f - c1f);
            bm0 = fmaxf(bm0, fmaxf(Sf[t][0], Sf[t][1]));
            bm1 = fmaxf(bm1, fmaxf(Sf[t][2], Sf[t][3]));
        }
        bm0 = fmaxf(bm0, __shfl_xor_sync(~0u, bm0, 1));
        bm0 = fmaxf(bm0, __shfl_xor_sync(~0u, bm0, 2));
        bm1 = fmaxf(bm1, __shfl_xor_sync(~0u, bm1, 1));
        bm1 = fmaxf(bm1, __shfl_xor_sync(~0u, bm1, 2));

        const float mn0 = fmaxf(m0, bm0), mn1 = fmaxf(m1, bm1);
        const float sc0 = __expf(m0 - mn0), sc1 = __expf(m1 - mn1);
        l0 *= sc0; l1 *= sc1;
#pragma unroll
        for (int nt = 0; nt < 8; nt++) {
            Of[nt][0] *= sc0; Of[nt][1] *= sc0;
            Of[nt][2] *= sc1; Of[nt][3] *= sc1;
        }
        m0 = mn0; m1 = mn1;

#pragma unroll
        for (int t = 0; t < 16; t++) {
            Sf[t][0] = __expf(Sf[t][0] - mn0);
            Sf[t][1] = __expf(Sf[t][1] - mn0);
            Sf[t][2] = __expf(Sf[t][2] - mn1);
            Sf[t][3] = __expf(Sf[t][3] - mn1);
            l0 += Sf[t][0] + Sf[t][1];
            l1 += Sf[t][2] + Sf[t][3];
        }

        // ---- P fragments (A-operand layout, hi/lo)
        uint32_t Ph[8][4], Pl[8][4];
#pragma unroll
        for (int kc = 0; kc < 8; kc++) {
            cvt_hilo2(Sf[2 * kc][0],     Sf[2 * kc][1],     Ph[kc][0], Pl[kc][0]);
            cvt_hilo2(Sf[2 * kc][2],     Sf[2 * kc][3],     Ph[kc][1], Pl[kc][1]);
            cvt_hilo2(Sf[2 * kc + 1][0], Sf[2 * kc + 1][1], Ph[kc][2], Pl[kc][2]);
            cvt_hilo2(Sf[2 * kc + 1][2], Sf[2 * kc + 1][3], Ph[kc][3], Pl[kc][3]);
        }

        // ---- O += P V
#pragma unroll
        for (int ntp = 0; ntp < 4; ntp++) {
#pragma unroll
            for (int kc = 0; kc < 8; kc++) {
                uint32_t Vh4[4], Vl4[4];
                ldmat_x4_t(Vh4, vHi + vOff + kc * (16 * KST * 2) + ntp * 32);
                ldmat_x4_t(Vl4, vLo + vOff + kc * (16 * KST * 2) + ntp * 32);
                mma16816(Of[2 * ntp],     Ph[kc], Vh4[0], Vh4[1]);
                mma16816(Of[2 * ntp],     Ph[kc], Vl4[0], Vl4[1]);
                mma16816(Of[2 * ntp],     Pl[kc], Vh4[0], Vh4[1]);
                mma16816(Of[2 * ntp + 1], Ph[kc], Vh4[2], Vh4[3]);
                mma16816(Of[2 * ntp + 1], Ph[kc], Vl4[2], Vl4[3]);
                mma16816(Of[2 * ntp + 1], Pl[kc], Vh4[2], Vh4[3]);
            }
        }
        __syncthreads();
    }

    // ---- finalize
    l0 += __shfl_xor_sync(~0u, l0, 1);
    l0 += __shfl_xor_sync(~0u, l0, 2);
    l1 += __shfl_xor_sync(~0u, l1, 1);
    l1 += __shfl_xor_sync(~0u, l1, 2);
    const float inv0 = 1.f / l0, inv1 = 1.f / l1;

    const int row0 = qrow0 + w * 16 + (lane >> 2);
    float* ob = outp + (size_t)b * Tk * Dk + h * HDk;
#pragma unroll
    for (int nt = 0; nt < 8; nt++) {
        const int cc = nt * 8 + (lane & 3) * 2;
        float2 v0 = make_float2(Of[nt][0] * inv0, Of[nt][1] * inv0);
        float2 v1 = make_float2(Of[nt][2] * inv1, Of[nt][3] * inv1);
        *(float2*)(ob + (size_t)row0 * Dk + cc)       = v0;
        *(float2*)(ob + (size_t)(row0 + 8) * Dk + cc) = v1;
    }
}

// ---------------------------------------------------------------------------
// h = LN(h + o) * g + b
// ---------------------------------------------------------------------------
__global__ __launch_bounds__(256) void ln_residual_kernel(
    float* __restrict__ h, const float* __restrict__ o,
    const float* __restrict__ gam, const float* __restrict__ bet)
{
    __shared__ float rs[8], rs2[8];
    const size_t row = blockIdx.x;
    float* hp = h + row * Dk;
    const float* op = o + row * Dk;
    const int tid = threadIdx.x;

    float4 hv = ((const float4*)hp)[tid];
    float4 ov = ((const float4*)op)[tid];
    float r0 = hv.x + ov.x, r1 = hv.y + ov.y, r2 = hv.z + ov.z, r3 = hv.w + ov.w;

    float s  = r0 + r1 + r2 + r3;
    float s2 = r0 * r0 + r1 * r1 + r2 * r2 + r3 * r3;
#pragma unroll
    for (int of = 16; of; of >>= 1) {
        s  += __shfl_xor_sync(~0u, s,  of);
        s2 += __shfl_xor_sync(~0u, s2, of);
    }
    if ((tid & 31) == 0) { rs[tid >> 5] = s; rs2[tid >> 5] = s2; }
    __syncthreads();
    float S = 0.f, S2 = 0.f;
#pragma unroll
    for (int i = 0; i < 8; i++) { S += rs[i]; S2 += rs2[i]; }

    const float mu  = S * (1.f / (float)Dk);
    const float var = S2 * (1.f / (float)Dk) - mu * mu;
    const float inv = rsqrtf(var + EPSk);

    float4 gg = ((const float4*)gam)[tid];
    float4 bb = ((const float4*)bet)[tid];
    float4 out;
    out.x = (r0 - mu) * inv * gg.x + bb.x;
    out.y = (r1 - mu) * inv * gg.y + bb.y;
    out.z = (r2 - mu) * inv * gg.z + bb.z;
    out.w = (r3 - mu) * inv * gg.w + bb.w;
    ((float4*)hp)[tid] = out;
}

// ---------------------------------------------------------------------------
// head
// ---------------------------------------------------------------------------
__global__ void head_kernel(const float* __restrict__ h,
                            const float* __restrict__ hw,
                            const float* __restrict__ hb,
                            float* __restrict__ outp)
{
    const int idx = blockIdx.x;
    const int b = idx / Ck, c = idx % Ck;
    const float* hp = h + ((size_t)b * Tk + (Tk - 1)) * Dk;
    const float* wp = hw + (size_t)c * Dk;
    const int lane = threadIdx.x;
    float s = 0.f;
    for (int i = lane; i < Dk; i += 32) s += hp[i] * wp[i];
#pragma unroll
    for (int o = 16; o; o >>= 1) s += __shfl_xor_sync(~0u, s, o);
    if (lane == 0) outp[idx] = s + hb[c];
}

// ---------------------------------------------------------------------------
// Host orchestration
// ---------------------------------------------------------------------------
extern "C" void kernel_launch(void* const* d_in, const int* in_sizes, int n_in,
                              void* d_out, int out_size)
{
    (void)in_sizes; (void)n_in; (void)out_size;
    const float* x       = (const float*)d_in[0];
    const float* input_w = (const float*)d_in[1];
    const float* input_b = (const float*)d_in[2];
    const float* Wqkv    = (const float*)d_in[3];
    const float* bqkv    = (const float*)d_in[4];
    const float* Wo      = (const float*)d_in[5];
    const float* bo      = (const float*)d_in[6];
    const float* ln1_g   = (const float*)d_in[7];
    const float* ln1_b   = (const float*)d_in[8];
    const float* ln2_g   = (const float*)d_in[9];
    const float* ln2_b   = (const float*)d_in[10];
    const float* W1      = (const float*)d_in[11];
    const float* b1      = (const float*)d_in[12];
    const float* W2      = (const float*)d_in[13];
    const float* b2      = (const float*)d_in[14];
    const float* head_w  = (const float*)d_in[15];
    const float* head_b  = (const float*)d_in[16];
    float* outp = (float*)d_out;

    float *h, *o, *tmp, *qkv, *ffb;
    cudaGetSymbolAddress((void**)&h,   g_h);
    cudaGetSymbolAddress((void**)&o,   g_o);
    cudaGetSymbolAddress((void**)&tmp, g_tmp);
    cudaGetSymbolAddress((void**)&qkv, g_qkv);
    cudaGetSymbolAddress((void**)&ffb, g_ff);

    cudaFuncSetAttribute(flash_attn_kernel,
                         cudaFuncAttributeMaxDynamicSharedMemorySize, FLASH_SMEM);

    const int M = Bk * Tk;  // 4096
    dim3 blk(256);

    // input projection
    mma_gemm_nt<<<dim3(Dk / 128, M / 128), blk>>>(
        x, INk, input_w, INk, input_b, h, Dk, INk, 0);

    for (int l = 0; l < Lk; l++) {
        mma_gemm_nt<<<dim3(D3k / 128, M / 128), blk>>>(
            h, Dk, Wqkv + (size_t)l * D3k * Dk, Dk, bqkv + (size_t)l * D3k,
            qkv, D3k, Dk, 0);
        flash_attn_kernel<<<dim3(Tk / 128, Bk * Hk), blk, FLASH_SMEM>>>(qkv, o);
        mma_gemm_nt<<<dim3(Dk / 128, M / 128), blk>>>(
            o, Dk, Wo + (size_t)l * Dk * Dk, Dk, bo + (size_t)l * Dk,
            tmp, Dk, Dk, 0);
        ln_residual_kernel<<<M, 256>>>(h, tmp, ln1_g + (size_t)l * Dk, ln1_b + (size_t)l * Dk);
        mma_gemm_nt<<<dim3(FFk / 128, M / 128), blk>>>(
            h, Dk, W1 + (size_t)l * FFk * Dk, Dk, b1 + (size_t)l * FFk,
            ffb, FFk, Dk, 1);
        mma_gemm_nt<<<dim3(Dk / 128, M / 128), blk>>>(
            ffb, FFk, W2 + (size_t)l * Dk * FFk, FFk, b2 + (size_t)l * Dk,
            tmp, Dk, FFk, 0);
        ln_residual_kernel<<<M, 256>>>(h, tmp, ln2_g + (size_t)l * Dk, ln2_b + (size_t)l * Dk);
    }

    head_kernel<<<Bk * Ck, 32>>>(h, head_w, head_b, outp);
}

// round 7
// speedup vs baseline: 2.5693x; 1.1311x over previous
#include <cuda_runtime.h>
#include <cuda_bf16.h>
#include <math.h>
#include <stdint.h>

// ---------------------------------------------------------------------------
// Problem constants
// ---------------------------------------------------------------------------
namespace {
constexpr int Bk = 4;       // batch
constexpr int Tk = 1024;    // seq len
constexpr int INk = 256;    // input dim
constexpr int Dk = 1024;    // model dim
constexpr int Hk = 16;      // heads
constexpr int HDk = 64;     // head dim
constexpr int FFk = 4096;   // ff dim
constexpr int Ck = 10;      // classes
constexpr int Lk = 6;       // layers
constexpr int D3k = 3 * Dk;
constexpr float EPSk = 1e-5f;
}

// ---------------------------------------------------------------------------
// Scratch buffers (static device globals — no allocations allowed)
// ---------------------------------------------------------------------------
__device__ float g_h[Bk * Tk * Dk];
__device__ float g_tmp[Bk * Tk * Dk];
__device__ float g_qkv[Bk * Tk * D3k];

// hi/lo bf16 activation buffers
__device__ __nv_bfloat16 g_x_hi[Bk * Tk * INk],  g_x_lo[Bk * Tk * INk];
__device__ __nv_bfloat16 g_h_hi[Bk * Tk * Dk],   g_h_lo[Bk * Tk * Dk];
__device__ __nv_bfloat16 g_o_hi[Bk * Tk * Dk],   g_o_lo[Bk * Tk * Dk];
__device__ __nv_bfloat16 g_ff_hi[Bk * Tk * FFk], g_ff_lo[Bk * Tk * FFk];

// hi/lo bf16 weight buffers
__device__ __nv_bfloat16 g_win_hi[Dk * INk],        g_win_lo[Dk * INk];
__device__ __nv_bfloat16 g_wqkv_hi[Lk * D3k * Dk],  g_wqkv_lo[Lk * D3k * Dk];
__device__ __nv_bfloat16 g_wo_hi[Lk * Dk * Dk],     g_wo_lo[Lk * Dk * Dk];
__device__ __nv_bfloat16 g_w1_hi[Lk * FFk * Dk],    g_w1_lo[Lk * FFk * Dk];
__device__ __nv_bfloat16 g_w2_hi[Lk * Dk * FFk],    g_w2_lo[Lk * Dk * FFk];

// ---------------------------------------------------------------------------
// PTX helpers (sm_80-era features only — compile on base sm_100)
// ---------------------------------------------------------------------------
__device__ __forceinline__ uint32_t smem_u32(const void* p) {
    uint32_t a;
    asm("{ .reg .u64 t; cvta.to.shared.u64 t, %1; cvt.u32.u64 %0, t; }"
        : "=r"(a) : "l"(p));
    return a;
}

__device__ __forceinline__ void ldmat_x4(uint32_t* r, uint32_t addr) {
    asm volatile("ldmatrix.sync.aligned.m8n8.x4.shared.b16 {%0,%1,%2,%3}, [%4];"
                 : "=r"(r[0]), "=r"(r[1]), "=r"(r[2]), "=r"(r[3]) : "r"(addr));
}

__device__ __forceinline__ void ldmat_x4_t(uint32_t* r, uint32_t addr) {
    asm volatile("ldmatrix.sync.aligned.m8n8.x4.trans.shared.b16 {%0,%1,%2,%3}, [%4];"
                 : "=r"(r[0]), "=r"(r[1]), "=r"(r[2]), "=r"(r[3]) : "r"(addr));
}

__device__ __forceinline__ void mma16816(float* c, const uint32_t* a,
                                         uint32_t b0, uint32_t b1) {
    asm volatile(
        "mma.sync.aligned.m16n8k16.row.col.f32.bf16.bf16.f32 "
        "{%0,%1,%2,%3}, {%4,%5,%6,%7}, {%8,%9}, {%0,%1,%2,%3};"
        : "+f"(c[0]), "+f"(c[1]), "+f"(c[2]), "+f"(c[3])
        : "r"(a[0]), "r"(a[1]), "r"(a[2]), "r"(a[3]), "r"(b0), "r"(b1));
}

__device__ __forceinline__ void sts128(uint32_t addr, uint4 v) {
    asm volatile("st.shared.v4.b32 [%0], {%1,%2,%3,%4};"
                 :: "r"(addr), "r"(v.x), "r"(v.y), "r"(v.z), "r"(v.w) : "memory");
}

__device__ __forceinline__ void cp_async16(uint32_t saddr, const void* gptr) {
    asm volatile("cp.async.cg.shared.global [%0], [%1], 16;"
                 :: "r"(saddr), "l"(gptr) : "memory");
}
#define CP_COMMIT() asm volatile("cp.async.commit_group;" ::: "memory")
#define CP_WAIT1()  asm volatile("cp.async.wait_group 1;" ::: "memory")
#define CP_WAIT0()  asm volatile("cp.async.wait_group 0;" ::: "memory")

// split 2 floats into bf16 hi pair + bf16 lo pair (packed u32 each)
__device__ __forceinline__ void cvt_hilo2(float a, float b, uint32_t& hi, uint32_t& lo) {
    __nv_bfloat162 h = __floats2bfloat162_rn(a, b);
    float2 hf = __bfloat1622float2(h);
    __nv_bfloat162 l = __floats2bfloat162_rn(a - hf.x, b - hf.y);
    hi = *reinterpret_cast<uint32_t*>(&h);
    lo = *reinterpret_cast<uint32_t*>(&l);
}

__device__ __forceinline__ void cvt_hilo8(float4 a, float4 b, uint4& hi, uint4& lo) {
    cvt_hilo2(a.x, a.y, hi.x, lo.x);
    cvt_hilo2(a.z, a.w, hi.y, lo.y);
    cvt_hilo2(b.x, b.y, hi.z, lo.z);
    cvt_hilo2(b.z, b.w, hi.w, lo.w);
}

// ---------------------------------------------------------------------------
// Elementwise fp32 -> bf16 hi/lo conversion (for weights + x)
// ---------------------------------------------------------------------------
__global__ __launch_bounds__(256) void cvt_hl_kernel(
    const float* __restrict__ src, __nv_bfloat16* __restrict__ hi,
    __nv_bfloat16* __restrict__ lo, int n)
{
    const int i = (blockIdx.x * 256 + threadIdx.x) * 4;
    if (i >= n) return;
    float4 v = *(const float4*)(src + i);
    uint32_t h0, l0, h1, l1;
    cvt_hilo2(v.x, v.y, h0, l0);
    cvt_hilo2(v.z, v.w, h1, l1);
    *(uint2*)(hi + i) = make_uint2(h0, h1);
    *(uint2*)(lo + i) = make_uint2(l0, l1);
}

// ---------------------------------------------------------------------------
// bf16 hi/lo NT GEMM: C = A * W^T + bias, cp.async double-buffered.
// A,W given as separate hi/lo bf16 row-major [rows, K] arrays.
// 128x128 tile, BK=32, 3-term split, fp32 accum.
// flags: 1=relu, 2=write fp32 C, 4=write hi/lo C
// ---------------------------------------------------------------------------
namespace {
constexpr int SST = 40;                        // smem row stride (bf16)
constexpr int ARR_B = 128 * SST * 2;           // 10240 bytes per array
constexpr int STAGE_B = 4 * ARR_B;             // 40960 bytes per stage
}
static constexpr int GEMM_SMEM = 2 * STAGE_B;  // 81920

__global__ __launch_bounds__(256) void mma_gemm_hl_nt(
    const __nv_bfloat16* __restrict__ Ahi, const __nv_bfloat16* __restrict__ Alo, int lda,
    const __nv_bfloat16* __restrict__ Bhi, const __nv_bfloat16* __restrict__ Blo, int ldb,
    const float* __restrict__ bias,
    float* __restrict__ Cf, __nv_bfloat16* __restrict__ Chi, __nv_bfloat16* __restrict__ Clo,
    int ldc, int K, int flags)
{
    extern __shared__ __align__(16) char gsm[];
    const uint32_t base = smem_u32(gsm);

    const int tid  = threadIdx.x;
    const int lane = tid & 31;
    const int wid  = tid >> 5;
    const int wm   = wid & 3;
    const int wn   = wid >> 2;
    const int row0 = blockIdx.y * 128;
    const int col0 = blockIdx.x * 128;

    // global load mapping: thread -> 16 bf16 of one row of each array
    const int grow = tid >> 1;
    const int gc16 = (tid & 1) * 16;
    const __nv_bfloat16* Ah_p = Ahi + (size_t)(row0 + grow) * lda + gc16;
    const __nv_bfloat16* Al_p = Alo + (size_t)(row0 + grow) * lda + gc16;
    const __nv_bfloat16* Bh_p = Bhi + (size_t)(col0 + grow) * ldb + gc16;
    const __nv_bfloat16* Bl_p = Blo + (size_t)(col0 + grow) * ldb + gc16;
    const uint32_t soff = grow * (SST * 2) + gc16 * 2;   // bytes

    // ldmatrix per-lane offsets (same verified formulas as before)
    const uint32_t aRowOff = (uint32_t)((wm * 32 + (lane & 15)) * SST * 2 + (lane >> 4) * 16);
    const uint32_t bRowOff = (uint32_t)(((wn * 64 + ((lane >> 4) << 3) + (lane & 7)) * SST) * 2
                                        + ((lane >> 3) & 1) * 16);

    float acc[2][8][4];
#pragma unroll
    for (int i = 0; i < 2; i++)
#pragma unroll
        for (int j = 0; j < 8; j++)
#pragma unroll
            for (int q = 0; q < 4; q++) acc[i][j][q] = 0.f;

    const int nc = K >> 5;

    auto issue = [&](int c, int s) {
        const uint32_t sb = base + s * STAGE_B;
        const __nv_bfloat16* p = Ah_p + c * 32;
        cp_async16(sb + soff, p);                 cp_async16(sb + soff + 16, p + 8);
        p = Al_p + c * 32;
        cp_async16(sb + ARR_B + soff, p);         cp_async16(sb + ARR_B + soff + 16, p + 8);
        p = Bh_p + c * 32;
        cp_async16(sb + 2 * ARR_B + soff, p);     cp_async16(sb + 2 * ARR_B + soff + 16, p + 8);
        p = Bl_p + c * 32;
        cp_async16(sb + 3 * ARR_B + soff, p);     cp_async16(sb + 3 * ARR_B + soff + 16, p + 8);
        CP_COMMIT();
    };

    issue(0, 0);

    for (int c = 0; c < nc; c++) {
        if (c + 1 < nc) { issue(c + 1, (c + 1) & 1); CP_WAIT1(); }
        else            { CP_WAIT0(); }
        __syncthreads();

        const uint32_t sb = base + (c & 1) * STAGE_B;
        const uint32_t aHi = sb, aLo = sb + ARR_B, bHi = sb + 2 * ARR_B, bLo = sb + 3 * ARR_B;

#pragma unroll
        for (int ks = 0; ks < 2; ks++) {
            const uint32_t kb = ks * 32;
            uint32_t Ah[2][4], Al[2][4];
#pragma unroll
            for (int mt = 0; mt < 2; mt++) {
                ldmat_x4(Ah[mt], aHi + aRowOff + mt * (16 * SST * 2) + kb);
                ldmat_x4(Al[mt], aLo + aRowOff + mt * (16 * SST * 2) + kb);
            }
#pragma unroll
            for (int pr = 0; pr < 4; pr++) {
                uint32_t Bh[4], Bl[4];
                ldmat_x4(Bh, bHi + bRowOff + pr * (16 * SST * 2) + kb);
                ldmat_x4(Bl, bLo + bRowOff + pr * (16 * SST * 2) + kb);
#pragma unroll
                for (int sbb = 0; sbb < 2; sbb++) {
                    const int nt = pr * 2 + sbb;
#pragma unroll
                    for (int mt = 0; mt < 2; mt++) {
                        mma16816(acc[mt][nt], Ah[mt], Bh[sbb * 2], Bh[sbb * 2 + 1]);
                        mma16816(acc[mt][nt], Ah[mt], Bl[sbb * 2], Bl[sbb * 2 + 1]);
                        mma16816(acc[mt][nt], Al[mt], Bh[sbb * 2], Bh[sbb * 2 + 1]);
                    }
                }
            }
        }
        __syncthreads();
    }

    // ---- epilogue
    const int erow = lane >> 2;
    const int ecol = (lane & 3) * 2;
    const int relu = flags & 1;
#pragma unroll
    for (int mt = 0; mt < 2; mt++) {
        const int r = row0 + wm * 32 + mt * 16 + erow;
#pragma unroll
        for (int nt = 0; nt < 8; nt++) {
            const int cc = col0 + wn * 64 + nt * 8 + ecol;
            float2 bv = *(const float2*)(bias + cc);
            float2 v0, v1;
            v0.x = acc[mt][nt][0] + bv.x;  v0.y = acc[mt][nt][1] + bv.y;
            v1.x = acc[mt][nt][2] + bv.x;  v1.y = acc[mt][nt][3] + bv.y;
            if (relu) {
                v0.x = fmaxf(v0.x, 0.f); v0.y = fmaxf(v0.y, 0.f);
                v1.x = fmaxf(v1.x, 0.f); v1.y = fmaxf(v1.y, 0.f);
            }
            if (flags & 2) {
                *(float2*)(Cf + (size_t)r * ldc + cc)       = v0;
                *(float2*)(Cf + (size_t)(r + 8) * ldc + cc) = v1;
            }
            if (flags & 4) {
                uint32_t hv, lv;
                cvt_hilo2(v0.x, v0.y, hv, lv);
                *(uint32_t*)(Chi + (size_t)r * ldc + cc) = hv;
                *(uint32_t*)(Clo + (size_t)r * ldc + cc) = lv;
                cvt_hilo2(v1.x, v1.y, hv, lv);
                *(uint32_t*)(Chi + (size_t)(r + 8) * ldc + cc) = hv;
                *(uint32_t*)(Clo + (size_t)(r + 8) * ldc + cc) = lv;
            }
        }
    }
}

// ---------------------------------------------------------------------------
// Fused flash attention (unchanged math); epilogue writes o as bf16 hi/lo.
// ---------------------------------------------------------------------------
namespace { constexpr int KST = 72; }
static constexpr int FLASH_SMEM = 4 * 128 * KST * 2;   // 73728 B

__global__ __launch_bounds__(256) void flash_attn_kernel(
    const float* __restrict__ qkv,
    __nv_bfloat16* __restrict__ ohi, __nv_bfloat16* __restrict__ olo)
{
    extern __shared__ __align__(16) char fsm[];
    const uint32_t kHi = smem_u32(fsm);
    const uint32_t kLo = kHi + 128 * KST * 2;
    const uint32_t vHi = kLo + 128 * KST * 2;
    const uint32_t vLo = vHi + 128 * KST * 2;

    const int tid  = threadIdx.x;
    const int lane = tid & 31;
    const int w    = tid >> 5;
    const int bh = blockIdx.y;
    const int b = bh >> 4, h = bh & 15;
    const int qrow0 = blockIdx.x * 128;

    const float* Qbase = qkv + (size_t)b * Tk * D3k + h * HDk;
    const float* Kbase = Qbase + Dk;
    const float* Vbase = Qbase + 2 * Dk;

    float slope = 0.f;
#pragma unroll
    for (int i = 1; i <= Hk; i++) slope += exp2f(-0.5f * (float)i);
    slope *= (1.f / (float)Hk);
    const float scale = 0.125f;

    const int grow = tid >> 1;
    const int gcol = (tid & 1) * 32;
    const uint32_t gso = grow * (KST * 2) + gcol * 2;
    {
        const float* qp = Qbase + (size_t)(qrow0 + grow) * D3k + gcol;
#pragma unroll
        for (int j = 0; j < 4; j++) {
            float4 f0 = *(const float4*)(qp + j * 8);
            float4 f1 = *(const float4*)(qp + j * 8 + 4);
            uint4 hi, lo;
            cvt_hilo8(f0, f1, hi, lo);
            sts128(kHi + gso + j * 16, hi);
            sts128(kLo + gso + j * 16, lo);
        }
    }
    __syncthreads();

    uint32_t Qh[4][4], Ql[4][4];
    const uint32_t qOff = (w * 16 + (lane & 15)) * (KST * 2) + (lane >> 4) * 16;
#pragma unroll
    for (int kc = 0; kc < 4; kc++) {
        ldmat_x4(Qh[kc], kHi + qOff + kc * 32);
        ldmat_x4(Ql[kc], kLo + qOff + kc * 32);
    }
    __syncthreads();

    const uint32_t bOff = (((lane >> 4) << 3) + (lane & 7)) * (KST * 2) + ((lane >> 3) & 1) * 16;
    const uint32_t vOff = ((lane & 7) + ((lane >> 3) & 1) * 8) * (KST * 2) + (lane >> 4) * 16;

    float Of[8][4];
#pragma unroll
    for (int i = 0; i < 8; i++)
#pragma unroll
        for (int q = 0; q < 4; q++) Of[i][q] = 0.f;
    float m0 = -1e30f, m1 = -1e30f, l0 = 0.f, l1 = 0.f;

    const float r0f = (float)(qrow0 + w * 16 + (lane >> 2));
    const float r1f = r0f + 8.f;

    for (int kb = 0; kb < Tk / 128; kb++) {
        {
            const float* kp = Kbase + (size_t)(kb * 128 + grow) * D3k + gcol;
            const float* vp = Vbase + (size_t)(kb * 128 + grow) * D3k + gcol;
#pragma unroll
            for (int j = 0; j < 4; j++) {
                float4 f0 = *(const float4*)(kp + j * 8);
                float4 f1 = *(const float4*)(kp + j * 8 + 4);
                uint4 hi, lo;
                cvt_hilo8(f0, f1, hi, lo);
                sts128(kHi + gso + j * 16, hi);
                sts128(kLo + gso + j * 16, lo);
                f0 = *(const float4*)(vp + j * 8);
                f1 = *(const float4*)(vp + j * 8 + 4);
                cvt_hilo8(f0, f1, hi, lo);
                sts128(vHi + gso + j * 16, hi);
                sts128(vLo + gso + j * 16, lo);
            }
        }
        __syncthreads();

        float Sf[16][4];
#pragma unroll
        for (int ntp = 0; ntp < 8; ntp++) {
#pragma unroll
            for (int q = 0; q < 4; q++) { Sf[2 * ntp][q] = 0.f; Sf[2 * ntp + 1][q] = 0.f; }
#pragma unroll
            for (int kc = 0; kc < 4; kc++) {
                uint32_t Bh4[4], Bl4[4];
                ldmat_x4(Bh4, kHi + bOff + ntp * (16 * KST * 2) + kc * 32);
                ldmat_x4(Bl4, kLo + bOff + ntp * (16 * KST * 2) + kc * 32);
                mma16816(Sf[2 * ntp],     Qh[kc], Bh4[0], Bh4[1]);
                mma16816(Sf[2 * ntp],     Qh[kc], Bl4[0], Bl4[1]);
                mma16816(Sf[2 * ntp],     Ql[kc], Bh4[0], Bh4[1]);
                mma16816(Sf[2 * ntp + 1], Qh[kc], Bh4[2], Bh4[3]);
                mma16816(Sf[2 * ntp + 1], Qh[kc], Bl4[2], Bl4[3]);
                mma16816(Sf[2 * ntp + 1], Ql[kc], Bh4[2], Bh4[3]);
            }
        }

        float bm0 = -1e30f, bm1 = -1e30f;
#pragma unroll
        for (int t = 0; t < 16; t++) {
            const float c0f = (float)(kb * 128 + t * 8 + (lane & 3) * 2);
            const float c1f = c0f + 1.f;
            Sf[t][0] = Sf[t][0] * scale - slope * fabsf(r0f - c0f);
            Sf[t][1] = Sf[t][1] * scale - slope * fabsf(r0f - c1f);
            Sf[t][2] = Sf[t][2] * scale - slope * fabsf(r1f - c0f);
            Sf[t][3] = Sf[t][3] * scale - slope * fabsf(r1f - c1f);
            bm0 = fmaxf(bm0, fmaxf(Sf[t][0], Sf[t][1]));
            bm1 = fmaxf(bm1, fmaxf(Sf[t][2], Sf[t][3]));
        }
        bm0 = fmaxf(bm0, __shfl_xor_sync(~0u, bm0, 1));
        bm0 = fmaxf(bm0, __shfl_xor_sync(~0u, bm0, 2));
        bm1 = fmaxf(bm1, __shfl_xor_sync(~0u, bm1, 1));
        bm1 = fmaxf(bm1, __shfl_xor_sync(~0u, bm1, 2));

        const float mn0 = fmaxf(m0, bm0), mn1 = fmaxf(m1, bm1);
        const float sc0 = __expf(m0 - mn0), sc1 = __expf(m1 - mn1);
        l0 *= sc0; l1 *= sc1;
#pragma unroll
        for (int nt = 0; nt < 8; nt++) {
            Of[nt][0] *= sc0; Of[nt][1] *= sc0;
            Of[nt][2] *= sc1; Of[nt][3] *= sc1;
        }
        m0 = mn0; m1 = mn1;

#pragma unroll
        for (int t = 0; t < 16; t++) {
            Sf[t][0] = __expf(Sf[t][0] - mn0);
            Sf[t][1] = __expf(Sf[t][1] - mn0);
            Sf[t][2] = __expf(Sf[t][2] - mn1);
            Sf[t][3] = __expf(Sf[t][3] - mn1);
            l0 += Sf[t][0] + Sf[t][1];
            l1 += Sf[t][2] + Sf[t][3];
        }

        uint32_t Ph[8][4], Pl[8][4];
#pragma unroll
        for (int kc = 0; kc < 8; kc++) {
            cvt_hilo2(Sf[2 * kc][0],     Sf[2 * kc][1],     Ph[kc][0], Pl[kc][0]);
            cvt_hilo2(Sf[2 * kc][2],     Sf[2 * kc][3],     Ph[kc][1], Pl[kc][1]);
            cvt_hilo2(Sf[2 * kc + 1][0], Sf[2 * kc + 1][1], Ph[kc][2], Pl[kc][2]);
            cvt_hilo2(Sf[2 * kc + 1][2], Sf[2 * kc + 1][3], Ph[kc][3], Pl[kc][3]);
        }

#pragma unroll
        for (int ntp = 0; ntp < 4; ntp++) {
#pragma unroll
            for (int kc = 0; kc < 8; kc++) {
                uint32_t Vh4[4], Vl4[4];
                ldmat_x4_t(Vh4, vHi + vOff + kc * (16 * KST * 2) + ntp * 32);
                ldmat_x4_t(Vl4, vLo + vOff + kc * (16 * KST * 2) + ntp * 32);
                mma16816(Of[2 * ntp],     Ph[kc], Vh4[0], Vh4[1]);
                mma16816(Of[2 * ntp],     Ph[kc], Vl4[0], Vl4[1]);
                mma16816(Of[2 * ntp],     Pl[kc], Vh4[0], Vh4[1]);
                mma16816(Of[2 * ntp + 1], Ph[kc], Vh4[2], Vh4[3]);
                mma16816(Of[2 * ntp + 1], Ph[kc], Vl4[2], Vl4[3]);
                mma16816(Of[2 * ntp + 1], Pl[kc], Vh4[2], Vh4[3]);
            }
        }
        __syncthreads();
    }

    l0 += __shfl_xor_sync(~0u, l0, 1);
    l0 += __shfl_xor_sync(~0u, l0, 2);
    l1 += __shfl_xor_sync(~0u, l1, 1);
    l1 += __shfl_xor_sync(~0u, l1, 2);
    const float inv0 = 1.f / l0, inv1 = 1.f / l1;

    const int row0 = qrow0 + w * 16 + (lane >> 2);
    __nv_bfloat16* ohb = ohi + (size_t)b * Tk * Dk + h * HDk;
    __nv_bfloat16* olb = olo + (size_t)b * Tk * Dk + h * HDk;
#pragma unroll
    for (int nt = 0; nt < 8; nt++) {
        const int cc = nt * 8 + (lane & 3) * 2;
        uint32_t hv, lv;
        cvt_hilo2(Of[nt][0] * inv0, Of[nt][1] * inv0, hv, lv);
        *(uint32_t*)(ohb + (size_t)row0 * Dk + cc) = hv;
        *(uint32_t*)(olb + (size_t)row0 * Dk + cc) = lv;
        cvt_hilo2(Of[nt][2] * inv1, Of[nt][3] * inv1, hv, lv);
        *(uint32_t*)(ohb + (size_t)(row0 + 8) * Dk + cc) = hv;
        *(uint32_t*)(olb + (size_t)(row0 + 8) * Dk + cc) = lv;
    }
}

// ---------------------------------------------------------------------------
// h = LN(h + o) * g + b; also writes h as bf16 hi/lo for the next GEMM.
// ---------------------------------------------------------------------------
__global__ __launch_bounds__(256) void ln_residual_kernel(
    float* __restrict__ h, const float* __restrict__ o,
    const float* __restrict__ gam, const float* __restrict__ bet,
    __nv_bfloat16* __restrict__ hhi, __nv_bfloat16* __restrict__ hlo)
{
    __shared__ float rs[8], rs2[8];
    const size_t row = blockIdx.x;
    float* hp = h + row * Dk;
    const float* op = o + row * Dk;
    const int tid = threadIdx.x;

    float4 hv = ((const float4*)hp)[tid];
    float4 ov = ((const float4*)op)[tid];
    float r0 = hv.x + ov.x, r1 = hv.y + ov.y, r2 = hv.z + ov.z, r3 = hv.w + ov.w;

    float s  = r0 + r1 + r2 + r3;
    float s2 = r0 * r0 + r1 * r1 + r2 * r2 + r3 * r3;
#pragma unroll
    for (int of = 16; of; of >>= 1) {
        s  += __shfl_xor_sync(~0u, s,  of);
        s2 += __shfl_xor_sync(~0u, s2, of);
    }
    if ((tid & 31) == 0) { rs[tid >> 5] = s; rs2[tid >> 5] = s2; }
    __syncthreads();
    float S = 0.f, S2 = 0.f;
#pragma unroll
    for (int i = 0; i < 8; i++) { S += rs[i]; S2 += rs2[i]; }

    const float mu  = S * (1.f / (float)Dk);
    const float var = S2 * (1.f / (float)Dk) - mu * mu;
    const float inv = rsqrtf(var + EPSk);

    float4 gg = ((const float4*)gam)[tid];
    float4 bb = ((const float4*)bet)[tid];
    float4 out;
    out.x = (r0 - mu) * inv * gg.x + bb.x;
    out.y = (r1 - mu) * inv * gg.y + bb.y;
    out.z = (r2 - mu) * inv * gg.z + bb.z;
    out.w = (r3 - mu) * inv * gg.w + bb.w;
    ((float4*)hp)[tid] = out;

    uint32_t h0, l0w, h1, l1w;
    cvt_hilo2(out.x, out.y, h0, l0w);
    cvt_hilo2(out.z, out.w, h1, l1w);
    *(uint2*)(hhi + row * Dk + tid * 4) = make_uint2(h0, h1);
    *(uint2*)(hlo + row * Dk + tid * 4) = make_uint2(l0w, l1w);
}

// ---------------------------------------------------------------------------
// head
// ---------------------------------------------------------------------------
__global__ void head_kernel(const float* __restrict__ h,
                            const float* __restrict__ hw,
                            const float* __restrict__ hb,
                            float* __restrict__ outp)
{
    const int idx = blockIdx.x;
    const int b = idx / Ck, c = idx % Ck;
    const float* hp = h + ((size_t)b * Tk + (Tk - 1)) * Dk;
    const float* wp = hw + (size_t)c * Dk;
    const int lane = threadIdx.x;
    float s = 0.f;
    for (int i = lane; i < Dk; i += 32) s += hp[i] * wp[i];
#pragma unroll
    for (int o = 16; o; o >>= 1) s += __shfl_xor_sync(~0u, s, o);
    if (lane == 0) outp[idx] = s + hb[c];
}

// ---------------------------------------------------------------------------
// Host orchestration
// ---------------------------------------------------------------------------
static inline void cvt_hl(const float* src, __nv_bfloat16* hi, __nv_bfloat16* lo, int n) {
    cvt_hl_kernel<<<n / 1024, 256>>>(src, hi, lo, n);
}

extern "C" void kernel_launch(void* const* d_in, const int* in_sizes, int n_in,
                              void* d_out, int out_size)
{
    (void)in_sizes; (void)n_in; (void)out_size;
    const float* x       = (const float*)d_in[0];
    const float* input_w = (const float*)d_in[1];
    const float* input_b = (const float*)d_in[2];
    const float* Wqkv    = (const float*)d_in[3];
    const float* bqkv    = (const float*)d_in[4];
    const float* Wo      = (const float*)d_in[5];
    const float* bo      = (const float*)d_in[6];
    const float* ln1_g   = (const float*)d_in[7];
    const float* ln1_b   = (const float*)d_in[8];
    const float* ln2_g   = (const float*)d_in[9];
    const float* ln2_b   = (const float*)d_in[10];
    const float* W1      = (const float*)d_in[11];
    const float* b1      = (const float*)d_in[12];
    const float* W2      = (const float*)d_in[13];
    const float* b2      = (const float*)d_in[14];
    const float* head_w  = (const float*)d_in[15];
    const float* head_b  = (const float*)d_in[16];
    float* outp = (float*)d_out;

    float *h, *tmp, *qkv;
    __nv_bfloat16 *xhi, *xlo, *hhi, *hlo, *ohi, *olo, *fhi, *flo;
    __nv_bfloat16 *winh, *winl, *wqh, *wql, *woh, *wol, *w1h, *w1l, *w2h, *w2l;
    cudaGetSymbolAddress((void**)&h,    g_h);
    cudaGetSymbolAddress((void**)&tmp,  g_tmp);
    cudaGetSymbolAddress((void**)&qkv,  g_qkv);
    cudaGetSymbolAddress((void**)&xhi,  g_x_hi);  cudaGetSymbolAddress((void**)&xlo,  g_x_lo);
    cudaGetSymbolAddress((void**)&hhi,  g_h_hi);  cudaGetSymbolAddress((void**)&hlo,  g_h_lo);
    cudaGetSymbolAddress((void**)&ohi,  g_o_hi);  cudaGetSymbolAddress((void**)&olo,  g_o_lo);
    cudaGetSymbolAddress((void**)&fhi,  g_ff_hi); cudaGetSymbolAddress((void**)&flo,  g_ff_lo);
    cudaGetSymbolAddress((void**)&winh, g_win_hi); cudaGetSymbolAddress((void**)&winl, g_win_lo);
    cudaGetSymbolAddress((void**)&wqh,  g_wqkv_hi); cudaGetSymbolAddress((void**)&wql, g_wqkv_lo);
    cudaGetSymbolAddress((void**)&woh,  g_wo_hi);  cudaGetSymbolAddress((void**)&wol,  g_wo_lo);
    cudaGetSymbolAddress((void**)&w1h,  g_w1_hi);  cudaGetSymbolAddress((void**)&w1l,  g_w1_lo);
    cudaGetSymbolAddress((void**)&w2h,  g_w2_hi);  cudaGetSymbolAddress((void**)&w2l,  g_w2_lo);

    cudaFuncSetAttribute(mma_gemm_hl_nt,
                         cudaFuncAttributeMaxDynamicSharedMemorySize, GEMM_SMEM);
    cudaFuncSetAttribute(flash_attn_kernel,
                         cudaFuncAttributeMaxDynamicSharedMemorySize, FLASH_SMEM);

    const int M = Bk * Tk;  // 4096
    dim3 blk(256);

    // ---- precision-split conversions (weights + x) — every launch, deterministic
    cvt_hl(x, xhi, xlo, Bk * Tk * INk);
    cvt_hl(input_w, winh, winl, Dk * INk);
    cvt_hl(Wqkv, wqh, wql, Lk * D3k * Dk);
    cvt_hl(Wo, woh, wol, Lk * Dk * Dk);
    cvt_hl(W1, w1h, w1l, Lk * FFk * Dk);
    cvt_hl(W2, w2h, w2l, Lk * Dk * FFk);

    // ---- input projection: h (fp32) + h_hl
    mma_gemm_hl_nt<<<dim3(Dk / 128, M / 128), blk, GEMM_SMEM>>>(
        xhi, xlo, INk, winh, winl, INk, input_b, h, hhi, hlo, Dk, INk, 2 | 4);

    for (int l = 0; l < Lk; l++) {
        // qkv (fp32 out, feeds flash)
        mma_gemm_hl_nt<<<dim3(D3k / 128, M / 128), blk, GEMM_SMEM>>>(
            hhi, hlo, Dk, wqh + (size_t)l * D3k * Dk, wql + (size_t)l * D3k * Dk, Dk,
            bqkv + (size_t)l * D3k, qkv, nullptr, nullptr, D3k, Dk, 2);
        // attention -> o hi/lo
        flash_attn_kernel<<<dim3(Tk / 128, Bk * Hk), blk, FLASH_SMEM>>>(qkv, ohi, olo);
        // Wo proj (fp32 out)
        mma_gemm_hl_nt<<<dim3(Dk / 128, M / 128), blk, GEMM_SMEM>>>(
            ohi, olo, Dk, woh + (size_t)l * Dk * Dk, wol + (size_t)l * Dk * Dk, Dk,
            bo + (size_t)l * Dk, tmp, nullptr, nullptr, Dk, Dk, 2);
        // LN1 -> h fp32 + h_hl
        ln_residual_kernel<<<M, 256>>>(h, tmp, ln1_g + (size_t)l * Dk, ln1_b + (size_t)l * Dk,
                                       hhi, hlo);
        // FF1 (relu, hl out only)
        mma_gemm_hl_nt<<<dim3(FFk / 128, M / 128), blk, GEMM_SMEM>>>(
            hhi, hlo, Dk, w1h + (size_t)l * FFk * Dk, w1l + (size_t)l * FFk * Dk, Dk,
            b1 + (size_t)l * FFk, nullptr, fhi, flo, FFk, Dk, 1 | 4);
        // FF2 (fp32 out)
        mma_gemm_hl_nt<<<dim3(Dk / 128, M / 128), blk, GEMM_SMEM>>>(
            fhi, flo, FFk, w2h + (size_t)l * Dk * FFk, w2l + (size_t)l * Dk * FFk, FFk,
            b2 + (size_t)l * Dk, tmp, nullptr, nullptr, Dk, FFk, 2);
        // LN2 -> h fp32 + h_hl
        ln_residual_kernel<<<M, 256>>>(h, tmp, ln2_g + (size_t)l * Dk, ln2_b + (size_t)l * Dk,
                                       hhi, hlo);
    }

    head_kernel<<<Bk * Ck, 32>>>(h, head_w, head_b, outp);
}

// round 9
// speedup vs baseline: 3.1906x; 1.2418x over previous
#include <cuda_runtime.h>
#include <cuda_bf16.h>
#include <cuda_fp16.h>
#include <math.h>
#include <stdint.h>

// ---------------------------------------------------------------------------
// Problem constants
// ---------------------------------------------------------------------------
namespace {
constexpr int Bk = 4;       // batch
constexpr int Tk = 1024;    // seq len
constexpr int INk = 256;    // input dim
constexpr int Dk = 1024;    // model dim
constexpr int Hk = 16;      // heads
constexpr int HDk = 64;     // head dim
constexpr int FFk = 4096;   // ff dim
constexpr int Ck = 10;      // classes
constexpr int Lk = 6;       // layers
constexpr int D3k = 3 * Dk;
constexpr float EPSk = 1e-5f;
}

// ---------------------------------------------------------------------------
// Scratch buffers (static device globals — no allocations allowed)
// ---------------------------------------------------------------------------
__device__ float g_h[Bk * Tk * Dk];
__device__ float g_tmp[Bk * Tk * Dk];
__device__ float g_qkv[Bk * Tk * D3k];

// fp16 hi/lo activation buffers
__device__ __half g_x_hi[Bk * Tk * INk],  g_x_lo[Bk * Tk * INk];
__device__ __half g_h_hi[Bk * Tk * Dk],   g_h_lo[Bk * Tk * Dk];
__device__ __half g_o_hi[Bk * Tk * Dk],   g_o_lo[Bk * Tk * Dk];
__device__ __half g_ff_hi[Bk * Tk * FFk], g_ff_lo[Bk * Tk * FFk];

// fp16 weight buffers (single rounding)
__device__ __half g_win_h[Dk * INk];
__device__ __half g_wqkv_h[Lk * D3k * Dk];
__device__ __half g_wo_h[Lk * Dk * Dk];
__device__ __half g_w1_h[Lk * FFk * Dk];
__device__ __half g_w2_h[Lk * Dk * FFk];

// ---------------------------------------------------------------------------
// PTX helpers (sm_80-era features only — compile on base sm_100)
// ---------------------------------------------------------------------------
__device__ __forceinline__ uint32_t smem_u32(const void* p) {
    uint32_t a;
    asm("{ .reg .u64 t; cvta.to.shared.u64 t, %1; cvt.u32.u64 %0, t; }"
        : "=r"(a) : "l"(p));
    return a;
}

__device__ __forceinline__ void ldmat_x4(uint32_t* r, uint32_t addr) {
    asm volatile("ldmatrix.sync.aligned.m8n8.x4.shared.b16 {%0,%1,%2,%3}, [%4];"
                 : "=r"(r[0]), "=r"(r[1]), "=r"(r[2]), "=r"(r[3]) : "r"(addr));
}

__device__ __forceinline__ void ldmat_x4_t(uint32_t* r, uint32_t addr) {
    asm volatile("ldmatrix.sync.aligned.m8n8.x4.trans.shared.b16 {%0,%1,%2,%3}, [%4];"
                 : "=r"(r[0]), "=r"(r[1]), "=r"(r[2]), "=r"(r[3]) : "r"(addr));
}

// bf16 mma (flash attention)
__device__ __forceinline__ void mma16816(float* c, const uint32_t* a,
                                         uint32_t b0, uint32_t b1) {
    asm volatile(
        "mma.sync.aligned.m16n8k16.row.col.f32.bf16.bf16.f32 "
        "{%0,%1,%2,%3}, {%4,%5,%6,%7}, {%8,%9}, {%0,%1,%2,%3};"
        : "+f"(c[0]), "+f"(c[1]), "+f"(c[2]), "+f"(c[3])
        : "r"(a[0]), "r"(a[1]), "r"(a[2]), "r"(a[3]), "r"(b0), "r"(b1));
}

// fp16 mma (dense GEMMs)
__device__ __forceinline__ void mma16816h(float* c, const uint32_t* a,
                                          uint32_t b0, uint32_t b1) {
    asm volatile(
        "mma.sync.aligned.m16n8k16.row.col.f32.f16.f16.f32 "
        "{%0,%1,%2,%3}, {%4,%5,%6,%7}, {%8,%9}, {%0,%1,%2,%3};"
        : "+f"(c[0]), "+f"(c[1]), "+f"(c[2]), "+f"(c[3])
        : "r"(a[0]), "r"(a[1]), "r"(a[2]), "r"(a[3]), "r"(b0), "r"(b1));
}

__device__ __forceinline__ void sts128(uint32_t addr, uint4 v) {
    asm volatile("st.shared.v4.b32 [%0], {%1,%2,%3,%4};"
                 :: "r"(addr), "r"(v.x), "r"(v.y), "r"(v.z), "r"(v.w) : "memory");
}

__device__ __forceinline__ void cp_async16(uint32_t saddr, const void* gptr) {
    asm volatile("cp.async.cg.shared.global [%0], [%1], 16;"
                 :: "r"(saddr), "l"(gptr) : "memory");
}
#define CP_COMMIT() asm volatile("cp.async.commit_group;" ::: "memory")
#define CP_WAIT1()  asm volatile("cp.async.wait_group 1;" ::: "memory")
#define CP_WAIT0()  asm volatile("cp.async.wait_group 0;" ::: "memory")

// ---- bf16 hi/lo split (flash attention path)
__device__ __forceinline__ void cvt_hilo2(float a, float b, uint32_t& hi, uint32_t& lo) {
    __nv_bfloat162 h = __floats2bfloat162_rn(a, b);
    float2 hf = __bfloat1622float2(h);
    __nv_bfloat162 l = __floats2bfloat162_rn(a - hf.x, b - hf.y);
    hi = *reinterpret_cast<uint32_t*>(&h);
    lo = *reinterpret_cast<uint32_t*>(&l);
}

__device__ __forceinline__ void cvt_hilo8(float4 a, float4 b, uint4& hi, uint4& lo) {
    cvt_hilo2(a.x, a.y, hi.x, lo.x);
    cvt_hilo2(a.z, a.w, hi.y, lo.y);
    cvt_hilo2(b.x, b.y, hi.z, lo.z);
    cvt_hilo2(b.z, b.w, hi.w, lo.w);
}

// ---- fp16 hi/lo split (dense GEMM activations)
__device__ __forceinline__ void cvt_hilo2h(float a, float b, uint32_t& hi, uint32_t& lo) {
    __half2 h = __floats2half2_rn(a, b);
    float2 hf = __half22float2(h);
    __half2 l = __floats2half2_rn(a - hf.x, b - hf.y);
    hi = *reinterpret_cast<uint32_t*>(&h);
    lo = *reinterpret_cast<uint32_t*>(&l);
}

// ---------------------------------------------------------------------------
// Conversion kernels
// ---------------------------------------------------------------------------
__global__ __launch_bounds__(256) void cvt_hl16_kernel(
    const float* __restrict__ src, __half* __restrict__ hi,
    __half* __restrict__ lo, int n)
{
    const int i = (blockIdx.x * 256 + threadIdx.x) * 4;
    if (i >= n) return;
    float4 v = *(const float4*)(src + i);
    uint32_t h0, l0, h1, l1;
    cvt_hilo2h(v.x, v.y, h0, l0);
    cvt_hilo2h(v.z, v.w, h1, l1);
    *(uint2*)(hi + i) = make_uint2(h0, h1);
    *(uint2*)(lo + i) = make_uint2(l0, l1);
}

__global__ __launch_bounds__(256) void cvt_h16_kernel(
    const float* __restrict__ src, __half* __restrict__ dst, int n)
{
    const int i = (blockIdx.x * 256 + threadIdx.x) * 4;
    if (i >= n) return;
    float4 v = *(const float4*)(src + i);
    __half2 h0 = __floats2half2_rn(v.x, v.y);
    __half2 h1 = __floats2half2_rn(v.z, v.w);
    *(uint2*)(dst + i) = make_uint2(*reinterpret_cast<uint32_t*>(&h0),
                                    *reinterpret_cast<uint32_t*>(&h1));
}

// ---------------------------------------------------------------------------
// fp16 2-term NT GEMM: C = (Ahi+Alo) * W^T + bias.
// A as fp16 hi/lo pair, W as single fp16. 2 MMAs per tile.
// 128x128 tile, BK=32, 3-stage cp.async pipeline, 1 syncthreads/chunk.
// flags: 1=relu, 2=write fp32 C, 4=write fp16 hi/lo C
// ---------------------------------------------------------------------------
namespace {
constexpr int SST = 40;                        // smem row stride (fp16)
constexpr int ARR_B = 128 * SST * 2;           // 10240 bytes per tile array
constexpr int STAGE_B = 3 * ARR_B;             // Ahi|Alo|Bh = 30720 bytes
}
static constexpr int GEMM_SMEM = 3 * STAGE_B;  // 92160

__global__ __launch_bounds__(256) void mma_gemm_f16_nt(
    const __half* __restrict__ Ahi, const __half* __restrict__ Alo, int lda,
    const __half* __restrict__ Bh, int ldb,
    const float* __restrict__ bias,
    float* __restrict__ Cf, __half* __restrict__ Chi, __half* __restrict__ Clo,
    int ldc, int K, int flags)
{
    extern __shared__ __align__(16) char gsm[];
    const uint32_t base = smem_u32(gsm);

    const int tid  = threadIdx.x;
    const int lane = tid & 31;
    const int wid  = tid >> 5;
    const int wm   = wid & 3;
    const int wn   = wid >> 2;
    const int row0 = blockIdx.y * 128;
    const int col0 = blockIdx.x * 128;

    const int grow = tid >> 1;
    const int gc16 = (tid & 1) * 16;
    const __half* Ah_p = Ahi + (size_t)(row0 + grow) * lda + gc16;
    const __half* Al_p = Alo + (size_t)(row0 + grow) * lda + gc16;
    const __half* Bh_p = Bh  + (size_t)(col0 + grow) * ldb + gc16;
    const uint32_t soff = grow * (SST * 2) + gc16 * 2;

    const uint32_t aRowOff = (uint32_t)((wm * 32 + (lane & 15)) * SST * 2 + (lane >> 4) * 16);
    const uint32_t bRowOff = (uint32_t)(((wn * 64 + ((lane >> 4) << 3) + (lane & 7)) * SST) * 2
                                        + ((lane >> 3) & 1) * 16);

    float acc[2][8][4];
#pragma unroll
    for (int i = 0; i < 2; i++)
#pragma unroll
        for (int j = 0; j < 8; j++)
#pragma unroll
            for (int q = 0; q < 4; q++) acc[i][j][q] = 0.f;

    const int nc = K >> 5;

    auto issue = [&](int c, int s) {
        const uint32_t sb = base + s * STAGE_B;
        const __half* p = Ah_p + c * 32;
        cp_async16(sb + soff, p);                 cp_async16(sb + soff + 16, p + 8);
        p = Al_p + c * 32;
        cp_async16(sb + ARR_B + soff, p);         cp_async16(sb + ARR_B + soff + 16, p + 8);
        p = Bh_p + c * 32;
        cp_async16(sb + 2 * ARR_B + soff, p);     cp_async16(sb + 2 * ARR_B + soff + 16, p + 8);
        CP_COMMIT();
    };

    issue(0, 0);
    if (nc > 1) issue(1, 1);

    for (int c = 0; c < nc; c++) {
        if (c + 1 < nc) { CP_WAIT1(); }
        else            { CP_WAIT0(); }
        __syncthreads();
        if (c + 2 < nc) issue(c + 2, (c + 2) % 3);

        const uint32_t sb = base + (c % 3) * STAGE_B;
        const uint32_t aHi = sb, aLo = sb + ARR_B, bHi = sb + 2 * ARR_B;

#pragma unroll
        for (int ks = 0; ks < 2; ks++) {
            const uint32_t kb = ks * 32;
            uint32_t Ah4[2][4], Al4[2][4];
#pragma unroll
            for (int mt = 0; mt < 2; mt++) {
                ldmat_x4(Ah4[mt], aHi + aRowOff + mt * (16 * SST * 2) + kb);
                ldmat_x4(Al4[mt], aLo + aRowOff + mt * (16 * SST * 2) + kb);
            }
#pragma unroll
            for (int pr = 0; pr < 4; pr++) {
                uint32_t B4[4];
                ldmat_x4(B4, bHi + bRowOff + pr * (16 * SST * 2) + kb);
#pragma unroll
                for (int sbb = 0; sbb < 2; sbb++) {
                    const int nt = pr * 2 + sbb;
#pragma unroll
                    for (int mt = 0; mt < 2; mt++) {
                        mma16816h(acc[mt][nt], Ah4[mt], B4[sbb * 2], B4[sbb * 2 + 1]);
                        mma16816h(acc[mt][nt], Al4[mt], B4[sbb * 2], B4[sbb * 2 + 1]);
                    }
                }
            }
        }
    }
    __syncthreads();

    // ---- epilogue
    const int erow = lane >> 2;
    const int ecol = (lane & 3) * 2;
    const int relu = flags & 1;
#pragma unroll
    for (int mt = 0; mt < 2; mt++) {
        const int r = row0 + wm * 32 + mt * 16 + erow;
#pragma unroll
        for (int nt = 0; nt < 8; nt++) {
            const int cc = col0 + wn * 64 + nt * 8 + ecol;
            float2 bv = *(const float2*)(bias + cc);
            float2 v0, v1;
            v0.x = acc[mt][nt][0] + bv.x;  v0.y = acc[mt][nt][1] + bv.y;
            v1.x = acc[mt][nt][2] + bv.x;  v1.y = acc[mt][nt][3] + bv.y;
            if (relu) {
                v0.x = fmaxf(v0.x, 0.f); v0.y = fmaxf(v0.y, 0.f);
                v1.x = fmaxf(v1.x, 0.f); v1.y = fmaxf(v1.y, 0.f);
            }
            if (flags & 2) {
                *(float2*)(Cf + (size_t)r * ldc + cc)       = v0;
                *(float2*)(Cf + (size_t)(r + 8) * ldc + cc) = v1;
            }
            if (flags & 4) {
                uint32_t hv, lv;
                cvt_hilo2h(v0.x, v0.y, hv, lv);
                *(uint32_t*)(Chi + (size_t)r * ldc + cc) = hv;
                *(uint32_t*)(Clo + (size_t)r * ldc + cc) = lv;
                cvt_hilo2h(v1.x, v1.y, hv, lv);
                *(uint32_t*)(Chi + (size_t)(r + 8) * ldc + cc) = hv;
                *(uint32_t*)(Clo + (size_t)(r + 8) * ldc + cc) = lv;
            }
        }
    }
}

// ---------------------------------------------------------------------------
// Fused flash attention (bf16 3-term, unchanged math); writes o fp16 hi/lo.
// ---------------------------------------------------------------------------
namespace { constexpr int KST = 72; }
static constexpr int FLASH_SMEM = 4 * 128 * KST * 2;   // 73728 B

__global__ __launch_bounds__(256) void flash_attn_kernel(
    const float* __restrict__ qkv,
    __half* __restrict__ ohi, __half* __restrict__ olo)
{
    extern __shared__ __align__(16) char fsm[];
    const uint32_t kHi = smem_u32(fsm);
    const uint32_t kLo = kHi + 128 * KST * 2;
    const uint32_t vHi = kLo + 128 * KST * 2;
    const uint32_t vLo = vHi + 128 * KST * 2;

    const int tid  = threadIdx.x;
    const int lane = tid & 31;
    const int w    = tid >> 5;
    const int bh = blockIdx.y;
    const int b = bh >> 4, h = bh & 15;
    const int qrow0 = blockIdx.x * 128;

    const float* Qbase = qkv + (size_t)b * Tk * D3k + h * HDk;
    const float* Kbase = Qbase + Dk;
    const float* Vbase = Qbase + 2 * Dk;

    float slope = 0.f;
#pragma unroll
    for (int i = 1; i <= Hk; i++) slope += exp2f(-0.5f * (float)i);
    slope *= (1.f / (float)Hk);
    const float scale = 0.125f;

    const int grow = tid >> 1;
    const int gcol = (tid & 1) * 32;
    const uint32_t gso = grow * (KST * 2) + gcol * 2;
    {
        const float* qp = Qbase + (size_t)(qrow0 + grow) * D3k + gcol;
#pragma unroll
        for (int j = 0; j < 4; j++) {
            float4 f0 = *(const float4*)(qp + j * 8);
            float4 f1 = *(const float4*)(qp + j * 8 + 4);
            uint4 hi, lo;
            cvt_hilo8(f0, f1, hi, lo);
            sts128(kHi + gso + j * 16, hi);
            sts128(kLo + gso + j * 16, lo);
        }
    }
    __syncthreads();

    uint32_t Qh[4][4], Ql[4][4];
    const uint32_t qOff = (w * 16 + (lane & 15)) * (KST * 2) + (lane >> 4) * 16;
#pragma unroll
    for (int kc = 0; kc < 4; kc++) {
        ldmat_x4(Qh[kc], kHi + qOff + kc * 32);
        ldmat_x4(Ql[kc], kLo + qOff + kc * 32);
    }
    __syncthreads();

    const uint32_t bOff = (((lane >> 4) << 3) + (lane & 7)) * (KST * 2) + ((lane >> 3) & 1) * 16;
    const uint32_t vOff = ((lane & 7) + ((lane >> 3) & 1) * 8) * (KST * 2) + (lane >> 4) * 16;

    float Of[8][4];
#pragma unroll
    for (int i = 0; i < 8; i++)
#pragma unroll
        for (int q = 0; q < 4; q++) Of[i][q] = 0.f;
    float m0 = -1e30f, m1 = -1e30f, l0 = 0.f, l1 = 0.f;

    const float r0f = (float)(qrow0 + w * 16 + (lane >> 2));
    const float r1f = r0f + 8.f;

    for (int kb = 0; kb < Tk / 128; kb++) {
        {
            const float* kp = Kbase + (size_t)(kb * 128 + grow) * D3k + gcol;
            const float* vp = Vbase + (size_t)(kb * 128 + grow) * D3k + gcol;
#pragma unroll
            for (int j = 0; j < 4; j++) {
                float4 f0 = *(const float4*)(kp + j * 8);
                float4 f1 = *(const float4*)(kp + j * 8 + 4);
                uint4 hi, lo;
                cvt_hilo8(f0, f1, hi, lo);
                sts128(kHi + gso + j * 16, hi);
                sts128(kLo + gso + j * 16, lo);
                f0 = *(const float4*)(vp + j * 8);
                f1 = *(const float4*)(vp + j * 8 + 4);
                cvt_hilo8(f0, f1, hi, lo);
                sts128(vHi + gso + j * 16, hi);
                sts128(vLo + gso + j * 16, lo);
            }
        }
        __syncthreads();

        float Sf[16][4];
#pragma unroll
        for (int ntp = 0; ntp < 8; ntp++) {
#pragma unroll
            for (int q = 0; q < 4; q++) { Sf[2 * ntp][q] = 0.f; Sf[2 * ntp + 1][q] = 0.f; }
#pragma unroll
            for (int kc = 0; kc < 4; kc++) {
                uint32_t Bh4[4], Bl4[4];
                ldmat_x4(Bh4, kHi + bOff + ntp * (16 * KST * 2) + kc * 32);
                ldmat_x4(Bl4, kLo + bOff + ntp * (16 * KST * 2) + kc * 32);
                mma16816(Sf[2 * ntp],     Qh[kc], Bh4[0], Bh4[1]);
                mma16816(Sf[2 * ntp],     Qh[kc], Bl4[0], Bl4[1]);
                mma16816(Sf[2 * ntp],     Ql[kc], Bh4[0], Bh4[1]);
                mma16816(Sf[2 * ntp + 1], Qh[kc], Bh4[2], Bh4[3]);
                mma16816(Sf[2 * ntp + 1], Qh[kc], Bl4[2], Bl4[3]);
                mma16816(Sf[2 * ntp + 1], Ql[kc], Bh4[2], Bh4[3]);
            }
        }

        float bm0 = -1e30f, bm1 = -1e30f;
#pragma unroll
        for (int t = 0; t < 16; t++) {
            const float c0f = (float)(kb * 128 + t * 8 + (lane & 3) * 2);
            const float c1f = c0f + 1.f;
            Sf[t][0] = Sf[t][0] * scale - slope * fabsf(r0f - c0f);
            Sf[t][1] = Sf[t][1] * scale - slope * fabsf(r0f - c1f);
            Sf[t][2] = Sf[t][2] * scale - slope * fabsf(r1f - c0f);
            Sf[t][3] = Sf[t][3] * scale - slope * fabsf(r1f - c1f);
            bm0 = fmaxf(bm0, fmaxf(Sf[t][0], Sf[t][1]));
            bm1 = fmaxf(bm1, fmaxf(Sf[t][2], Sf[t][3]));
        }
        bm0 = fmaxf(bm0, __shfl_xor_sync(~0u, bm0, 1));
        bm0 = fmaxf(bm0, __shfl_xor_sync(~0u, bm0, 2));
        bm1 = fmaxf(bm1, __shfl_xor_sync(~0u, bm1, 1));
        bm1 = fmaxf(bm1, __shfl_xor_sync(~0u, bm1, 2));

        const float mn0 = fmaxf(m0, bm0), mn1 = fmaxf(m1, bm1);
        const float sc0 = __expf(m0 - mn0), sc1 = __expf(m1 - mn1);
        l0 *= sc0; l1 *= sc1;
#pragma unroll
        for (int nt = 0; nt < 8; nt++) {
            Of[nt][0] *= sc0; Of[nt][1] *= sc0;
            Of[nt][2] *= sc1; Of[nt][3] *= sc1;
        }
        m0 = mn0; m1 = mn1;

#pragma unroll
        for (int t = 0; t < 16; t++) {
            Sf[t][0] = __expf(Sf[t][0] - mn0);
            Sf[t][1] = __expf(Sf[t][1] - mn0);
            Sf[t][2] = __expf(Sf[t][2] - mn1);
            Sf[t][3] = __expf(Sf[t][3] - mn1);
            l0 += Sf[t][0] + Sf[t][1];
            l1 += Sf[t][2] + Sf[t][3];
        }

        uint32_t Ph[8][4], Pl[8][4];
#pragma unroll
        for (int kc = 0; kc < 8; kc++) {
            cvt_hilo2(Sf[2 * kc][0],     Sf[2 * kc][1],     Ph[kc][0], Pl[kc][0]);
            cvt_hilo2(Sf[2 * kc][2],     Sf[2 * kc][3],     Ph[kc][1], Pl[kc][1]);
            cvt_hilo2(Sf[2 * kc + 1][0], Sf[2 * kc + 1][1], Ph[kc][2], Pl[kc][2]);
            cvt_hilo2(Sf[2 * kc + 1][2], Sf[2 * kc + 1][3], Ph[kc][3], Pl[kc][3]);
        }

#pragma unroll
        for (int ntp = 0; ntp < 4; ntp++) {
#pragma unroll
            for (int kc = 0; kc < 8; kc++) {
                uint32_t Vh4[4], Vl4[4];
                ldmat_x4_t(Vh4, vHi + vOff + kc * (16 * KST * 2) + ntp * 32);
                ldmat_x4_t(Vl4, vLo + vOff + kc * (16 * KST * 2) + ntp * 32);
                mma16816(Of[2 * ntp],     Ph[kc], Vh4[0], Vh4[1]);
                mma16816(Of[2 * ntp],     Ph[kc], Vl4[0], Vl4[1]);
                mma16816(Of[2 * ntp],     Pl[kc], Vh4[0], Vh4[1]);
                mma16816(Of[2 * ntp + 1], Ph[kc], Vh4[2], Vh4[3]);
                mma16816(Of[2 * ntp + 1], Ph[kc], Vl4[2], Vl4[3]);
                mma16816(Of[2 * ntp + 1], Pl[kc], Vh4[2], Vh4[3]);
            }
        }
        __syncthreads();
    }

    l0 += __shfl_xor_sync(~0u, l0, 1);
    l0 += __shfl_xor_sync(~0u, l0, 2);
    l1 += __shfl_xor_sync(~0u, l1, 1);
    l1 += __shfl_xor_sync(~0u, l1, 2);
    const float inv0 = 1.f / l0, inv1 = 1.f / l1;

    const int row0 = qrow0 + w * 16 + (lane >> 2);
    __half* ohb = ohi + (size_t)b * Tk * Dk + h * HDk;
    __half* olb = olo + (size_t)b * Tk * Dk + h * HDk;
#pragma unroll
    for (int nt = 0; nt < 8; nt++) {
        const int cc = nt * 8 + (lane & 3) * 2;
        uint32_t hv, lv;
        cvt_hilo2h(Of[nt][0] * inv0, Of[nt][1] * inv0, hv, lv);
        *(uint32_t*)(ohb + (size_t)row0 * Dk + cc) = hv;
        *(uint32_t*)(olb + (size_t)row0 * Dk + cc) = lv;
        cvt_hilo2h(Of[nt][2] * inv1, Of[nt][3] * inv1, hv, lv);
        *(uint32_t*)(ohb + (size_t)(row0 + 8) * Dk + cc) = hv;
        *(uint32_t*)(olb + (size_t)(row0 + 8) * Dk + cc) = lv;
    }
}

// ---------------------------------------------------------------------------
// h = LN(h + o) * g + b; also writes h as fp16 hi/lo for the next GEMM.
// ---------------------------------------------------------------------------
__global__ __launch_bounds__(256) void ln_residual_kernel(
    float* __restrict__ h, const float* __restrict__ o,
    const float* __restrict__ gam, const float* __restrict__ bet,
    __half* __restrict__ hhi, __half* __restrict__ hlo)
{
    __shared__ float rs[8], rs2[8];
    const size_t row = blockIdx.x;
    float* hp = h + row * Dk;
    const float* op = o + row * Dk;
    const int tid = threadIdx.x;

    float4 hv = ((const float4*)hp)[tid];
    float4 ov = ((const float4*)op)[tid];
    float r0 = hv.x + ov.x, r1 = hv.y + ov.y, r2 = hv.z + ov.z, r3 = hv.w + ov.w;

    float s  = r0 + r1 + r2 + r3;
    float s2 = r0 * r0 + r1 * r1 + r2 * r2 + r3 * r3;
#pragma unroll
    for (int of = 16; of; of >>= 1) {
        s  += __shfl_xor_sync(~0u, s,  of);
        s2 += __shfl_xor_sync(~0u, s2, of);
    }
    if ((tid & 31) == 0) { rs[tid >> 5] = s; rs2[tid >> 5] = s2; }
    __syncthreads();
    float S = 0.f, S2 = 0.f;
#pragma unroll
    for (int i = 0; i < 8; i++) { S += rs[i]; S2 += rs2[i]; }

    const float mu  = S * (1.f / (float)Dk);
    const float var = S2 * (1.f / (float)Dk) - mu * mu;
    const float inv = rsqrtf(var + EPSk);

    float4 gg = ((const float4*)gam)[tid];
    float4 bb = ((const float4*)bet)[tid];
    float4 out;
    out.x = (r0 - mu) * inv * gg.x + bb.x;
    out.y = (r1 - mu) * inv * gg.y + bb.y;
    out.z = (r2 - mu) * inv * gg.z + bb.z;
    out.w = (r3 - mu) * inv * gg.w + bb.w;
    ((float4*)hp)[tid] = out;

    uint32_t h0, l0w, h1, l1w;
    cvt_hilo2h(out.x, out.y, h0, l0w);
    cvt_hilo2h(out.z, out.w, h1, l1w);
    *(uint2*)(hhi + row * Dk + tid * 4) = make_uint2(h0, h1);
    *(uint2*)(hlo + row * Dk + tid * 4) = make_uint2(l0w, l1w);
}

// ---------------------------------------------------------------------------
// head
// ---------------------------------------------------------------------------
__global__ void head_kernel(const float* __restrict__ h,
                            const float* __restrict__ hw,
                            const float* __restrict__ hb,
                            float* __restrict__ outp)
{
    const int idx = blockIdx.x;
    const int b = idx / Ck, c = idx % Ck;
    const float* hp = h + ((size_t)b * Tk + (Tk - 1)) * Dk;
    const float* wp = hw + (size_t)c * Dk;
    const int lane = threadIdx.x;
    float s = 0.f;
    for (int i = lane; i < Dk; i += 32) s += hp[i] * wp[i];
#pragma unroll
    for (int o = 16; o; o >>= 1) s += __shfl_xor_sync(~0u, s, o);
    if (lane == 0) outp[idx] = s + hb[c];
}

// ---------------------------------------------------------------------------
// Host orchestration
// ---------------------------------------------------------------------------
extern "C" void kernel_launch(void* const* d_in, const int* in_sizes, int n_in,
                              void* d_out, int out_size)
{
    (void)in_sizes; (void)n_in; (void)out_size;
    const float* x       = (const float*)d_in[0];
    const float* input_w = (const float*)d_in[1];
    const float* input_b = (const float*)d_in[2];
    const float* Wqkv    = (const float*)d_in[3];
    const float* bqkv    = (const float*)d_in[4];
    const float* Wo      = (const float*)d_in[5];
    const float* bo      = (const float*)d_in[6];
    const float* ln1_g   = (const float*)d_in[7];
    const float* ln1_b   = (const float*)d_in[8];
    const float* ln2_g   = (const float*)d_in[9];
    const float* ln2_b   = (const float*)d_in[10];
    const float* W1      = (const float*)d_in[11];
    const float* b1      = (const float*)d_in[12];
    const float* W2      = (const float*)d_in[13];
    const float* b2      = (const float*)d_in[14];
    const float* head_w  = (const float*)d_in[15];
    const float* head_b  = (const float*)d_in[16];
    float* outp = (float*)d_out;

    float *h, *tmp, *qkv;
    __half *xhi, *xlo, *hhi, *hlo, *ohi, *olo, *fhi, *flo;
    __half *winh, *wqh, *woh, *w1h, *w2h;
    cudaGetSymbolAddress((void**)&h,    g_h);
    cudaGetSymbolAddress((void**)&tmp,  g_tmp);
    cudaGetSymbolAddress((void**)&qkv,  g_qkv);
    cudaGetSymbolAddress((void**)&xhi,  g_x_hi);  cudaGetSymbolAddress((void**)&xlo,  g_x_lo);
    cudaGetSymbolAddress((void**)&hhi,  g_h_hi);  cudaGetSymbolAddress((void**)&hlo,  g_h_lo);
    cudaGetSymbolAddress((void**)&ohi,  g_o_hi);  cudaGetSymbolAddress((void**)&olo,  g_o_lo);
    cudaGetSymbolAddress((void**)&fhi,  g_ff_hi); cudaGetSymbolAddress((void**)&flo,  g_ff_lo);
    cudaGetSymbolAddress((void**)&winh, g_win_h);
    cudaGetSymbolAddress((void**)&wqh,  g_wqkv_h);
    cudaGetSymbolAddress((void**)&woh,  g_wo_h);
    cudaGetSymbolAddress((void**)&w1h,  g_w1_h);
    cudaGetSymbolAddress((void**)&w2h,  g_w2_h);

    cudaFuncSetAttribute(mma_gemm_f16_nt,
                         cudaFuncAttributeMaxDynamicSharedMemorySize, GEMM_SMEM);
    cudaFuncSetAttribute(flash_attn_kernel,
                         cudaFuncAttributeMaxDynamicSharedMemorySize, FLASH_SMEM);

    const int M = Bk * Tk;  // 4096
    dim3 blk(256);

    // ---- conversions: x -> fp16 hi/lo, weights -> fp16
    cvt_hl16_kernel<<<(Bk * Tk * INk) / 1024, 256>>>(x, xhi, xlo, Bk * Tk * INk);
    cvt_h16_kernel<<<(Dk * INk) / 1024, 256>>>(input_w, winh, Dk * INk);
    cvt_h16_kernel<<<(Lk * D3k * Dk) / 1024, 256>>>(Wqkv, wqh, Lk * D3k * Dk);
    cvt_h16_kernel<<<(Lk * Dk * Dk) / 1024, 256>>>(Wo, woh, Lk * Dk * Dk);
    cvt_h16_kernel<<<(Lk * FFk * Dk) / 1024, 256>>>(W1, w1h, Lk * FFk * Dk);
    cvt_h16_kernel<<<(Lk * Dk * FFk) / 1024, 256>>>(W2, w2h, Lk * Dk * FFk);

    // ---- input projection: h (fp32) + h hi/lo
    mma_gemm_f16_nt<<<dim3(Dk / 128, M / 128), blk, GEMM_SMEM>>>(
        xhi, xlo, INk, winh, INk, input_b, h, hhi, hlo, Dk, INk, 2 | 4);

    for (int l = 0; l < Lk; l++) {
        // qkv (fp32 out, feeds flash)
        mma_gemm_f16_nt<<<dim3(D3k / 128, M / 128), blk, GEMM_SMEM>>>(
            hhi, hlo, Dk, wqh + (size_t)l * D3k * Dk, Dk,
            bqkv + (size_t)l * D3k, qkv, nullptr, nullptr, D3k, Dk, 2);
        // attention -> o hi/lo
        flash_attn_kernel<<<dim3(Tk / 128, Bk * Hk), blk, FLASH_SMEM>>>(qkv, ohi, olo);
        // Wo proj (fp32 out)
        mma_gemm_f16_nt<<<dim3(Dk / 128, M / 128), blk, GEMM_SMEM>>>(
            ohi, olo, Dk, woh + (size_t)l * Dk * Dk, Dk,
            bo + (size_t)l * Dk, tmp, nullptr, nullptr, Dk, Dk, 2);
        // LN1 -> h fp32 + h hi/lo
        ln_residual_kernel<<<M, 256>>>(h, tmp, ln1_g + (size_t)l * Dk, ln1_b + (size_t)l * Dk,
                                       hhi, hlo);
        // FF1 (relu, hi/lo out only)
        mma_gemm_f16_nt<<<dim3(FFk / 128, M / 128), blk, GEMM_SMEM>>>(
            hhi, hlo, Dk, w1h + (size_t)l * FFk * Dk, Dk,
            b1 + (size_t)l * FFk, nullptr, fhi, flo, FFk, Dk, 1 | 4);
        // FF2 (fp32 out)
        mma_gemm_f16_nt<<<dim3(Dk / 128, M / 128), blk, GEMM_SMEM>>>(
            fhi, flo, FFk, w2h + (size_t)l * Dk * FFk, FFk,
            b2 + (size_t)l * Dk, tmp, nullptr, nullptr, Dk, FFk, 2);
        // LN2 -> h fp32 + h hi/lo
        ln_residual_kernel<<<M, 256>>>(h, tmp, ln2_g + (size_t)l * Dk, ln2_b + (size_t)l * Dk,
                                       hhi, hlo);
    }

    head_kernel<<<Bk * Ck, 32>>>(h, head_w, head_b, outp);
}

// round 10
// speedup vs baseline: 3.1953x; 1.0015x over previous
#include <cuda_runtime.h>
#include <cuda_bf16.h>
#include <cuda_fp16.h>
#include <math.h>
#include <stdint.h>

// ---------------------------------------------------------------------------
// Problem constants
// ---------------------------------------------------------------------------
namespace {
constexpr int Bk = 4;       // batch
constexpr int Tk = 1024;    // seq len
constexpr int INk = 256;    // input dim
constexpr int Dk = 1024;    // model dim
constexpr int Hk = 16;      // heads
constexpr int HDk = 64;     // head dim
constexpr int FFk = 4096;   // ff dim
constexpr int Ck = 10;      // classes
constexpr int Lk = 6;       // layers
constexpr int D3k = 3 * Dk;
constexpr float EPSk = 1e-5f;
}

// ---------------------------------------------------------------------------
// Scratch buffers (static device globals — no allocations allowed)
// ---------------------------------------------------------------------------
__device__ float g_h[Bk * Tk * Dk];
__device__ float g_tmp[Bk * Tk * Dk];
__device__ float g_qkv[Bk * Tk * D3k];

// fp16 hi/lo activation buffers
__device__ __half g_x_hi[Bk * Tk * INk],  g_x_lo[Bk * Tk * INk];
__device__ __half g_h_hi[Bk * Tk * Dk],   g_h_lo[Bk * Tk * Dk];
__device__ __half g_o_hi[Bk * Tk * Dk],   g_o_lo[Bk * Tk * Dk];
__device__ __half g_ff_hi[Bk * Tk * FFk], g_ff_lo[Bk * Tk * FFk];

// fp16 weight buffers (single rounding)
__device__ __half g_win_h[Dk * INk];
__device__ __half g_wqkv_h[Lk * D3k * Dk];
__device__ __half g_wo_h[Lk * Dk * Dk];
__device__ __half g_w1_h[Lk * FFk * Dk];
__device__ __half g_w2_h[Lk * Dk * FFk];

// ---------------------------------------------------------------------------
// PTX helpers (sm_80-era features only — compile on base sm_100)
// ---------------------------------------------------------------------------
__device__ __forceinline__ uint32_t smem_u32(const void* p) {
    uint32_t a;
    asm("{ .reg .u64 t; cvta.to.shared.u64 t, %1; cvt.u32.u64 %0, t; }"
        : "=r"(a) : "l"(p));
    return a;
}

__device__ __forceinline__ void ldmat_x4(uint32_t* r, uint32_t addr) {
    asm volatile("ldmatrix.sync.aligned.m8n8.x4.shared.b16 {%0,%1,%2,%3}, [%4];"
                 : "=r"(r[0]), "=r"(r[1]), "=r"(r[2]), "=r"(r[3]) : "r"(addr));
}

__device__ __forceinline__ void ldmat_x4_t(uint32_t* r, uint32_t addr) {
    asm volatile("ldmatrix.sync.aligned.m8n8.x4.trans.shared.b16 {%0,%1,%2,%3}, [%4];"
                 : "=r"(r[0]), "=r"(r[1]), "=r"(r[2]), "=r"(r[3]) : "r"(addr));
}

// bf16 mma (flash attention)
__device__ __forceinline__ void mma16816(float* c, const uint32_t* a,
                                         uint32_t b0, uint32_t b1) {
    asm volatile(
        "mma.sync.aligned.m16n8k16.row.col.f32.bf16.bf16.f32 "
        "{%0,%1,%2,%3}, {%4,%5,%6,%7}, {%8,%9}, {%0,%1,%2,%3};"
        : "+f"(c[0]), "+f"(c[1]), "+f"(c[2]), "+f"(c[3])
        : "r"(a[0]), "r"(a[1]), "r"(a[2]), "r"(a[3]), "r"(b0), "r"(b1));
}

// fp16 mma (dense GEMMs)
__device__ __forceinline__ void mma16816h(float* c, const uint32_t* a,
                                          uint32_t b0, uint32_t b1) {
    asm volatile(
        "mma.sync.aligned.m16n8k16.row.col.f32.f16.f16.f32 "
        "{%0,%1,%2,%3}, {%4,%5,%6,%7}, {%8,%9}, {%0,%1,%2,%3};"
        : "+f"(c[0]), "+f"(c[1]), "+f"(c[2]), "+f"(c[3])
        : "r"(a[0]), "r"(a[1]), "r"(a[2]), "r"(a[3]), "r"(b0), "r"(b1));
}

__device__ __forceinline__ void sts128(uint32_t addr, uint4 v) {
    asm volatile("st.shared.v4.b32 [%0], {%1,%2,%3,%4};"
                 :: "r"(addr), "r"(v.x), "r"(v.y), "r"(v.z), "r"(v.w) : "memory");
}

__device__ __forceinline__ void cp_async16(uint32_t saddr, const void* gptr) {
    asm volatile("cp.async.cg.shared.global [%0], [%1], 16;"
                 :: "r"(saddr), "l"(gptr) : "memory");
}
#define CP_COMMIT() asm volatile("cp.async.commit_group;" ::: "memory")
#define CP_WAIT1()  asm volatile("cp.async.wait_group 1;" ::: "memory")
#define CP_WAIT0()  asm volatile("cp.async.wait_group 0;" ::: "memory")

// ---- bf16 hi/lo split (flash attention path)
__device__ __forceinline__ void cvt_hilo2(float a, float b, uint32_t& hi, uint32_t& lo) {
    __nv_bfloat162 h = __floats2bfloat162_rn(a, b);
    float2 hf = __bfloat1622float2(h);
    __nv_bfloat162 l = __floats2bfloat162_rn(a - hf.x, b - hf.y);
    hi = *reinterpret_cast<uint32_t*>(&h);
    lo = *reinterpret_cast<uint32_t*>(&l);
}

__device__ __forceinline__ void cvt_hilo8(float4 a, float4 b, uint4& hi, uint4& lo) {
    cvt_hilo2(a.x, a.y, hi.x, lo.x);
    cvt_hilo2(a.z, a.w, hi.y, lo.y);
    cvt_hilo2(b.x, b.y, hi.z, lo.z);
    cvt_hilo2(b.z, b.w, hi.w, lo.w);
}

// ---- fp16 hi/lo split (dense GEMM activations)
__device__ __forceinline__ void cvt_hilo2h(float a, float b, uint32_t& hi, uint32_t& lo) {
    __half2 h = __floats2half2_rn(a, b);
    float2 hf = __half22float2(h);
    __half2 l = __floats2half2_rn(a - hf.x, b - hf.y);
    hi = *reinterpret_cast<uint32_t*>(&h);
    lo = *reinterpret_cast<uint32_t*>(&l);
}

// ---------------------------------------------------------------------------
// Conversion kernels
// ---------------------------------------------------------------------------
__global__ __launch_bounds__(256) void cvt_hl16_kernel(
    const float* __restrict__ src, __half* __restrict__ hi,
    __half* __restrict__ lo, int n)
{
    const int i = (blockIdx.x * 256 + threadIdx.x) * 4;
    if (i >= n) return;
    float4 v = *(const float4*)(src + i);
    uint32_t h0, l0, h1, l1;
    cvt_hilo2h(v.x, v.y, h0, l0);
    cvt_hilo2h(v.z, v.w, h1, l1);
    *(uint2*)(hi + i) = make_uint2(h0, h1);
    *(uint2*)(lo + i) = make_uint2(l0, l1);
}

__global__ __launch_bounds__(256) void cvt_h16_kernel(
    const float* __restrict__ src, __half* __restrict__ dst, int n)
{
    const int i = (blockIdx.x * 256 + threadIdx.x) * 4;
    if (i >= n) return;
    float4 v = *(const float4*)(src + i);
    __half2 h0 = __floats2half2_rn(v.x, v.y);
    __half2 h1 = __floats2half2_rn(v.z, v.w);
    *(uint2*)(dst + i) = make_uint2(*reinterpret_cast<uint32_t*>(&h0),
                                    *reinterpret_cast<uint32_t*>(&h1));
}

// ---------------------------------------------------------------------------
// fp16 2-term NT GEMM: C = (Ahi+Alo) * W^T + bias.
// A as fp16 hi/lo pair, W as single fp16. 2 MMAs per tile.
// 128x128 tile, BK=32, 3-stage cp.async pipeline, 1 syncthreads/chunk.
// flags: 1=relu, 2=write fp32 C, 4=write fp16 hi/lo C
// ---------------------------------------------------------------------------
namespace {
constexpr int SST = 40;                        // smem row stride (fp16)
constexpr int ARR_B = 128 * SST * 2;           // 10240 bytes per tile array
constexpr int STAGE_B = 3 * ARR_B;             // Ahi|Alo|Bh = 30720 bytes
}
static constexpr int GEMM_SMEM = 3 * STAGE_B;  // 92160

__global__ __launch_bounds__(256) void mma_gemm_f16_nt(
    const __half* __restrict__ Ahi, const __half* __restrict__ Alo, int lda,
    const __half* __restrict__ Bh, int ldb,
    const float* __restrict__ bias,
    float* __restrict__ Cf, __half* __restrict__ Chi, __half* __restrict__ Clo,
    int ldc, int K, int flags)
{
    extern __shared__ __align__(16) char gsm[];
    const uint32_t base = smem_u32(gsm);

    const int tid  = threadIdx.x;
    const int lane = tid & 31;
    const int wid  = tid >> 5;
    const int wm   = wid & 3;
    const int wn   = wid >> 2;
    const int row0 = blockIdx.y * 128;
    const int col0 = blockIdx.x * 128;

    const int grow = tid >> 1;
    const int gc16 = (tid & 1) * 16;
    const __half* Ah_p = Ahi + (size_t)(row0 + grow) * lda + gc16;
    const __half* Al_p = Alo + (size_t)(row0 + grow) * lda + gc16;
    const __half* Bh_p = Bh  + (size_t)(col0 + grow) * ldb + gc16;
    const uint32_t soff = grow * (SST * 2) + gc16 * 2;

    const uint32_t aRowOff = (uint32_t)((wm * 32 + (lane & 15)) * SST * 2 + (lane >> 4) * 16);
    const uint32_t bRowOff = (uint32_t)(((wn * 64 + ((lane >> 4) << 3) + (lane & 7)) * SST) * 2
                                        + ((lane >> 3) & 1) * 16);

    float acc[2][8][4];
#pragma unroll
    for (int i = 0; i < 2; i++)
#pragma unroll
        for (int j = 0; j < 8; j++)
#pragma unroll
            for (int q = 0; q < 4; q++) acc[i][j][q] = 0.f;

    const int nc = K >> 5;

    auto issue = [&](int c, int s) {
        const uint32_t sb = base + s * STAGE_B;
        const __half* p = Ah_p + c * 32;
        cp_async16(sb + soff, p);                 cp_async16(sb + soff + 16, p + 8);
        p = Al_p + c * 32;
        cp_async16(sb + ARR_B + soff, p);         cp_async16(sb + ARR_B + soff + 16, p + 8);
        p = Bh_p + c * 32;
        cp_async16(sb + 2 * ARR_B + soff, p);     cp_async16(sb + 2 * ARR_B + soff + 16, p + 8);
        CP_COMMIT();
    };

    issue(0, 0);
    if (nc > 1) issue(1, 1);

    for (int c = 0; c < nc; c++) {
        if (c + 1 < nc) { CP_WAIT1(); }
        else            { CP_WAIT0(); }
        __syncthreads();
        if (c + 2 < nc) issue(c + 2, (c + 2) % 3);

        const uint32_t sb = base + (c % 3) * STAGE_B;
        const uint32_t aHi = sb, aLo = sb + ARR_B, bHi = sb + 2 * ARR_B;

#pragma unroll
        for (int ks = 0; ks < 2; ks++) {
            const uint32_t kb = ks * 32;
            uint32_t Ah4[2][4], Al4[2][4];
#pragma unroll
            for (int mt = 0; mt < 2; mt++) {
                ldmat_x4(Ah4[mt], aHi + aRowOff + mt * (16 * SST * 2) + kb);
                ldmat_x4(Al4[mt], aLo + aRowOff + mt * (16 * SST * 2) + kb);
            }
#pragma unroll
            for (int pr = 0; pr < 4; pr++) {
                uint32_t B4[4];
                ldmat_x4(B4, bHi + bRowOff + pr * (16 * SST * 2) + kb);
#pragma unroll
                for (int sbb = 0; sbb < 2; sbb++) {
                    const int nt = pr * 2 + sbb;
#pragma unroll
                    for (int mt = 0; mt < 2; mt++) {
                        mma16816h(acc[mt][nt], Ah4[mt], B4[sbb * 2], B4[sbb * 2 + 1]);
                        mma16816h(acc[mt][nt], Al4[mt], B4[sbb * 2], B4[sbb * 2 + 1]);
                    }
                }
            }
        }
    }
    __syncthreads();

    // ---- epilogue
    const int erow = lane >> 2;
    const int ecol = (lane & 3) * 2;
    const int relu = flags & 1;
#pragma unroll
    for (int mt = 0; mt < 2; mt++) {
        const int r = row0 + wm * 32 + mt * 16 + erow;
#pragma unroll
        for (int nt = 0; nt < 8; nt++) {
            const int cc = col0 + wn * 64 + nt * 8 + ecol;
            float2 bv = *(const float2*)(bias + cc);
            float2 v0, v1;
            v0.x = acc[mt][nt][0] + bv.x;  v0.y = acc[mt][nt][1] + bv.y;
            v1.x = acc[mt][nt][2] + bv.x;  v1.y = acc[mt][nt][3] + bv.y;
            if (relu) {
                v0.x = fmaxf(v0.x, 0.f); v0.y = fmaxf(v0.y, 0.f);
                v1.x = fmaxf(v1.x, 0.f); v1.y = fmaxf(v1.y, 0.f);
            }
            if (flags & 2) {
                *(float2*)(Cf + (size_t)r * ldc + cc)       = v0;
                *(float2*)(Cf + (size_t)(r + 8) * ldc + cc) = v1;
            }
            if (flags & 4) {
                uint32_t hv, lv;
                cvt_hilo2h(v0.x, v0.y, hv, lv);
                *(uint32_t*)(Chi + (size_t)r * ldc + cc) = hv;
                *(uint32_t*)(Clo + (size_t)r * ldc + cc) = lv;
                cvt_hilo2h(v1.x, v1.y, hv, lv);
                *(uint32_t*)(Chi + (size_t)(r + 8) * ldc + cc) = hv;
                *(uint32_t*)(Clo + (size_t)(r + 8) * ldc + cc) = lv;
            }
        }
    }
}

// ---------------------------------------------------------------------------
// Fused flash attention (bf16 3-term, unchanged math); writes o fp16 hi/lo.
// ---------------------------------------------------------------------------
namespace { constexpr int KST = 72; }
static constexpr int FLASH_SMEM = 4 * 128 * KST * 2;   // 73728 B

__global__ __launch_bounds__(256) void flash_attn_kernel(
    const float* __restrict__ qkv,
    __half* __restrict__ ohi, __half* __restrict__ olo)
{
    extern __shared__ __align__(16) char fsm[];
    const uint32_t kHi = smem_u32(fsm);
    const uint32_t kLo = kHi + 128 * KST * 2;
    const uint32_t vHi = kLo + 128 * KST * 2;
    const uint32_t vLo = vHi + 128 * KST * 2;

    const int tid  = threadIdx.x;
    const int lane = tid & 31;
    const int w    = tid >> 5;
    const int bh = blockIdx.y;
    const int b = bh >> 4, h = bh & 15;
    const int qrow0 = blockIdx.x * 128;

    const float* Qbase = qkv + (size_t)b * Tk * D3k + h * HDk;
    const float* Kbase = Qbase + Dk;
    const float* Vbase = Qbase + 2 * Dk;

    float slope = 0.f;
#pragma unroll
    for (int i = 1; i <= Hk; i++) slope += exp2f(-0.5f * (float)i);
    slope *= (1.f / (float)Hk);
    const float scale = 0.125f;

    const int grow = tid >> 1;
    const int gcol = (tid & 1) * 32;
    const uint32_t gso = grow * (KST * 2) + gcol * 2;
    {
        const float* qp = Qbase + (size_t)(qrow0 + grow) * D3k + gcol;
#pragma unroll
        for (int j = 0; j < 4; j++) {
            float4 f0 = *(const float4*)(qp + j * 8);
            float4 f1 = *(const float4*)(qp + j * 8 + 4);
            uint4 hi, lo;
            cvt_hilo8(f0, f1, hi, lo);
            sts128(kHi + gso + j * 16, hi);
            sts128(kLo + gso + j * 16, lo);
        }
    }
    __syncthreads();

    uint32_t Qh[4][4], Ql[4][4];
    const uint32_t qOff = (w * 16 + (lane & 15)) * (KST * 2) + (lane >> 4) * 16;
#pragma unroll
    for (int kc = 0; kc < 4; kc++) {
        ldmat_x4(Qh[kc], kHi + qOff + kc * 32);
        ldmat_x4(Ql[kc], kLo + qOff + kc * 32);
    }
    __syncthreads();

    const uint32_t bOff = (((lane >> 4) << 3) + (lane & 7)) * (KST * 2) + ((lane >> 3) & 1) * 16;
    const uint32_t vOff = ((lane & 7) + ((lane >> 3) & 1) * 8) * (KST * 2) + (lane >> 4) * 16;

    float Of[8][4];
#pragma unroll
    for (int i = 0; i < 8; i++)
#pragma unroll
        for (int q = 0; q < 4; q++) Of[i][q] = 0.f;
    float m0 = -1e30f, m1 = -1e30f, l0 = 0.f, l1 = 0.f;

    const float r0f = (float)(qrow0 + w * 16 + (lane >> 2));
    const float r1f = r0f + 8.f;

    for (int kb = 0; kb < Tk / 128; kb++) {
        {
            const float* kp = Kbase + (size_t)(kb * 128 + grow) * D3k + gcol;
            const float* vp = Vbase + (size_t)(kb * 128 + grow) * D3k + gcol;
#pragma unroll
            for (int j = 0; j < 4; j++) {
                float4 f0 = *(const float4*)(kp + j * 8);
                float4 f1 = *(const float4*)(kp + j * 8 + 4);
                uint4 hi, lo;
                cvt_hilo8(f0, f1, hi, lo);
                sts128(kHi + gso + j * 16, hi);
                sts128(kLo + gso + j * 16, lo);
                f0 = *(const float4*)(vp + j * 8);
                f1 = *(const float4*)(vp + j * 8 + 4);
                cvt_hilo8(f0, f1, hi, lo);
                sts128(vHi + gso + j * 16, hi);
                sts128(vLo + gso + j * 16, lo);
            }
        }
        __syncthreads();

        float Sf[16][4];
#pragma unroll
        for (int ntp = 0; ntp < 8; ntp++) {
#pragma unroll
            for (int q = 0; q < 4; q++) { Sf[2 * ntp][q] = 0.f; Sf[2 * ntp + 1][q] = 0.f; }
#pragma unroll
            for (int kc = 0; kc < 4; kc++) {
                uint32_t Bh4[4], Bl4[4];
                ldmat_x4(Bh4, kHi + bOff + ntp * (16 * KST * 2) + kc * 32);
                ldmat_x4(Bl4, kLo + bOff + ntp * (16 * KST * 2) + kc * 32);
                mma16816(Sf[2 * ntp],     Qh[kc], Bh4[0], Bh4[1]);
                mma16816(Sf[2 * ntp],     Qh[kc], Bl4[0], Bl4[1]);
                mma16816(Sf[2 * ntp],     Ql[kc], Bh4[0], Bh4[1]);
                mma16816(Sf[2 * ntp + 1], Qh[kc], Bh4[2], Bh4[3]);
                mma16816(Sf[2 * ntp + 1], Qh[kc], Bl4[2], Bl4[3]);
                mma16816(Sf[2 * ntp + 1], Ql[kc], Bh4[2], Bh4[3]);
            }
        }

        float bm0 = -1e30f, bm1 = -1e30f;
#pragma unroll
        for (int t = 0; t < 16; t++) {
            const float c0f = (float)(kb * 128 + t * 8 + (lane & 3) * 2);
            const float c1f = c0f + 1.f;
            Sf[t][0] = Sf[t][0] * scale - slope * fabsf(r0f - c0f);
            Sf[t][1] = Sf[t][1] * scale - slope * fabsf(r0f - c1f);
            Sf[t][2] = Sf[t][2] * scale - slope * fabsf(r1f - c0f);
            Sf[t][3] = Sf[t][3] * scale - slope * fabsf(r1f - c1f);
            bm0 = fmaxf(bm0, fmaxf(Sf[t][0], Sf[t][1]));
            bm1 = fmaxf(bm1, fmaxf(Sf[t][2], Sf[t][3]));
        }
        bm0 = fmaxf(bm0, __shfl_xor_sync(~0u, bm0, 1));
        bm0 = fmaxf(bm0, __shfl_xor_sync(~0u, bm0, 2));
        bm1 = fmaxf(bm1, __shfl_xor_sync(~0u, bm1, 1));
        bm1 = fmaxf(bm1, __shfl_xor_sync(~0u, bm1, 2));

        const float mn0 = fmaxf(m0, bm0), mn1 = fmaxf(m1, bm1);
        const float sc0 = __expf(m0 - mn0), sc1 = __expf(m1 - mn1);
        l0 *= sc0; l1 *= sc1;
#pragma unroll
        for (int nt = 0; nt < 8; nt++) {
            Of[nt][0] *= sc0; Of[nt][1] *= sc0;
            Of[nt][2] *= sc1; Of[nt][3] *= sc1;
        }
        m0 = mn0; m1 = mn1;

#pragma unroll
        for (int t = 0; t < 16; t++) {
            Sf[t][0] = __expf(Sf[t][0] - mn0);
            Sf[t][1] = __expf(Sf[t][1] - mn0);
            Sf[t][2] = __expf(Sf[t][2] - mn1);
            Sf[t][3] = __expf(Sf[t][3] - mn1);
            l0 += Sf[t][0] + Sf[t][1];
            l1 += Sf[t][2] + Sf[t][3];
        }

        uint32_t Ph[8][4], Pl[8][4];
#pragma unroll
        for (int kc = 0; kc < 8; kc++) {
            cvt_hilo2(Sf[2 * kc][0],     Sf[2 * kc][1],     Ph[kc][0], Pl[kc][0]);
            cvt_hilo2(Sf[2 * kc][2],     Sf[2 * kc][3],     Ph[kc][1], Pl[kc][1]);
            cvt_hilo2(Sf[2 * kc + 1][0], Sf[2 * kc + 1][1], Ph[kc][2], Pl[kc][2]);
            cvt_hilo2(Sf[2 * kc + 1][2], Sf[2 * kc + 1][3], Ph[kc][3], Pl[kc][3]);
        }

#pragma unroll
        for (int ntp = 0; ntp < 4; ntp++) {
#pragma unroll
            for (int kc = 0; kc < 8; kc++) {
                uint32_t Vh4[4], Vl4[4];
                ldmat_x4_t(Vh4, vHi + vOff + kc * (16 * KST * 2) + ntp * 32);
                ldmat_x4_t(Vl4, vLo + vOff + kc * (16 * KST * 2) + ntp * 32);
                mma16816(Of[2 * ntp],     Ph[kc], Vh4[0], Vh4[1]);
                mma16816(Of[2 * ntp],     Ph[kc], Vl4[0], Vl4[1]);
                mma16816(Of[2 * ntp],     Pl[kc], Vh4[0], Vh4[1]);
                mma16816(Of[2 * ntp + 1], Ph[kc], Vh4[2], Vh4[3]);
                mma16816(Of[2 * ntp + 1], Ph[kc], Vl4[2], Vl4[3]);
                mma16816(Of[2 * ntp + 1], Pl[kc], Vh4[2], Vh4[3]);
            }
        }
        __syncthreads();
    }

    l0 += __shfl_xor_sync(~0u, l0, 1);
    l0 += __shfl_xor_sync(~0u, l0, 2);
    l1 += __shfl_xor_sync(~0u, l1, 1);
    l1 += __shfl_xor_sync(~0u, l1, 2);
    const float inv0 = 1.f / l0, inv1 = 1.f / l1;

    const int row0 = qrow0 + w * 16 + (lane >> 2);
    __half* ohb = ohi + (size_t)b * Tk * Dk + h * HDk;
    __half* olb = olo + (size_t)b * Tk * Dk + h * HDk;
#pragma unroll
    for (int nt = 0; nt < 8; nt++) {
        const int cc = nt * 8 + (lane & 3) * 2;
        uint32_t hv, lv;
        cvt_hilo2h(Of[nt][0] * inv0, Of[nt][1] * inv0, hv, lv);
        *(uint32_t*)(ohb + (size_t)row0 * Dk + cc) = hv;
        *(uint32_t*)(olb + (size_t)row0 * Dk + cc) = lv;
        cvt_hilo2h(Of[nt][2] * inv1, Of[nt][3] * inv1, hv, lv);
        *(uint32_t*)(ohb + (size_t)(row0 + 8) * Dk + cc) = hv;
        *(uint32_t*)(olb + (size_t)(row0 + 8) * Dk + cc) = lv;
    }
}

// ---------------------------------------------------------------------------
// h = LN(h + o) * g + b; also writes h as fp16 hi/lo for the next GEMM.
// ---------------------------------------------------------------------------
__global__ __launch_bounds__(256) void ln_residual_kernel(
    float* __restrict__ h, const float* __restrict__ o,
    const float* __restrict__ gam, const float* __restrict__ bet,
    __half* __restrict__ hhi, __half* __restrict__ hlo)
{
    __shared__ float rs[8], rs2[8];
    const size_t row = blockIdx.x;
    float* hp = h + row * Dk;
    const float* op = o + row * Dk;
    const int tid = threadIdx.x;

    float4 hv = ((const float4*)hp)[tid];
    float4 ov = ((const float4*)op)[tid];
    float r0 = hv.x + ov.x, r1 = hv.y + ov.y, r2 = hv.z + ov.z, r3 = hv.w + ov.w;

    float s  = r0 + r1 + r2 + r3;
    float s2 = r0 * r0 + r1 * r1 + r2 * r2 + r3 * r3;
#pragma unroll
    for (int of = 16; of; of >>= 1) {
        s  += __shfl_xor_sync(~0u, s,  of);
        s2 += __shfl_xor_sync(~0u, s2, of);
    }
    if ((tid & 31) == 0) { rs[tid >> 5] = s; rs2[tid >> 5] = s2; }
    __syncthreads();
    float S = 0.f, S2 = 0.f;
#pragma unroll
    for (int i = 0; i < 8; i++) { S += rs[i]; S2 += rs2[i]; }

    const float mu  = S * (1.f / (float)Dk);
    const float var = S2 * (1.f / (float)Dk) - mu * mu;
    const float inv = rsqrtf(var + EPSk);

    float4 gg = ((const float4*)gam)[tid];
    float4 bb = ((const float4*)bet)[tid];
    float4 out;
    out.x = (r0 - mu) * inv * gg.x + bb.x;
    out.y = (r1 - mu) * inv * gg.y + bb.y;
    out.z = (r2 - mu) * inv * gg.z + bb.z;
    out.w = (r3 - mu) * inv * gg.w + bb.w;
    ((float4*)hp)[tid] = out;

    uint32_t h0, l0w, h1, l1w;
    cvt_hilo2h(out.x, out.y, h0, l0w);
    cvt_hilo2h(out.z, out.w, h1, l1w);
    *(uint2*)(hhi + row * Dk + tid * 4) = make_uint2(h0, h1);
    *(uint2*)(hlo + row * Dk + tid * 4) = make_uint2(l0w, l1w);
}

// ---------------------------------------------------------------------------
// head
// ---------------------------------------------------------------------------
__global__ void head_kernel(const float* __restrict__ h,
                            const float* __restrict__ hw,
                            const float* __restrict__ hb,
                            float* __restrict__ outp)
{
    const int idx = blockIdx.x;
    const int b = idx / Ck, c = idx % Ck;
    const float* hp = h + ((size_t)b * Tk + (Tk - 1)) * Dk;
    const float* wp = hw + (size_t)c * Dk;
    const int lane = threadIdx.x;
    float s = 0.f;
    for (int i = lane; i < Dk; i += 32) s += hp[i] * wp[i];
#pragma unroll
    for (int o = 16; o; o >>= 1) s += __shfl_xor_sync(~0u, s, o);
    if (lane == 0) outp[idx] = s + hb[c];
}

// ---------------------------------------------------------------------------
// Host orchestration
// ---------------------------------------------------------------------------
extern "C" void kernel_launch(void* const* d_in, const int* in_sizes, int n_in,
                              void* d_out, int out_size)
{
    (void)in_sizes; (void)n_in; (void)out_size;
    const float* x       = (const float*)d_in[0];
    const float* input_w = (const float*)d_in[1];
    const float* input_b = (const float*)d_in[2];
    const float* Wqkv    = (const float*)d_in[3];
    const float* bqkv    = (const float*)d_in[4];
    const float* Wo      = (const float*)d_in[5];
    const float* bo      = (const float*)d_in[6];
    const float* ln1_g   = (const float*)d_in[7];
    const float* ln1_b   = (const float*)d_in[8];
    const float* ln2_g   = (const float*)d_in[9];
    const float* ln2_b   = (const float*)d_in[10];
    const float* W1      = (const float*)d_in[11];
    const float* b1      = (const float*)d_in[12];
    const float* W2      = (const float*)d_in[13];
    const float* b2      = (const float*)d_in[14];
    const float* head_w  = (const float*)d_in[15];
    const float* head_b  = (const float*)d_in[16];
    float* outp = (float*)d_out;

    float *h, *tmp, *qkv;
    __half *xhi, *xlo, *hhi, *hlo, *ohi, *olo, *fhi, *flo;
    __half *winh, *wqh, *woh, *w1h, *w2h;
    cudaGetSymbolAddress((void**)&h,    g_h);
    cudaGetSymbolAddress((void**)&tmp,  g_tmp);
    cudaGetSymbolAddress((void**)&qkv,  g_qkv);
    cudaGetSymbolAddress((void**)&xhi,  g_x_hi);  cudaGetSymbolAddress((void**)&xlo,  g_x_lo);
    cudaGetSymbolAddress((void**)&hhi,  g_h_hi);  cudaGetSymbolAddress((void**)&hlo,  g_h_lo);
    cudaGetSymbolAddress((void**)&ohi,  g_o_hi);  cudaGetSymbolAddress((void**)&olo,  g_o_lo);
    cudaGetSymbolAddress((void**)&fhi,  g_ff_hi); cudaGetSymbolAddress((void**)&flo,  g_ff_lo);
    cudaGetSymbolAddress((void**)&winh, g_win_h);
    cudaGetSymbolAddress((void**)&wqh,  g_wqkv_h);
    cudaGetSymbolAddress((void**)&woh,  g_wo_h);
    cudaGetSymbolAddress((void**)&w1h,  g_w1_h);
    cudaGetSymbolAddress((void**)&w2h,  g_w2_h);

    cudaFuncSetAttribute(mma_gemm_f16_nt,
                         cudaFuncAttributeMaxDynamicSharedMemorySize, GEMM_SMEM);
    cudaFuncSetAttribute(flash_attn_kernel,
                         cudaFuncAttributeMaxDynamicSharedMemorySize, FLASH_SMEM);

    const int M = Bk * Tk;  // 4096
    dim3 blk(256);

    // ---- conversions: x -> fp16 hi/lo, weights -> fp16
    cvt_hl16_kernel<<<(Bk * Tk * INk) / 1024, 256>>>(x, xhi, xlo, Bk * Tk * INk);
    cvt_h16_kernel<<<(Dk * INk) / 1024, 256>>>(input_w, winh, Dk * INk);
    cvt_h16_kernel<<<(Lk * D3k * Dk) / 1024, 256>>>(Wqkv, wqh, Lk * D3k * Dk);
    cvt_h16_kernel<<<(Lk * Dk * Dk) / 1024, 256>>>(Wo, woh, Lk * Dk * Dk);
    cvt_h16_kernel<<<(Lk * FFk * Dk) / 1024, 256>>>(W1, w1h, Lk * FFk * Dk);
    cvt_h16_kernel<<<(Lk * Dk * FFk) / 1024, 256>>>(W2, w2h, Lk * Dk * FFk);

    // ---- input projection: h (fp32) + h hi/lo
    mma_gemm_f16_nt<<<dim3(Dk / 128, M / 128), blk, GEMM_SMEM>>>(
        xhi, xlo, INk, winh, INk, input_b, h, hhi, hlo, Dk, INk, 2 | 4);

    for (int l = 0; l < Lk; l++) {
        // qkv (fp32 out, feeds flash)
        mma_gemm_f16_nt<<<dim3(D3k / 128, M / 128), blk, GEMM_SMEM>>>(
            hhi, hlo, Dk, wqh + (size_t)l * D3k * Dk, Dk,
            bqkv + (size_t)l * D3k, qkv, nullptr, nullptr, D3k, Dk, 2);
        // attention -> o hi/lo
        flash_attn_kernel<<<dim3(Tk / 128, Bk * Hk), blk, FLASH_SMEM>>>(qkv, ohi, olo);
        // Wo proj (fp32 out)
        mma_gemm_f16_nt<<<dim3(Dk / 128, M / 128), blk, GEMM_SMEM>>>(
            ohi, olo, Dk, woh + (size_t)l * Dk * Dk, Dk,
            bo + (size_t)l * Dk, tmp, nullptr, nullptr, Dk, Dk, 2);
        // LN1 -> h fp32 + h hi/lo
        ln_residual_kernel<<<M, 256>>>(h, tmp, ln1_g + (size_t)l * Dk, ln1_b + (size_t)l * Dk,
                                       hhi, hlo);
        // FF1 (relu, hi/lo out only)
        mma_gemm_f16_nt<<<dim3(FFk / 128, M / 128), blk, GEMM_SMEM>>>(
            hhi, hlo, Dk, w1h + (size_t)l * FFk * Dk, Dk,
            b1 + (size_t)l * FFk, nullptr, fhi, flo, FFk, Dk, 1 | 4);
        // FF2 (fp32 out)
        mma_gemm_f16_nt<<<dim3(Dk / 128, M / 128), blk, GEMM_SMEM>>>(
            fhi, flo, FFk, w2h + (size_t)l * Dk * FFk, FFk,
            b2 + (size_t)l * Dk, tmp, nullptr, nullptr, Dk, FFk, 2);
        // LN2 -> h fp32 + h hi/lo
        ln_residual_kernel<<<M, 256>>>(h, tmp, ln2_g + (size_t)l * Dk, ln2_b + (size_t)l * Dk,
                                       hhi, hlo);
    }

    head_kernel<<<Bk * Ck, 32>>>(h, head_w, head_b, outp);
}

// round 11
// speedup vs baseline: 3.3122x; 1.0366x over previous
#include <cuda_runtime.h>
#include <cuda_fp16.h>
#include <math.h>
#include <stdint.h>

// ---------------------------------------------------------------------------
// Problem constants
// ---------------------------------------------------------------------------
namespace {
constexpr int Bk = 4;       // batch
constexpr int Tk = 1024;    // seq len
constexpr int INk = 256;    // input dim
constexpr int Dk = 1024;    // model dim
constexpr int Hk = 16;      // heads
constexpr int HDk = 64;     // head dim
constexpr int FFk = 4096;   // ff dim
constexpr int Ck = 10;      // classes
constexpr int Lk = 6;       // layers
constexpr int D3k = 3 * Dk;
constexpr float EPSk = 1e-5f;
}

// ---------------------------------------------------------------------------
// Scratch buffers (static device globals — no allocations allowed)
// ---------------------------------------------------------------------------
__device__ float g_h[Bk * Tk * Dk];
__device__ float g_tmp[Bk * Tk * Dk];

// fp16 hi/lo activation buffers
__device__ __half g_x_hi[Bk * Tk * INk],   g_x_lo[Bk * Tk * INk];
__device__ __half g_h_hi[Bk * Tk * Dk],    g_h_lo[Bk * Tk * Dk];
__device__ __half g_o_hi[Bk * Tk * Dk],    g_o_lo[Bk * Tk * Dk];
__device__ __half g_ff_hi[Bk * Tk * FFk],  g_ff_lo[Bk * Tk * FFk];
__device__ __half g_qkv_hi[Bk * Tk * D3k], g_qkv_lo[Bk * Tk * D3k];

// fp16 weight buffers (single rounding)
__device__ __half g_win_h[Dk * INk];
__device__ __half g_wqkv_h[Lk * D3k * Dk];
__device__ __half g_wo_h[Lk * Dk * Dk];
__device__ __half g_w1_h[Lk * FFk * Dk];
__device__ __half g_w2_h[Lk * Dk * FFk];

// ---------------------------------------------------------------------------
// PTX helpers (sm_80-era features only — compile on base sm_100)
// ---------------------------------------------------------------------------
__device__ __forceinline__ uint32_t smem_u32(const void* p) {
    uint32_t a;
    asm("{ .reg .u64 t; cvta.to.shared.u64 t, %1; cvt.u32.u64 %0, t; }"
        : "=r"(a) : "l"(p));
    return a;
}

__device__ __forceinline__ void ldmat_x4(uint32_t* r, uint32_t addr) {
    asm volatile("ldmatrix.sync.aligned.m8n8.x4.shared.b16 {%0,%1,%2,%3}, [%4];"
                 : "=r"(r[0]), "=r"(r[1]), "=r"(r[2]), "=r"(r[3]) : "r"(addr));
}

__device__ __forceinline__ void ldmat_x4_t(uint32_t* r, uint32_t addr) {
    asm volatile("ldmatrix.sync.aligned.m8n8.x4.trans.shared.b16 {%0,%1,%2,%3}, [%4];"
                 : "=r"(r[0]), "=r"(r[1]), "=r"(r[2]), "=r"(r[3]) : "r"(addr));
}

// fp16 mma
__device__ __forceinline__ void mma16816h(float* c, const uint32_t* a,
                                          uint32_t b0, uint32_t b1) {
    asm volatile(
        "mma.sync.aligned.m16n8k16.row.col.f32.f16.f16.f32 "
        "{%0,%1,%2,%3}, {%4,%5,%6,%7}, {%8,%9}, {%0,%1,%2,%3};"
        : "+f"(c[0]), "+f"(c[1]), "+f"(c[2]), "+f"(c[3])
        : "r"(a[0]), "r"(a[1]), "r"(a[2]), "r"(a[3]), "r"(b0), "r"(b1));
}

__device__ __forceinline__ void sts128(uint32_t addr, uint4 v) {
    asm volatile("st.shared.v4.b32 [%0], {%1,%2,%3,%4};"
                 :: "r"(addr), "r"(v.x), "r"(v.y), "r"(v.z), "r"(v.w) : "memory");
}

__device__ __forceinline__ void cp_async16(uint32_t saddr, const void* gptr) {
    asm volatile("cp.async.cg.shared.global [%0], [%1], 16;"
                 :: "r"(saddr), "l"(gptr) : "memory");
}
#define CP_COMMIT() asm volatile("cp.async.commit_group;" ::: "memory")
#define CP_WAIT1()  asm volatile("cp.async.wait_group 1;" ::: "memory")
#define CP_WAIT0()  asm volatile("cp.async.wait_group 0;" ::: "memory")

// ---- fp16 hi/lo split
__device__ __forceinline__ void cvt_hilo2h(float a, float b, uint32_t& hi, uint32_t& lo) {
    __half2 h = __floats2half2_rn(a, b);
    float2 hf = __half22float2(h);
    __half2 l = __floats2half2_rn(a - hf.x, b - hf.y);
    hi = *reinterpret_cast<uint32_t*>(&h);
    lo = *reinterpret_cast<uint32_t*>(&l);
}

// ---------------------------------------------------------------------------
// Conversion kernels
// ---------------------------------------------------------------------------
__global__ __launch_bounds__(256) void cvt_hl16_kernel(
    const float* __restrict__ src, __half* __restrict__ hi,
    __half* __restrict__ lo, int n)
{
    const int i = (blockIdx.x * 256 + threadIdx.x) * 4;
    if (i >= n) return;
    float4 v = *(const float4*)(src + i);
    uint32_t h0, l0, h1, l1;
    cvt_hilo2h(v.x, v.y, h0, l0);
    cvt_hilo2h(v.z, v.w, h1, l1);
    *(uint2*)(hi + i) = make_uint2(h0, h1);
    *(uint2*)(lo + i) = make_uint2(l0, l1);
}

__global__ __launch_bounds__(256) void cvt_h16_kernel(
    const float* __restrict__ src, __half* __restrict__ dst, int n)
{
    const int i = (blockIdx.x * 256 + threadIdx.x) * 4;
    if (i >= n) return;
    float4 v = *(const float4*)(src + i);
    __half2 h0 = __floats2half2_rn(v.x, v.y);
    __half2 h1 = __floats2half2_rn(v.z, v.w);
    *(uint2*)(dst + i) = make_uint2(*reinterpret_cast<uint32_t*>(&h0),
                                    *reinterpret_cast<uint32_t*>(&h1));
}

// ---------------------------------------------------------------------------
// fp16 2-term NT GEMM: C = (Ahi+Alo) * W^T + bias.
// 128x128 tile, BK=32, 3-stage cp.async, forced 2 CTAs/SM (<=128 regs).
// flags: 1=relu, 2=write fp32 C, 4=write fp16 hi/lo C
// ---------------------------------------------------------------------------
namespace {
constexpr int SST = 40;                        // smem row stride (fp16)
constexpr int ARR_B = 128 * SST * 2;           // 10240 bytes per tile array
constexpr int STAGE_B = 3 * ARR_B;             // Ahi|Alo|Bh = 30720 bytes
}
static constexpr int GEMM_SMEM = 3 * STAGE_B;  // 92160

__global__ __launch_bounds__(256, 2) void mma_gemm_f16_nt(
    const __half* __restrict__ Ahi, const __half* __restrict__ Alo, int lda,
    const __half* __restrict__ Bh, int ldb,
    const float* __restrict__ bias,
    float* __restrict__ Cf, __half* __restrict__ Chi, __half* __restrict__ Clo,
    int ldc, int K, int flags)
{
    extern __shared__ __align__(16) char gsm[];
    const uint32_t base = smem_u32(gsm);

    const int tid  = threadIdx.x;
    const int lane = tid & 31;
    const int wid  = tid >> 5;
    const int wm   = wid & 3;
    const int wn   = wid >> 2;
    const int row0 = blockIdx.y * 128;
    const int col0 = blockIdx.x * 128;

    const int grow = tid >> 1;
    const int gc16 = (tid & 1) * 16;
    const __half* Ah_p = Ahi + (size_t)(row0 + grow) * lda + gc16;
    const __half* Al_p = Alo + (size_t)(row0 + grow) * lda + gc16;
    const __half* Bh_p = Bh  + (size_t)(col0 + grow) * ldb + gc16;
    const uint32_t soff = grow * (SST * 2) + gc16 * 2;

    const uint32_t aRowOff = (uint32_t)((wm * 32 + (lane & 15)) * SST * 2 + (lane >> 4) * 16);
    const uint32_t bRowOff = (uint32_t)(((wn * 64 + ((lane >> 4) << 3) + (lane & 7)) * SST) * 2
                                        + ((lane >> 3) & 1) * 16);

    float acc[2][8][4];
#pragma unroll
    for (int i = 0; i < 2; i++)
#pragma unroll
        for (int j = 0; j < 8; j++)
#pragma unroll
            for (int q = 0; q < 4; q++) acc[i][j][q] = 0.f;

    const int nc = K >> 5;

    auto issue = [&](int c, int s) {
        const uint32_t sb = base + s * STAGE_B;
        const __half* p = Ah_p + c * 32;
        cp_async16(sb + soff, p);                 cp_async16(sb + soff + 16, p + 8);
        p = Al_p + c * 32;
        cp_async16(sb + ARR_B + soff, p);         cp_async16(sb + ARR_B + soff + 16, p + 8);
        p = Bh_p + c * 32;
        cp_async16(sb + 2 * ARR_B + soff, p);     cp_async16(sb + 2 * ARR_B + soff + 16, p + 8);
        CP_COMMIT();
    };

    issue(0, 0);
    if (nc > 1) issue(1, 1);

    for (int c = 0; c < nc; c++) {
        if (c + 1 < nc) { CP_WAIT1(); }
        else            { CP_WAIT0(); }
        __syncthreads();
        if (c + 2 < nc) issue(c + 2, (c + 2) % 3);

        const uint32_t sb = base + (c % 3) * STAGE_B;
        const uint32_t aHi = sb, aLo = sb + ARR_B, bHi = sb + 2 * ARR_B;

#pragma unroll
        for (int ks = 0; ks < 2; ks++) {
            const uint32_t kb = ks * 32;
            uint32_t Ah4[2][4], Al4[2][4];
#pragma unroll
            for (int mt = 0; mt < 2; mt++) {
                ldmat_x4(Ah4[mt], aHi + aRowOff + mt * (16 * SST * 2) + kb);
                ldmat_x4(Al4[mt], aLo + aRowOff + mt * (16 * SST * 2) + kb);
            }
#pragma unroll
            for (int pr = 0; pr < 4; pr++) {
                uint32_t B4[4];
                ldmat_x4(B4, bHi + bRowOff + pr * (16 * SST * 2) + kb);
#pragma unroll
                for (int sbb = 0; sbb < 2; sbb++) {
                    const int nt = pr * 2 + sbb;
#pragma unroll
                    for (int mt = 0; mt < 2; mt++) {
                        mma16816h(acc[mt][nt], Ah4[mt], B4[sbb * 2], B4[sbb * 2 + 1]);
                        mma16816h(acc[mt][nt], Al4[mt], B4[sbb * 2], B4[sbb * 2 + 1]);
                    }
                }
            }
        }
    }
    __syncthreads();

    // ---- epilogue
    const int erow = lane >> 2;
    const int ecol = (lane & 3) * 2;
    const int relu = flags & 1;
#pragma unroll
    for (int mt = 0; mt < 2; mt++) {
        const int r = row0 + wm * 32 + mt * 16 + erow;
#pragma unroll
        for (int nt = 0; nt < 8; nt++) {
            const int cc = col0 + wn * 64 + nt * 8 + ecol;
            float2 bv = *(const float2*)(bias + cc);
            float2 v0, v1;
            v0.x = acc[mt][nt][0] + bv.x;  v0.y = acc[mt][nt][1] + bv.y;
            v1.x = acc[mt][nt][2] + bv.x;  v1.y = acc[mt][nt][3] + bv.y;
            if (relu) {
                v0.x = fmaxf(v0.x, 0.f); v0.y = fmaxf(v0.y, 0.f);
                v1.x = fmaxf(v1.x, 0.f); v1.y = fmaxf(v1.y, 0.f);
            }
            if (flags & 2) {
                *(float2*)(Cf + (size_t)r * ldc + cc)       = v0;
                *(float2*)(Cf + (size_t)(r + 8) * ldc + cc) = v1;
            }
            if (flags & 4) {
                uint32_t hv, lv;
                cvt_hilo2h(v0.x, v0.y, hv, lv);
                *(uint32_t*)(Chi + (size_t)r * ldc + cc) = hv;
                *(uint32_t*)(Clo + (size_t)r * ldc + cc) = lv;
                cvt_hilo2h(v1.x, v1.y, hv, lv);
                *(uint32_t*)(Chi + (size_t)(r + 8) * ldc + cc) = hv;
                *(uint32_t*)(Clo + (size_t)(r + 8) * ldc + cc) = lv;
            }
        }
    }
}

// ---------------------------------------------------------------------------
// Fused flash attention on pre-split fp16 hi/lo qkv.
// 3-term fp16 MMAs; K/V loaded via cp.async, 3-stage ring; no in-kernel cvt
// of inputs. Q staged through stage-2 buffers before the pipeline starts.
// ---------------------------------------------------------------------------
namespace {
constexpr int KST   = 72;                 // smem row stride (fp16)
constexpr int ARR_F = 128 * KST * 2;      // 18432 bytes per array
constexpr int STAGE_F = 4 * ARR_F;        // Khi|Klo|Vhi|Vlo = 73728
}
static constexpr int FLASH_SMEM = 3 * STAGE_F;   // 221184

__global__ __launch_bounds__(256) void flash_attn_kernel(
    const __half* __restrict__ qkvhi, const __half* __restrict__ qkvlo,
    __half* __restrict__ ohi, __half* __restrict__ olo)
{
    extern __shared__ __align__(16) char fsm[];
    const uint32_t fbase = smem_u32(fsm);

    const int tid  = threadIdx.x;
    const int lane = tid & 31;
    const int w    = tid >> 5;
    const int bh = blockIdx.y;
    const int b = bh >> 4, h = bh & 15;
    const int qrow0 = blockIdx.x * 128;

    const size_t hd_off = (size_t)b * Tk * D3k + h * HDk;

    float slope = 0.f;
#pragma unroll
    for (int i = 1; i <= Hk; i++) slope += exp2f(-0.5f * (float)i);
    slope *= (1.f / (float)Hk);
    const float scale = 0.125f;

    const int grow = tid >> 1;
    const int gcol = (tid & 1) * 32;          // fp16 elements
    const uint32_t gso = grow * (KST * 2) + gcol * 2;

    // ---- stage Q (hi/lo fp16, straight copy) into stage-2 K slots
    {
        const uint32_t q_hi = fbase + 2 * STAGE_F;
        const uint32_t q_lo = q_hi + ARR_F;
        const __half* qh = qkvhi + hd_off + (size_t)(qrow0 + grow) * D3k + gcol;
        const __half* ql = qkvlo + hd_off + (size_t)(qrow0 + grow) * D3k + gcol;
#pragma unroll
        for (int j = 0; j < 4; j++) {
            sts128(q_hi + gso + j * 16, *(const uint4*)(qh + j * 8));
            sts128(q_lo + gso + j * 16, *(const uint4*)(ql + j * 8));
        }
    }
    __syncthreads();

    uint32_t Qh[4][4], Ql[4][4];
    {
        const uint32_t q_hi = fbase + 2 * STAGE_F;
        const uint32_t q_lo = q_hi + ARR_F;
        const uint32_t qOff = (w * 16 + (lane & 15)) * (KST * 2) + (lane >> 4) * 16;
#pragma unroll
        for (int kc = 0; kc < 4; kc++) {
            ldmat_x4(Qh[kc], q_hi + qOff + kc * 32);
            ldmat_x4(Ql[kc], q_lo + qOff + kc * 32);
        }
    }
    __syncthreads();   // Q reads done before stage-2 gets overwritten by issue

    // K/V cp.async sources (per-thread row)
    const __half* Khi_p = qkvhi + hd_off + Dk     + (size_t)grow * D3k + gcol;
    const __half* Klo_p = qkvlo + hd_off + Dk     + (size_t)grow * D3k + gcol;
    const __half* Vhi_p = qkvhi + hd_off + 2 * Dk + (size_t)grow * D3k + gcol;
    const __half* Vlo_p = qkvlo + hd_off + 2 * Dk + (size_t)grow * D3k + gcol;

    auto issueKV = [&](int kb, int s) {
        const uint32_t sb = fbase + s * STAGE_F;
        const size_t off = (size_t)(kb * 128) * D3k;
#pragma unroll
        for (int j = 0; j < 4; j++) {
            cp_async16(sb + gso + j * 16,               Khi_p + off + j * 8);
            cp_async16(sb + ARR_F + gso + j * 16,       Klo_p + off + j * 8);
            cp_async16(sb + 2 * ARR_F + gso + j * 16,   Vhi_p + off + j * 8);
            cp_async16(sb + 3 * ARR_F + gso + j * 16,   Vlo_p + off + j * 8);
        }
        CP_COMMIT();
    };

    const uint32_t bOff = (((lane >> 4) << 3) + (lane & 7)) * (KST * 2) + ((lane >> 3) & 1) * 16;
    const uint32_t vOff = ((lane & 7) + ((lane >> 3) & 1) * 8) * (KST * 2) + (lane >> 4) * 16;

    float Of[8][4];
#pragma unroll
    for (int i = 0; i < 8; i++)
#pragma unroll
        for (int q = 0; q < 4; q++) Of[i][q] = 0.f;
    float m0 = -1e30f, m1 = -1e30f, l0 = 0.f, l1 = 0.f;

    const float r0f = (float)(qrow0 + w * 16 + (lane >> 2));
    const float r1f = r0f + 8.f;

    constexpr int NKB = Tk / 128;   // 8
    issueKV(0, 0);
    issueKV(1, 1);

    for (int kb = 0; kb < NKB; kb++) {
        if (kb + 1 < NKB) { CP_WAIT1(); }
        else              { CP_WAIT0(); }
        __syncthreads();
        if (kb + 2 < NKB) issueKV(kb + 2, (kb + 2) % 3);

        const uint32_t sb  = fbase + (kb % 3) * STAGE_F;
        const uint32_t kHi = sb, kLo = sb + ARR_F, vHi = sb + 2 * ARR_F, vLo = sb + 3 * ARR_F;

        // ---- S = Q K^T  (3-term fp16)
        float Sf[16][4];
#pragma unroll
        for (int ntp = 0; ntp < 8; ntp++) {
#pragma unroll
            for (int q = 0; q < 4; q++) { Sf[2 * ntp][q] = 0.f; Sf[2 * ntp + 1][q] = 0.f; }
#pragma unroll
            for (int kc = 0; kc < 4; kc++) {
                uint32_t Bh4[4], Bl4[4];
                ldmat_x4(Bh4, kHi + bOff + ntp * (16 * KST * 2) + kc * 32);
                ldmat_x4(Bl4, kLo + bOff + ntp * (16 * KST * 2) + kc * 32);
                mma16816h(Sf[2 * ntp],     Qh[kc], Bh4[0], Bh4[1]);
                mma16816h(Sf[2 * ntp],     Qh[kc], Bl4[0], Bl4[1]);
                mma16816h(Sf[2 * ntp],     Ql[kc], Bh4[0], Bh4[1]);
                mma16816h(Sf[2 * ntp + 1], Qh[kc], Bh4[2], Bh4[3]);
                mma16816h(Sf[2 * ntp + 1], Qh[kc], Bl4[2], Bl4[3]);
                mma16816h(Sf[2 * ntp + 1], Ql[kc], Bh4[2], Bh4[3]);
            }
        }

        // ---- scale + alibi + block max
        float bm0 = -1e30f, bm1 = -1e30f;
#pragma unroll
        for (int t = 0; t < 16; t++) {
            const float c0f = (float)(kb * 128 + t * 8 + (lane & 3) * 2);
            const float c1f = c0f + 1.f;
            Sf[t][0] = Sf[t][0] * scale - slope * fabsf(r0f - c0f);
            Sf[t][1] = Sf[t][1] * scale - slope * fabsf(r0f - c1f);
            Sf[t][2] = Sf[t][2] * scale - slope * fabsf(r1f - c0f);
            Sf[t][3] = Sf[t][3] * scale - slope * fabsf(r1f - c1f);
            bm0 = fmaxf(bm0, fmaxf(Sf[t][0], Sf[t][1]));
            bm1 = fmaxf(bm1, fmaxf(Sf[t][2], Sf[t][3]));
        }
        bm0 = fmaxf(bm0, __shfl_xor_sync(~0u, bm0, 1));
        bm0 = fmaxf(bm0, __shfl_xor_sync(~0u, bm0, 2));
        bm1 = fmaxf(bm1, __shfl_xor_sync(~0u, bm1, 1));
        bm1 = fmaxf(bm1, __shfl_xor_sync(~0u, bm1, 2));

        const float mn0 = fmaxf(m0, bm0), mn1 = fmaxf(m1, bm1);
        const float sc0 = __expf(m0 - mn0), sc1 = __expf(m1 - mn1);
        l0 *= sc0; l1 *= sc1;
#pragma unroll
        for (int nt = 0; nt < 8; nt++) {
            Of[nt][0] *= sc0; Of[nt][1] *= sc0;
            Of[nt][2] *= sc1; Of[nt][3] *= sc1;
        }
        m0 = mn0; m1 = mn1;

#pragma unroll
        for (int t = 0; t < 16; t++) {
            Sf[t][0] = __expf(Sf[t][0] - mn0);
            Sf[t][1] = __expf(Sf[t][1] - mn0);
            Sf[t][2] = __expf(Sf[t][2] - mn1);
            Sf[t][3] = __expf(Sf[t][3] - mn1);
            l0 += Sf[t][0] + Sf[t][1];
            l1 += Sf[t][2] + Sf[t][3];
        }

        // ---- P fragments (fp16 hi/lo)
        uint32_t Ph[8][4], Pl[8][4];
#pragma unroll
        for (int kc = 0; kc < 8; kc++) {
            cvt_hilo2h(Sf[2 * kc][0],     Sf[2 * kc][1],     Ph[kc][0], Pl[kc][0]);
            cvt_hilo2h(Sf[2 * kc][2],     Sf[2 * kc][3],     Ph[kc][1], Pl[kc][1]);
            cvt_hilo2h(Sf[2 * kc + 1][0], Sf[2 * kc + 1][1], Ph[kc][2], Pl[kc][2]);
            cvt_hilo2h(Sf[2 * kc + 1][2], Sf[2 * kc + 1][3], Ph[kc][3], Pl[kc][3]);
        }

        // ---- O += P V (3-term fp16)
#pragma unroll
        for (int ntp = 0; ntp < 4; ntp++) {
#pragma unroll
            for (int kc = 0; kc < 8; kc++) {
                uint32_t Vh4[4], Vl4[4];
                ldmat_x4_t(Vh4, vHi + vOff + kc * (16 * KST * 2) + ntp * 32);
                ldmat_x4_t(Vl4, vLo + vOff + kc * (16 * KST * 2) + ntp * 32);
                mma16816h(Of[2 * ntp],     Ph[kc], Vh4[0], Vh4[1]);
                mma16816h(Of[2 * ntp],     Ph[kc], Vl4[0], Vl4[1]);
                mma16816h(Of[2 * ntp],     Pl[kc], Vh4[0], Vh4[1]);
                mma16816h(Of[2 * ntp + 1], Ph[kc], Vh4[2], Vh4[3]);
                mma16816h(Of[2 * ntp + 1], Ph[kc], Vl4[2], Vl4[3]);
                mma16816h(Of[2 * ntp + 1], Pl[kc], Vh4[2], Vh4[3]);
            }
        }
        __syncthreads();   // all reads of this stage done before re-issue
    }

    l0 += __shfl_xor_sync(~0u, l0, 1);
    l0 += __shfl_xor_sync(~0u, l0, 2);
    l1 += __shfl_xor_sync(~0u, l1, 1);
    l1 += __shfl_xor_sync(~0u, l1, 2);
    const float inv0 = 1.f / l0, inv1 = 1.f / l1;

    const int row0 = qrow0 + w * 16 + (lane >> 2);
    __half* ohb = ohi + (size_t)b * Tk * Dk + h * HDk;
    __half* olb = olo + (size_t)b * Tk * Dk + h * HDk;
#pragma unroll
    for (int nt = 0; nt < 8; nt++) {
        const int cc = nt * 8 + (lane & 3) * 2;
        uint32_t hv, lv;
        cvt_hilo2h(Of[nt][0] * inv0, Of[nt][1] * inv0, hv, lv);
        *(uint32_t*)(ohb + (size_t)row0 * Dk + cc) = hv;
        *(uint32_t*)(olb + (size_t)row0 * Dk + cc) = lv;
        cvt_hilo2h(Of[nt][2] * inv1, Of[nt][3] * inv1, hv, lv);
        *(uint32_t*)(ohb + (size_t)(row0 + 8) * Dk + cc) = hv;
        *(uint32_t*)(olb + (size_t)(row0 + 8) * Dk + cc) = lv;
    }
}

// ---------------------------------------------------------------------------
// h = LN(h + o) * g + b; also writes h as fp16 hi/lo for the next GEMM.
// ---------------------------------------------------------------------------
__global__ __launch_bounds__(256) void ln_residual_kernel(
    float* __restrict__ h, const float* __restrict__ o,
    const float* __restrict__ gam, const float* __restrict__ bet,
    __half* __restrict__ hhi, __half* __restrict__ hlo)
{
    __shared__ float rs[8], rs2[8];
    const size_t row = blockIdx.x;
    float* hp = h + row * Dk;
    const float* op = o + row * Dk;
    const int tid = threadIdx.x;

    float4 hv = ((const float4*)hp)[tid];
    float4 ov = ((const float4*)op)[tid];
    float r0 = hv.x + ov.x, r1 = hv.y + ov.y, r2 = hv.z + ov.z, r3 = hv.w + ov.w;

    float s  = r0 + r1 + r2 + r3;
    float s2 = r0 * r0 + r1 * r1 + r2 * r2 + r3 * r3;
#pragma unroll
    for (int of = 16; of; of >>= 1) {
        s  += __shfl_xor_sync(~0u, s,  of);
        s2 += __shfl_xor_sync(~0u, s2, of);
    }
    if ((tid & 31) == 0) { rs[tid >> 5] = s; rs2[tid >> 5] = s2; }
    __syncthreads();
    float S = 0.f, S2 = 0.f;
#pragma unroll
    for (int i = 0; i < 8; i++) { S += rs[i]; S2 += rs2[i]; }

    const float mu  = S * (1.f / (float)Dk);
    const float var = S2 * (1.f / (float)Dk) - mu * mu;
    const float inv = rsqrtf(var + EPSk);

    float4 gg = ((const float4*)gam)[tid];
    float4 bb = ((const float4*)bet)[tid];
    float4 out;
    out.x = (r0 - mu) * inv * gg.x + bb.x;
    out.y = (r1 - mu) * inv * gg.y + bb.y;
    out.z = (r2 - mu) * inv * gg.z + bb.z;
    out.w = (r3 - mu) * inv * gg.w + bb.w;
    ((float4*)hp)[tid] = out;

    uint32_t h0, l0w, h1, l1w;
    cvt_hilo2h(out.x, out.y, h0, l0w);
    cvt_hilo2h(out.z, out.w, h1, l1w);
    *(uint2*)(hhi + row * Dk + tid * 4) = make_uint2(h0, h1);
    *(uint2*)(hlo + row * Dk + tid * 4) = make_uint2(l0w, l1w);
}

// ---------------------------------------------------------------------------
// head
// ---------------------------------------------------------------------------
__global__ void head_kernel(const float* __restrict__ h,
                            const float* __restrict__ hw,
                            const float* __restrict__ hb,
                            float* __restrict__ outp)
{
    const int idx = blockIdx.x;
    const int b = idx / Ck, c = idx % Ck;
    const float* hp = h + ((size_t)b * Tk + (Tk - 1)) * Dk;
    const float* wp = hw + (size_t)c * Dk;
    const int lane = threadIdx.x;
    float s = 0.f;
    for (int i = lane; i < Dk; i += 32) s += hp[i] * wp[i];
#pragma unroll
    for (int o = 16; o; o >>= 1) s += __shfl_xor_sync(~0u, s, o);
    if (lane == 0) outp[idx] = s + hb[c];
}

// ---------------------------------------------------------------------------
// Host orchestration
// ---------------------------------------------------------------------------
extern "C" void kernel_launch(void* const* d_in, const int* in_sizes, int n_in,
                              void* d_out, int out_size)
{
    (void)in_sizes; (void)n_in; (void)out_size;
    const float* x       = (const float*)d_in[0];
    const float* input_w = (const float*)d_in[1];
    const float* input_b = (const float*)d_in[2];
    const float* Wqkv    = (const float*)d_in[3];
    const float* bqkv    = (const float*)d_in[4];
    const float* Wo      = (const float*)d_in[5];
    const float* bo      = (const float*)d_in[6];
    const float* ln1_g   = (const float*)d_in[7];
    const float* ln1_b   = (const float*)d_in[8];
    const float* ln2_g   = (const float*)d_in[9];
    const float* ln2_b   = (const float*)d_in[10];
    const float* W1      = (const float*)d_in[11];
    const float* b1      = (const float*)d_in[12];
    const float* W2      = (const float*)d_in[13];
    const float* b2      = (const float*)d_in[14];
    const float* head_w  = (const float*)d_in[15];
    const float* head_b  = (const float*)d_in[16];
    float* outp = (float*)d_out;

    float *h, *tmp;
    __half *xhi, *xlo, *hhi, *hlo, *ohi, *olo, *fhi, *flo, *qhi, *qlo;
    __half *winh, *wqh, *woh, *w1h, *w2h;
    cudaGetSymbolAddress((void**)&h,    g_h);
    cudaGetSymbolAddress((void**)&tmp,  g_tmp);
    cudaGetSymbolAddress((void**)&xhi,  g_x_hi);  cudaGetSymbolAddress((void**)&xlo,  g_x_lo);
    cudaGetSymbolAddress((void**)&hhi,  g_h_hi);  cudaGetSymbolAddress((void**)&hlo,  g_h_lo);
    cudaGetSymbolAddress((void**)&ohi,  g_o_hi);  cudaGetSymbolAddress((void**)&olo,  g_o_lo);
    cudaGetSymbolAddress((void**)&fhi,  g_ff_hi); cudaGetSymbolAddress((void**)&flo,  g_ff_lo);
    cudaGetSymbolAddress((void**)&qhi,  g_qkv_hi); cudaGetSymbolAddress((void**)&qlo, g_qkv_lo);
    cudaGetSymbolAddress((void**)&winh, g_win_h);
    cudaGetSymbolAddress((void**)&wqh,  g_wqkv_h);
    cudaGetSymbolAddress((void**)&woh,  g_wo_h);
    cudaGetSymbolAddress((void**)&w1h,  g_w1_h);
    cudaGetSymbolAddress((void**)&w2h,  g_w2_h);

    cudaFuncSetAttribute(mma_gemm_f16_nt,
                         cudaFuncAttributeMaxDynamicSharedMemorySize, GEMM_SMEM);
    cudaFuncSetAttribute(flash_attn_kernel,
                         cudaFuncAttributeMaxDynamicSharedMemorySize, FLASH_SMEM);

    const int M = Bk * Tk;  // 4096
    dim3 blk(256);

    // ---- conversions: x -> fp16 hi/lo, weights -> fp16
    cvt_hl16_kernel<<<(Bk * Tk * INk) / 1024, 256>>>(x, xhi, xlo, Bk * Tk * INk);
    cvt_h16_kernel<<<(Dk * INk) / 1024, 256>>>(input_w, winh, Dk * INk);
    cvt_h16_kernel<<<(Lk * D3k * Dk) / 1024, 256>>>(Wqkv, wqh, Lk * D3k * Dk);
    cvt_h16_kernel<<<(Lk * Dk * Dk) / 1024, 256>>>(Wo, woh, Lk * Dk * Dk);
    cvt_h16_kernel<<<(Lk * FFk * Dk) / 1024, 256>>>(W1, w1h, Lk * FFk * Dk);
    cvt_h16_kernel<<<(Lk * Dk * FFk) / 1024, 256>>>(W2, w2h, Lk * Dk * FFk);

    // ---- input projection: h (fp32) + h hi/lo
    mma_gemm_f16_nt<<<dim3(Dk / 128, M / 128), blk, GEMM_SMEM>>>(
        xhi, xlo, INk, winh, INk, input_b, h, hhi, hlo, Dk, INk, 2 | 4);

    for (int l = 0; l < Lk; l++) {
        // qkv -> fp16 hi/lo (feeds flash directly)
        mma_gemm_f16_nt<<<dim3(D3k / 128, M / 128), blk, GEMM_SMEM>>>(
            hhi, hlo, Dk, wqh + (size_t)l * D3k * Dk, Dk,
            bqkv + (size_t)l * D3k, nullptr, qhi, qlo, D3k, Dk, 4);
        // attention -> o hi/lo
        flash_attn_kernel<<<dim3(Tk / 128, Bk * Hk), blk, FLASH_SMEM>>>(qhi, qlo, ohi, olo);
        // Wo proj (fp32 out)
        mma_gemm_f16_nt<<<dim3(Dk / 128, M / 128), blk, GEMM_SMEM>>>(
            ohi, olo, Dk, woh + (size_t)l * Dk * Dk, Dk,
            bo + (size_t)l * Dk, tmp, nullptr, nullptr, Dk, Dk, 2);
        // LN1 -> h fp32 + h hi/lo
        ln_residual_kernel<<<M, 256>>>(h, tmp, ln1_g + (size_t)l * Dk, ln1_b + (size_t)l * Dk,
                                       hhi, hlo);
        // FF1 (relu, hi/lo out only)
        mma_gemm_f16_nt<<<dim3(FFk / 128, M / 128), blk, GEMM_SMEM>>>(
            hhi, hlo, Dk, w1h + (size_t)l * FFk * Dk, Dk,
            b1 + (size_t)l * FFk, nullptr, fhi, flo, FFk, Dk, 1 | 4);
        // FF2 (fp32 out)
        mma_gemm_f16_nt<<<dim3(Dk / 128, M / 128), blk, GEMM_SMEM>>>(
            fhi, flo, FFk, w2h + (size_t)l * Dk * FFk, FFk,
            b2 + (size_t)l * Dk, tmp, nullptr, nullptr, Dk, FFk, 2);
        // LN2 -> h fp32 + h hi/lo
        ln_residual_kernel<<<M, 256>>>(h, tmp, ln2_g + (size_t)l * Dk, ln2_b + (size_t)l * Dk,
                                       hhi, hlo);
    }

    head_kernel<<<Bk * Ck, 32>>>(h, head_w, head_b, outp);
}

// round 12
// speedup vs baseline: 3.3206x; 1.0025x over previous
#include <cuda_runtime.h>
#include <cuda_fp16.h>
#include <math.h>
#include <stdint.h>

// ---------------------------------------------------------------------------
// Problem constants
// ---------------------------------------------------------------------------
namespace {
constexpr int Bk = 4;       // batch
constexpr int Tk = 1024;    // seq len
constexpr int INk = 256;    // input dim
constexpr int Dk = 1024;    // model dim
constexpr int Hk = 16;      // heads
constexpr int HDk = 64;     // head dim
constexpr int FFk = 4096;   // ff dim
constexpr int Ck = 10;      // classes
constexpr int Lk = 6;       // layers
constexpr int D3k = 3 * Dk;
constexpr float EPSk = 1e-5f;
}

// ---------------------------------------------------------------------------
// Scratch buffers (static device globals — no allocations allowed)
// ---------------------------------------------------------------------------
__device__ float g_h[Bk * Tk * Dk];
__device__ float g_tmp[Bk * Tk * Dk];

// fp16 hi/lo activation buffers
__device__ __half g_x_hi[Bk * Tk * INk],   g_x_lo[Bk * Tk * INk];
__device__ __half g_h_hi[Bk * Tk * Dk],    g_h_lo[Bk * Tk * Dk];
__device__ __half g_o_hi[Bk * Tk * Dk],    g_o_lo[Bk * Tk * Dk];
__device__ __half g_ff_hi[Bk * Tk * FFk],  g_ff_lo[Bk * Tk * FFk];
__device__ __half g_qkv_hi[Bk * Tk * D3k], g_qkv_lo[Bk * Tk * D3k];

// fp16 weight buffers (single rounding)
__device__ __half g_win_h[Dk * INk];
__device__ __half g_wqkv_h[Lk * D3k * Dk];
__device__ __half g_wo_h[Lk * Dk * Dk];
__device__ __half g_w1_h[Lk * FFk * Dk];
__device__ __half g_w2_h[Lk * Dk * FFk];

// ---------------------------------------------------------------------------
// PTX helpers (sm_80-era features only — compile on base sm_100)
// ---------------------------------------------------------------------------
__device__ __forceinline__ uint32_t smem_u32(const void* p) {
    uint32_t a;
    asm("{ .reg .u64 t; cvta.to.shared.u64 t, %1; cvt.u32.u64 %0, t; }"
        : "=r"(a) : "l"(p));
    return a;
}

__device__ __forceinline__ void ldmat_x4(uint32_t* r, uint32_t addr) {
    asm volatile("ldmatrix.sync.aligned.m8n8.x4.shared.b16 {%0,%1,%2,%3}, [%4];"
                 : "=r"(r[0]), "=r"(r[1]), "=r"(r[2]), "=r"(r[3]) : "r"(addr));
}

__device__ __forceinline__ void ldmat_x4_t(uint32_t* r, uint32_t addr) {
    asm volatile("ldmatrix.sync.aligned.m8n8.x4.trans.shared.b16 {%0,%1,%2,%3}, [%4];"
                 : "=r"(r[0]), "=r"(r[1]), "=r"(r[2]), "=r"(r[3]) : "r"(addr));
}

// fp16 mma
__device__ __forceinline__ void mma16816h(float* c, const uint32_t* a,
                                          uint32_t b0, uint32_t b1) {
    asm volatile(
        "mma.sync.aligned.m16n8k16.row.col.f32.f16.f16.f32 "
        "{%0,%1,%2,%3}, {%4,%5,%6,%7}, {%8,%9}, {%0,%1,%2,%3};"
        : "+f"(c[0]), "+f"(c[1]), "+f"(c[2]), "+f"(c[3])
        : "r"(a[0]), "r"(a[1]), "r"(a[2]), "r"(a[3]), "r"(b0), "r"(b1));
}

__device__ __forceinline__ void sts128(uint32_t addr, uint4 v) {
    asm volatile("st.shared.v4.b32 [%0], {%1,%2,%3,%4};"
                 :: "r"(addr), "r"(v.x), "r"(v.y), "r"(v.z), "r"(v.w) : "memory");
}

__device__ __forceinline__ void cp_async16(uint32_t saddr, const void* gptr) {
    asm volatile("cp.async.cg.shared.global [%0], [%1], 16;"
                 :: "r"(saddr), "l"(gptr) : "memory");
}
#define CP_COMMIT() asm volatile("cp.async.commit_group;" ::: "memory")
#define CP_WAIT1()  asm volatile("cp.async.wait_group 1;" ::: "memory")
#define CP_WAIT0()  asm volatile("cp.async.wait_group 0;" ::: "memory")

// ---- fp16 hi/lo split
__device__ __forceinline__ void cvt_hilo2h(float a, float b, uint32_t& hi, uint32_t& lo) {
    __half2 h = __floats2half2_rn(a, b);
    float2 hf = __half22float2(h);
    __half2 l = __floats2half2_rn(a - hf.x, b - hf.y);
    hi = *reinterpret_cast<uint32_t*>(&h);
    lo = *reinterpret_cast<uint32_t*>(&l);
}

// ---------------------------------------------------------------------------
// Conversion kernels
// ---------------------------------------------------------------------------
__global__ __launch_bounds__(256) void cvt_hl16_kernel(
    const float* __restrict__ src, __half* __restrict__ hi,
    __half* __restrict__ lo, int n)
{
    const int i = (blockIdx.x * 256 + threadIdx.x) * 4;
    if (i >= n) return;
    float4 v = *(const float4*)(src + i);
    uint32_t h0, l0, h1, l1;
    cvt_hilo2h(v.x, v.y, h0, l0);
    cvt_hilo2h(v.z, v.w, h1, l1);
    *(uint2*)(hi + i) = make_uint2(h0, h1);
    *(uint2*)(lo + i) = make_uint2(l0, l1);
}

__global__ __launch_bounds__(256) void cvt_h16_kernel(
    const float* __restrict__ src, __half* __restrict__ dst, int n)
{
    const int i = (blockIdx.x * 256 + threadIdx.x) * 4;
    if (i >= n) return;
    float4 v = *(const float4*)(src + i);
    __half2 h0 = __floats2half2_rn(v.x, v.y);
    __half2 h1 = __floats2half2_rn(v.z, v.w);
    *(uint2*)(dst + i) = make_uint2(*reinterpret_cast<uint32_t*>(&h0),
                                    *reinterpret_cast<uint32_t*>(&h1));
}

// ---------------------------------------------------------------------------
// fp16 2-term NT GEMM: C = (Ahi+Alo) * W^T + bias.
// 128x128 tile, BK=32, 3-stage cp.async, forced 2 CTAs/SM (<=128 regs).
// flags: 1=relu, 2=write fp32 C, 4=write fp16 hi/lo C
// ---------------------------------------------------------------------------
namespace {
constexpr int SST = 40;                        // smem row stride (fp16)
constexpr int ARR_B = 128 * SST * 2;           // 10240 bytes per tile array
constexpr int STAGE_B = 3 * ARR_B;             // Ahi|Alo|Bh = 30720 bytes
}
static constexpr int GEMM_SMEM = 3 * STAGE_B;  // 92160

__global__ __launch_bounds__(256, 2) void mma_gemm_f16_nt(
    const __half* __restrict__ Ahi, const __half* __restrict__ Alo, int lda,
    const __half* __restrict__ Bh, int ldb,
    const float* __restrict__ bias,
    float* __restrict__ Cf, __half* __restrict__ Chi, __half* __restrict__ Clo,
    int ldc, int K, int flags)
{
    extern __shared__ __align__(16) char gsm[];
    const uint32_t base = smem_u32(gsm);

    const int tid  = threadIdx.x;
    const int lane = tid & 31;
    const int wid  = tid >> 5;
    const int wm   = wid & 3;
    const int wn   = wid >> 2;
    const int row0 = blockIdx.y * 128;
    const int col0 = blockIdx.x * 128;

    const int grow = tid >> 1;
    const int gc16 = (tid & 1) * 16;
    const __half* Ah_p = Ahi + (size_t)(row0 + grow) * lda + gc16;
    const __half* Al_p = Alo + (size_t)(row0 + grow) * lda + gc16;
    const __half* Bh_p = Bh  + (size_t)(col0 + grow) * ldb + gc16;
    const uint32_t soff = grow * (SST * 2) + gc16 * 2;

    const uint32_t aRowOff = (uint32_t)((wm * 32 + (lane & 15)) * SST * 2 + (lane >> 4) * 16);
    const uint32_t bRowOff = (uint32_t)(((wn * 64 + ((lane >> 4) << 3) + (lane & 7)) * SST) * 2
                                        + ((lane >> 3) & 1) * 16);

    float acc[2][8][4];
#pragma unroll
    for (int i = 0; i < 2; i++)
#pragma unroll
        for (int j = 0; j < 8; j++)
#pragma unroll
            for (int q = 0; q < 4; q++) acc[i][j][q] = 0.f;

    const int nc = K >> 5;

    auto issue = [&](int c, int s) {
        const uint32_t sb = base + s * STAGE_B;
        const __half* p = Ah_p + c * 32;
        cp_async16(sb + soff, p);                 cp_async16(sb + soff + 16, p + 8);
        p = Al_p + c * 32;
        cp_async16(sb + ARR_B + soff, p);         cp_async16(sb + ARR_B + soff + 16, p + 8);
        p = Bh_p + c * 32;
        cp_async16(sb + 2 * ARR_B + soff, p);     cp_async16(sb + 2 * ARR_B + soff + 16, p + 8);
        CP_COMMIT();
    };

    issue(0, 0);
    if (nc > 1) issue(1, 1);

    for (int c = 0; c < nc; c++) {
        if (c + 1 < nc) { CP_WAIT1(); }
        else            { CP_WAIT0(); }
        __syncthreads();
        if (c + 2 < nc) issue(c + 2, (c + 2) % 3);

        const uint32_t sb = base + (c % 3) * STAGE_B;
        const uint32_t aHi = sb, aLo = sb + ARR_B, bHi = sb + 2 * ARR_B;

#pragma unroll
        for (int ks = 0; ks < 2; ks++) {
            const uint32_t kb = ks * 32;
            uint32_t Ah4[2][4], Al4[2][4];
#pragma unroll
            for (int mt = 0; mt < 2; mt++) {
                ldmat_x4(Ah4[mt], aHi + aRowOff + mt * (16 * SST * 2) + kb);
                ldmat_x4(Al4[mt], aLo + aRowOff + mt * (16 * SST * 2) + kb);
            }
#pragma unroll
            for (int pr = 0; pr < 4; pr++) {
                uint32_t B4[4];
                ldmat_x4(B4, bHi + bRowOff + pr * (16 * SST * 2) + kb);
#pragma unroll
                for (int sbb = 0; sbb < 2; sbb++) {
                    const int nt = pr * 2 + sbb;
#pragma unroll
                    for (int mt = 0; mt < 2; mt++) {
                        mma16816h(acc[mt][nt], Ah4[mt], B4[sbb * 2], B4[sbb * 2 + 1]);
                        mma16816h(acc[mt][nt], Al4[mt], B4[sbb * 2], B4[sbb * 2 + 1]);
                    }
                }
            }
        }
    }
    __syncthreads();

    // ---- epilogue
    const int erow = lane >> 2;
    const int ecol = (lane & 3) * 2;
    const int relu = flags & 1;
#pragma unroll
    for (int mt = 0; mt < 2; mt++) {
        const int r = row0 + wm * 32 + mt * 16 + erow;
#pragma unroll
        for (int nt = 0; nt < 8; nt++) {
            const int cc = col0 + wn * 64 + nt * 8 + ecol;
            float2 bv = *(const float2*)(bias + cc);
            float2 v0, v1;
            v0.x = acc[mt][nt][0] + bv.x;  v0.y = acc[mt][nt][1] + bv.y;
            v1.x = acc[mt][nt][2] + bv.x;  v1.y = acc[mt][nt][3] + bv.y;
            if (relu) {
                v0.x = fmaxf(v0.x, 0.f); v0.y = fmaxf(v0.y, 0.f);
                v1.x = fmaxf(v1.x, 0.f); v1.y = fmaxf(v1.y, 0.f);
            }
            if (flags & 2) {
                *(float2*)(Cf + (size_t)r * ldc + cc)       = v0;
                *(float2*)(Cf + (size_t)(r + 8) * ldc + cc) = v1;
            }
            if (flags & 4) {
                uint32_t hv, lv;
                cvt_hilo2h(v0.x, v0.y, hv, lv);
                *(uint32_t*)(Chi + (size_t)r * ldc + cc) = hv;
                *(uint32_t*)(Clo + (size_t)r * ldc + cc) = lv;
                cvt_hilo2h(v1.x, v1.y, hv, lv);
                *(uint32_t*)(Chi + (size_t)(r + 8) * ldc + cc) = hv;
                *(uint32_t*)(Clo + (size_t)(r + 8) * ldc + cc) = lv;
            }
        }
    }
}

// ---------------------------------------------------------------------------
// Fused flash attention on pre-split fp16 hi/lo qkv.
// 3-term fp16 MMAs; K/V loaded via cp.async, 3-stage ring; no in-kernel cvt
// of inputs. Q staged through stage-2 buffers before the pipeline starts.
// ---------------------------------------------------------------------------
namespace {
constexpr int KST   = 72;                 // smem row stride (fp16)
constexpr int ARR_F = 128 * KST * 2;      // 18432 bytes per array
constexpr int STAGE_F = 4 * ARR_F;        // Khi|Klo|Vhi|Vlo = 73728
}
static constexpr int FLASH_SMEM = 3 * STAGE_F;   // 221184

__global__ __launch_bounds__(256) void flash_attn_kernel(
    const __half* __restrict__ qkvhi, const __half* __restrict__ qkvlo,
    __half* __restrict__ ohi, __half* __restrict__ olo)
{
    extern __shared__ __align__(16) char fsm[];
    const uint32_t fbase = smem_u32(fsm);

    const int tid  = threadIdx.x;
    const int lane = tid & 31;
    const int w    = tid >> 5;
    const int bh = blockIdx.y;
    const int b = bh >> 4, h = bh & 15;
    const int qrow0 = blockIdx.x * 128;

    const size_t hd_off = (size_t)b * Tk * D3k + h * HDk;

    float slope = 0.f;
#pragma unroll
    for (int i = 1; i <= Hk; i++) slope += exp2f(-0.5f * (float)i);
    slope *= (1.f / (float)Hk);
    const float scale = 0.125f;

    const int grow = tid >> 1;
    const int gcol = (tid & 1) * 32;          // fp16 elements
    const uint32_t gso = grow * (KST * 2) + gcol * 2;

    // ---- stage Q (hi/lo fp16, straight copy) into stage-2 K slots
    {
        const uint32_t q_hi = fbase + 2 * STAGE_F;
        const uint32_t q_lo = q_hi + ARR_F;
        const __half* qh = qkvhi + hd_off + (size_t)(qrow0 + grow) * D3k + gcol;
        const __half* ql = qkvlo + hd_off + (size_t)(qrow0 + grow) * D3k + gcol;
#pragma unroll
        for (int j = 0; j < 4; j++) {
            sts128(q_hi + gso + j * 16, *(const uint4*)(qh + j * 8));
            sts128(q_lo + gso + j * 16, *(const uint4*)(ql + j * 8));
        }
    }
    __syncthreads();

    uint32_t Qh[4][4], Ql[4][4];
    {
        const uint32_t q_hi = fbase + 2 * STAGE_F;
        const uint32_t q_lo = q_hi + ARR_F;
        const uint32_t qOff = (w * 16 + (lane & 15)) * (KST * 2) + (lane >> 4) * 16;
#pragma unroll
        for (int kc = 0; kc < 4; kc++) {
            ldmat_x4(Qh[kc], q_hi + qOff + kc * 32);
            ldmat_x4(Ql[kc], q_lo + qOff + kc * 32);
        }
    }
    __syncthreads();   // Q reads done before stage-2 gets overwritten by issue

    // K/V cp.async sources (per-thread row)
    const __half* Khi_p = qkvhi + hd_off + Dk     + (size_t)grow * D3k + gcol;
    const __half* Klo_p = qkvlo + hd_off + Dk     + (size_t)grow * D3k + gcol;
    const __half* Vhi_p = qkvhi + hd_off + 2 * Dk + (size_t)grow * D3k + gcol;
    const __half* Vlo_p = qkvlo + hd_off + 2 * Dk + (size_t)grow * D3k + gcol;

    auto issueKV = [&](int kb, int s) {
        const uint32_t sb = fbase + s * STAGE_F;
        const size_t off = (size_t)(kb * 128) * D3k;
#pragma unroll
        for (int j = 0; j < 4; j++) {
            cp_async16(sb + gso + j * 16,               Khi_p + off + j * 8);
            cp_async16(sb + ARR_F + gso + j * 16,       Klo_p + off + j * 8);
            cp_async16(sb + 2 * ARR_F + gso + j * 16,   Vhi_p + off + j * 8);
            cp_async16(sb + 3 * ARR_F + gso + j * 16,   Vlo_p + off + j * 8);
        }
        CP_COMMIT();
    };

    const uint32_t bOff = (((lane >> 4) << 3) + (lane & 7)) * (KST * 2) + ((lane >> 3) & 1) * 16;
    const uint32_t vOff = ((lane & 7) + ((lane >> 3) & 1) * 8) * (KST * 2) + (lane >> 4) * 16;

    float Of[8][4];
#pragma unroll
    for (int i = 0; i < 8; i++)
#pragma unroll
        for (int q = 0; q < 4; q++) Of[i][q] = 0.f;
    float m0 = -1e30f, m1 = -1e30f, l0 = 0.f, l1 = 0.f;

    const float r0f = (float)(qrow0 + w * 16 + (lane >> 2));
    const float r1f = r0f + 8.f;

    constexpr int NKB = Tk / 128;   // 8
    issueKV(0, 0);
    issueKV(1, 1);

    for (int kb = 0; kb < NKB; kb++) {
        if (kb + 1 < NKB) { CP_WAIT1(); }
        else              { CP_WAIT0(); }
        __syncthreads();
        if (kb + 2 < NKB) issueKV(kb + 2, (kb + 2) % 3);

        const uint32_t sb  = fbase + (kb % 3) * STAGE_F;
        const uint32_t kHi = sb, kLo = sb + ARR_F, vHi = sb + 2 * ARR_F, vLo = sb + 3 * ARR_F;

        // ---- S = Q K^T  (3-term fp16)
        float Sf[16][4];
#pragma unroll
        for (int ntp = 0; ntp < 8; ntp++) {
#pragma unroll
            for (int q = 0; q < 4; q++) { Sf[2 * ntp][q] = 0.f; Sf[2 * ntp + 1][q] = 0.f; }
#pragma unroll
            for (int kc = 0; kc < 4; kc++) {
                uint32_t Bh4[4], Bl4[4];
                ldmat_x4(Bh4, kHi + bOff + ntp * (16 * KST * 2) + kc * 32);
                ldmat_x4(Bl4, kLo + bOff + ntp * (16 * KST * 2) + kc * 32);
                mma16816h(Sf[2 * ntp],     Qh[kc], Bh4[0], Bh4[1]);
                mma16816h(Sf[2 * ntp],     Qh[kc], Bl4[0], Bl4[1]);
                mma16816h(Sf[2 * ntp],     Ql[kc], Bh4[0], Bh4[1]);
                mma16816h(Sf[2 * ntp + 1], Qh[kc], Bh4[2], Bh4[3]);
                mma16816h(Sf[2 * ntp + 1], Qh[kc], Bl4[2], Bl4[3]);
                mma16816h(Sf[2 * ntp + 1], Ql[kc], Bh4[2], Bh4[3]);
            }
        }

        // ---- scale + alibi + block max
        float bm0 = -1e30f, bm1 = -1e30f;
#pragma unroll
        for (int t = 0; t < 16; t++) {
            const float c0f = (float)(kb * 128 + t * 8 + (lane & 3) * 2);
            const float c1f = c0f + 1.f;
            Sf[t][0] = Sf[t][0] * scale - slope * fabsf(r0f - c0f);
            Sf[t][1] = Sf[t][1] * scale - slope * fabsf(r0f - c1f);
            Sf[t][2] = Sf[t][2] * scale - slope * fabsf(r1f - c0f);
            Sf[t][3] = Sf[t][3] * scale - slope * fabsf(r1f - c1f);
            bm0 = fmaxf(bm0, fmaxf(Sf[t][0], Sf[t][1]));
            bm1 = fmaxf(bm1, fmaxf(Sf[t][2], Sf[t][3]));
        }
        bm0 = fmaxf(bm0, __shfl_xor_sync(~0u, bm0, 1));
        bm0 = fmaxf(bm0, __shfl_xor_sync(~0u, bm0, 2));
        bm1 = fmaxf(bm1, __shfl_xor_sync(~0u, bm1, 1));
        bm1 = fmaxf(bm1, __shfl_xor_sync(~0u, bm1, 2));

        const float mn0 = fmaxf(m0, bm0), mn1 = fmaxf(m1, bm1);
        const float sc0 = __expf(m0 - mn0), sc1 = __expf(m1 - mn1);
        l0 *= sc0; l1 *= sc1;
#pragma unroll
        for (int nt = 0; nt < 8; nt++) {
            Of[nt][0] *= sc0; Of[nt][1] *= sc0;
            Of[nt][2] *= sc1; Of[nt][3] *= sc1;
        }
        m0 = mn0; m1 = mn1;

#pragma unroll
        for (int t = 0; t < 16; t++) {
            Sf[t][0] = __expf(Sf[t][0] - mn0);
            Sf[t][1] = __expf(Sf[t][1] - mn0);
            Sf[t][2] = __expf(Sf[t][2] - mn1);
            Sf[t][3] = __expf(Sf[t][3] - mn1);
            l0 += Sf[t][0] + Sf[t][1];
            l1 += Sf[t][2] + Sf[t][3];
        }

        // ---- P fragments (fp16 hi/lo)
        uint32_t Ph[8][4], Pl[8][4];
#pragma unroll
        for (int kc = 0; kc < 8; kc++) {
            cvt_hilo2h(Sf[2 * kc][0],     Sf[2 * kc][1],     Ph[kc][0], Pl[kc][0]);
            cvt_hilo2h(Sf[2 * kc][2],     Sf[2 * kc][3],     Ph[kc][1], Pl[kc][1]);
            cvt_hilo2h(Sf[2 * kc + 1][0], Sf[2 * kc + 1][1], Ph[kc][2], Pl[kc][2]);
            cvt_hilo2h(Sf[2 * kc + 1][2], Sf[2 * kc + 1][3], Ph[kc][3], Pl[kc][3]);
        }

        // ---- O += P V (3-term fp16)
#pragma unroll
        for (int ntp = 0; ntp < 4; ntp++) {
#pragma unroll
            for (int kc = 0; kc < 8; kc++) {
                uint32_t Vh4[4], Vl4[4];
                ldmat_x4_t(Vh4, vHi + vOff + kc * (16 * KST * 2) + ntp * 32);
                ldmat_x4_t(Vl4, vLo + vOff + kc * (16 * KST * 2) + ntp * 32);
                mma16816h(Of[2 * ntp],     Ph[kc], Vh4[0], Vh4[1]);
                mma16816h(Of[2 * ntp],     Ph[kc], Vl4[0], Vl4[1]);
                mma16816h(Of[2 * ntp],     Pl[kc], Vh4[0], Vh4[1]);
                mma16816h(Of[2 * ntp + 1], Ph[kc], Vh4[2], Vh4[3]);
                mma16816h(Of[2 * ntp + 1], Ph[kc], Vl4[2], Vl4[3]);
                mma16816h(Of[2 * ntp + 1], Pl[kc], Vh4[2], Vh4[3]);
            }
        }
        __syncthreads();   // all reads of this stage done before re-issue
    }

    l0 += __shfl_xor_sync(~0u, l0, 1);
    l0 += __shfl_xor_sync(~0u, l0, 2);
    l1 += __shfl_xor_sync(~0u, l1, 1);
    l1 += __shfl_xor_sync(~0u, l1, 2);
    const float inv0 = 1.f / l0, inv1 = 1.f / l1;

    const int row0 = qrow0 + w * 16 + (lane >> 2);
    __half* ohb = ohi + (size_t)b * Tk * Dk + h * HDk;
    __half* olb = olo + (size_t)b * Tk * Dk + h * HDk;
#pragma unroll
    for (int nt = 0; nt < 8; nt++) {
        const int cc = nt * 8 + (lane & 3) * 2;
        uint32_t hv, lv;
        cvt_hilo2h(Of[nt][0] * inv0, Of[nt][1] * inv0, hv, lv);
        *(uint32_t*)(ohb + (size_t)row0 * Dk + cc) = hv;
        *(uint32_t*)(olb + (size_t)row0 * Dk + cc) = lv;
        cvt_hilo2h(Of[nt][2] * inv1, Of[nt][3] * inv1, hv, lv);
        *(uint32_t*)(ohb + (size_t)(row0 + 8) * Dk + cc) = hv;
        *(uint32_t*)(olb + (size_t)(row0 + 8) * Dk + cc) = lv;
    }
}

// ---------------------------------------------------------------------------
// h = LN(h + o) * g + b; also writes h as fp16 hi/lo for the next GEMM.
// ---------------------------------------------------------------------------
__global__ __launch_bounds__(256) void ln_residual_kernel(
    float* __restrict__ h, const float* __restrict__ o,
    const float* __restrict__ gam, const float* __restrict__ bet,
    __half* __restrict__ hhi, __half* __restrict__ hlo)
{
    __shared__ float rs[8], rs2[8];
    const size_t row = blockIdx.x;
    float* hp = h + row * Dk;
    const float* op = o + row * Dk;
    const int tid = threadIdx.x;

    float4 hv = ((const float4*)hp)[tid];
    float4 ov = ((const float4*)op)[tid];
    float r0 = hv.x + ov.x, r1 = hv.y + ov.y, r2 = hv.z + ov.z, r3 = hv.w + ov.w;

    float s  = r0 + r1 + r2 + r3;
    float s2 = r0 * r0 + r1 * r1 + r2 * r2 + r3 * r3;
#pragma unroll
    for (int of = 16; of; of >>= 1) {
        s  += __shfl_xor_sync(~0u, s,  of);
        s2 += __shfl_xor_sync(~0u, s2, of);
    }
    if ((tid & 31) == 0) { rs[tid >> 5] = s; rs2[tid >> 5] = s2; }
    __syncthreads();
    float S = 0.f, S2 = 0.f;
#pragma unroll
    for (int i = 0; i < 8; i++) { S += rs[i]; S2 += rs2[i]; }

    const float mu  = S * (1.f / (float)Dk);
    const float var = S2 * (1.f / (float)Dk) - mu * mu;
    const float inv = rsqrtf(var + EPSk);

    float4 gg = ((const float4*)gam)[tid];
    float4 bb = ((const float4*)bet)[tid];
    float4 out;
    out.x = (r0 - mu) * inv * gg.x + bb.x;
    out.y = (r1 - mu) * inv * gg.y + bb.y;
    out.z = (r2 - mu) * inv * gg.z + bb.z;
    out.w = (r3 - mu) * inv * gg.w + bb.w;
    ((float4*)hp)[tid] = out;

    uint32_t h0, l0w, h1, l1w;
    cvt_hilo2h(out.x, out.y, h0, l0w);
    cvt_hilo2h(out.z, out.w, h1, l1w);
    *(uint2*)(hhi + row * Dk + tid * 4) = make_uint2(h0, h1);
    *(uint2*)(hlo + row * Dk + tid * 4) = make_uint2(l0w, l1w);
}

// ---------------------------------------------------------------------------
// head
// ---------------------------------------------------------------------------
__global__ void head_kernel(const float* __restrict__ h,
                            const float* __restrict__ hw,
                            const float* __restrict__ hb,
                            float* __restrict__ outp)
{
    const int idx = blockIdx.x;
    const int b = idx / Ck, c = idx % Ck;
    const float* hp = h + ((size_t)b * Tk + (Tk - 1)) * Dk;
    const float* wp = hw + (size_t)c * Dk;
    const int lane = threadIdx.x;
    float s = 0.f;
    for (int i = lane; i < Dk; i += 32) s += hp[i] * wp[i];
#pragma unroll
    for (int o = 16; o; o >>= 1) s += __shfl_xor_sync(~0u, s, o);
    if (lane == 0) outp[idx] = s + hb[c];
}

// ---------------------------------------------------------------------------
// Host orchestration
// ---------------------------------------------------------------------------
extern "C" void kernel_launch(void* const* d_in, const int* in_sizes, int n_in,
                              void* d_out, int out_size)
{
    (void)in_sizes; (void)n_in; (void)out_size;
    const float* x       = (const float*)d_in[0];
    const float* input_w = (const float*)d_in[1];
    const float* input_b = (const float*)d_in[2];
    const float* Wqkv    = (const float*)d_in[3];
    const float* bqkv    = (const float*)d_in[4];
    const float* Wo      = (const float*)d_in[5];
    const float* bo      = (const float*)d_in[6];
    const float* ln1_g   = (const float*)d_in[7];
    const float* ln1_b   = (const float*)d_in[8];
    const float* ln2_g   = (const float*)d_in[9];
    const float* ln2_b   = (const float*)d_in[10];
    const float* W1      = (const float*)d_in[11];
    const float* b1      = (const float*)d_in[12];
    const float* W2      = (const float*)d_in[13];
    const float* b2      = (const float*)d_in[14];
    const float* head_w  = (const float*)d_in[15];
    const float* head_b  = (const float*)d_in[16];
    float* outp = (float*)d_out;

    float *h, *tmp;
    __half *xhi, *xlo, *hhi, *hlo, *ohi, *olo, *fhi, *flo, *qhi, *qlo;
    __half *winh, *wqh, *woh, *w1h, *w2h;
    cudaGetSymbolAddress((void**)&h,    g_h);
    cudaGetSymbolAddress((void**)&tmp,  g_tmp);
    cudaGetSymbolAddress((void**)&xhi,  g_x_hi);  cudaGetSymbolAddress((void**)&xlo,  g_x_lo);
    cudaGetSymbolAddress((void**)&hhi,  g_h_hi);  cudaGetSymbolAddress((void**)&hlo,  g_h_lo);
    cudaGetSymbolAddress((void**)&ohi,  g_o_hi);  cudaGetSymbolAddress((void**)&olo,  g_o_lo);
    cudaGetSymbolAddress((void**)&fhi,  g_ff_hi); cudaGetSymbolAddress((void**)&flo,  g_ff_lo);
    cudaGetSymbolAddress((void**)&qhi,  g_qkv_hi); cudaGetSymbolAddress((void**)&qlo, g_qkv_lo);
    cudaGetSymbolAddress((void**)&winh, g_win_h);
    cudaGetSymbolAddress((void**)&wqh,  g_wqkv_h);
    cudaGetSymbolAddress((void**)&woh,  g_wo_h);
    cudaGetSymbolAddress((void**)&w1h,  g_w1_h);
    cudaGetSymbolAddress((void**)&w2h,  g_w2_h);

    cudaFuncSetAttribute(mma_gemm_f16_nt,
                         cudaFuncAttributeMaxDynamicSharedMemorySize, GEMM_SMEM);
    cudaFuncSetAttribute(flash_attn_kernel,
                         cudaFuncAttributeMaxDynamicSharedMemorySize, FLASH_SMEM);

    const int M = Bk * Tk;  // 4096
    dim3 blk(256);

    // ---- conversions: x -> fp16 hi/lo, weights -> fp16
    cvt_hl16_kernel<<<(Bk * Tk * INk) / 1024, 256>>>(x, xhi, xlo, Bk * Tk * INk);
    cvt_h16_kernel<<<(Dk * INk) / 1024, 256>>>(input_w, winh, Dk * INk);
    cvt_h16_kernel<<<(Lk * D3k * Dk) / 1024, 256>>>(Wqkv, wqh, Lk * D3k * Dk);
    cvt_h16_kernel<<<(Lk * Dk * Dk) / 1024, 256>>>(Wo, woh, Lk * Dk * Dk);
    cvt_h16_kernel<<<(Lk * FFk * Dk) / 1024, 256>>>(W1, w1h, Lk * FFk * Dk);
    cvt_h16_kernel<<<(Lk * Dk * FFk) / 1024, 256>>>(W2, w2h, Lk * Dk * FFk);

    // ---- input projection: h (fp32) + h hi/lo
    mma_gemm_f16_nt<<<dim3(Dk / 128, M / 128), blk, GEMM_SMEM>>>(
        xhi, xlo, INk, winh, INk, input_b, h, hhi, hlo, Dk, INk, 2 | 4);

    for (int l = 0; l < Lk; l++) {
        // qkv -> fp16 hi/lo (feeds flash directly)
        mma_gemm_f16_nt<<<dim3(D3k / 128, M / 128), blk, GEMM_SMEM>>>(
            hhi, hlo, Dk, wqh + (size_t)l * D3k * Dk, Dk,
            bqkv + (size_t)l * D3k, nullptr, qhi, qlo, D3k, Dk, 4);
        // attention -> o hi/lo
        flash_attn_kernel<<<dim3(Tk / 128, Bk * Hk), blk, FLASH_SMEM>>>(qhi, qlo, ohi, olo);
        // Wo proj (fp32 out)
        mma_gemm_f16_nt<<<dim3(Dk / 128, M / 128), blk, GEMM_SMEM>>>(
            ohi, olo, Dk, woh + (size_t)l * Dk * Dk, Dk,
            bo + (size_t)l * Dk, tmp, nullptr, nullptr, Dk, Dk, 2);
        // LN1 -> h fp32 + h hi/lo
        ln_residual_kernel<<<M, 256>>>(h, tmp, ln1_g + (size_t)l * Dk, ln1_b + (size_t)l * Dk,
                                       hhi, hlo);
        // FF1 (relu, hi/lo out only)
        mma_gemm_f16_nt<<<dim3(FFk / 128, M / 128), blk, GEMM_SMEM>>>(
            hhi, hlo, Dk, w1h + (size_t)l * FFk * Dk, Dk,
            b1 + (size_t)l * FFk, nullptr, fhi, flo, FFk, Dk, 1 | 4);
        // FF2 (fp32 out)
        mma_gemm_f16_nt<<<dim3(Dk / 128, M / 128), blk, GEMM_SMEM>>>(
            fhi, flo, FFk, w2h + (size_t)l * Dk * FFk, FFk,
            b2 + (size_t)l * Dk, tmp, nullptr, nullptr, Dk, FFk, 2);
        // LN2 -> h fp32 + h hi/lo
        ln_residual_kernel<<<M, 256>>>(h, tmp, ln2_g + (size_t)l * Dk, ln2_b + (size_t)l * Dk,
                                       hhi, hlo);
    }

    head_kernel<<<Bk * Ck, 32>>>(h, head_w, head_b, outp);
}

// round 13
// speedup vs baseline: 4.7731x; 1.4374x over previous
#include <cuda_runtime.h>
#include <cuda_fp16.h>
#include <math.h>
#include <stdint.h>

// ---------------------------------------------------------------------------
// Problem constants
// ---------------------------------------------------------------------------
namespace {
constexpr int Bk = 4;       // batch
constexpr int Tk = 1024;    // seq len
constexpr int INk = 256;    // input dim
constexpr int Dk = 1024;    // model dim
constexpr int Hk = 16;      // heads
constexpr int HDk = 64;     // head dim
constexpr int FFk = 4096;   // ff dim
constexpr int Ck = 10;      // classes
constexpr int Lk = 6;       // layers
constexpr int D3k = 3 * Dk;
constexpr float EPSk = 1e-5f;
}

// ---------------------------------------------------------------------------
// Scratch buffers (static device globals — no allocations allowed)
// ---------------------------------------------------------------------------
__device__ float g_h[Bk * Tk * Dk];
__device__ float g_tmp[Bk * Tk * Dk];

// single fp16 activation buffers
__device__ __half g_x_h[Bk * Tk * INk];
__device__ __half g_h_h[Bk * Tk * Dk];
__device__ __half g_o_h[Bk * Tk * Dk];
__device__ __half g_ff_h[Bk * Tk * FFk];
// qkv kept hi/lo (feeds 3-term flash attention)
__device__ __half g_qkv_hi[Bk * Tk * D3k], g_qkv_lo[Bk * Tk * D3k];

// fp16 weight buffers (single rounding)
__device__ __half g_win_h[Dk * INk];
__device__ __half g_wqkv_h[Lk * D3k * Dk];
__device__ __half g_wo_h[Lk * Dk * Dk];
__device__ __half g_w1_h[Lk * FFk * Dk];
__device__ __half g_w2_h[Lk * Dk * FFk];

// ---------------------------------------------------------------------------
// PTX helpers (sm_80-era features only — compile on base sm_100)
// ---------------------------------------------------------------------------
__device__ __forceinline__ uint32_t smem_u32(const void* p) {
    uint32_t a;
    asm("{ .reg .u64 t; cvta.to.shared.u64 t, %1; cvt.u32.u64 %0, t; }"
        : "=r"(a) : "l"(p));
    return a;
}

__device__ __forceinline__ void ldmat_x4(uint32_t* r, uint32_t addr) {
    asm volatile("ldmatrix.sync.aligned.m8n8.x4.shared.b16 {%0,%1,%2,%3}, [%4];"
                 : "=r"(r[0]), "=r"(r[1]), "=r"(r[2]), "=r"(r[3]) : "r"(addr));
}

__device__ __forceinline__ void ldmat_x4_t(uint32_t* r, uint32_t addr) {
    asm volatile("ldmatrix.sync.aligned.m8n8.x4.trans.shared.b16 {%0,%1,%2,%3}, [%4];"
                 : "=r"(r[0]), "=r"(r[1]), "=r"(r[2]), "=r"(r[3]) : "r"(addr));
}

// fp16 mma
__device__ __forceinline__ void mma16816h(float* c, const uint32_t* a,
                                          uint32_t b0, uint32_t b1) {
    asm volatile(
        "mma.sync.aligned.m16n8k16.row.col.f32.f16.f16.f32 "
        "{%0,%1,%2,%3}, {%4,%5,%6,%7}, {%8,%9}, {%0,%1,%2,%3};"
        : "+f"(c[0]), "+f"(c[1]), "+f"(c[2]), "+f"(c[3])
        : "r"(a[0]), "r"(a[1]), "r"(a[2]), "r"(a[3]), "r"(b0), "r"(b1));
}

__device__ __forceinline__ void sts128(uint32_t addr, uint4 v) {
    asm volatile("st.shared.v4.b32 [%0], {%1,%2,%3,%4};"
                 :: "r"(addr), "r"(v.x), "r"(v.y), "r"(v.z), "r"(v.w) : "memory");
}

__device__ __forceinline__ void cp_async16(uint32_t saddr, const void* gptr) {
    asm volatile("cp.async.cg.shared.global [%0], [%1], 16;"
                 :: "r"(saddr), "l"(gptr) : "memory");
}
#define CP_COMMIT() asm volatile("cp.async.commit_group;" ::: "memory")
#define CP_WAIT1()  asm volatile("cp.async.wait_group 1;" ::: "memory")
#define CP_WAIT0()  asm volatile("cp.async.wait_group 0;" ::: "memory")

// ---- fp16 hi/lo split
__device__ __forceinline__ void cvt_hilo2h(float a, float b, uint32_t& hi, uint32_t& lo) {
    __half2 h = __floats2half2_rn(a, b);
    float2 hf = __half22float2(h);
    __half2 l = __floats2half2_rn(a - hf.x, b - hf.y);
    hi = *reinterpret_cast<uint32_t*>(&h);
    lo = *reinterpret_cast<uint32_t*>(&l);
}

__device__ __forceinline__ uint32_t cvt_h2(float a, float b) {
    __half2 h = __floats2half2_rn(a, b);
    return *reinterpret_cast<uint32_t*>(&h);
}

// ---------------------------------------------------------------------------
// Conversion kernel (fp32 -> fp16)
// ---------------------------------------------------------------------------
__global__ __launch_bounds__(256) void cvt_h16_kernel(
    const float* __restrict__ src, __half* __restrict__ dst, int n)
{
    const int i = (blockIdx.x * 256 + threadIdx.x) * 4;
    if (i >= n) return;
    float4 v = *(const float4*)(src + i);
    *(uint2*)(dst + i) = make_uint2(cvt_h2(v.x, v.y), cvt_h2(v.z, v.w));
}

// ---------------------------------------------------------------------------
// fp16 single-term NT GEMM: C = A * W^T + bias.
// 128x128 tile, BK=32, 3-stage cp.async, 2 CTAs/SM.
// flags: 1=relu, 2=write fp32 C, 4=write fp16 hi/lo C, 8=write fp16 C
// ---------------------------------------------------------------------------
namespace {
constexpr int SST = 40;                        // smem row stride (fp16)
constexpr int ARR_B = 128 * SST * 2;           // 10240 bytes per tile array
constexpr int STAGE_B = 2 * ARR_B;             // A|B = 20480 bytes
}
static constexpr int GEMM_SMEM = 3 * STAGE_B;  // 61440

__global__ __launch_bounds__(256, 2) void mma_gemm_f16_nt(
    const __half* __restrict__ Ah, int lda,
    const __half* __restrict__ Bh, int ldb,
    const float* __restrict__ bias,
    float* __restrict__ Cf, __half* __restrict__ Chi, __half* __restrict__ Clo,
    int ldc, int K, int flags)
{
    extern __shared__ __align__(16) char gsm[];
    const uint32_t base = smem_u32(gsm);

    const int tid  = threadIdx.x;
    const int lane = tid & 31;
    const int wid  = tid >> 5;
    const int wm   = wid & 3;
    const int wn   = wid >> 2;
    const int row0 = blockIdx.y * 128;
    const int col0 = blockIdx.x * 128;

    const int grow = tid >> 1;
    const int gc16 = (tid & 1) * 16;
    const __half* Ah_p = Ah + (size_t)(row0 + grow) * lda + gc16;
    const __half* Bh_p = Bh + (size_t)(col0 + grow) * ldb + gc16;
    const uint32_t soff = grow * (SST * 2) + gc16 * 2;

    const uint32_t aRowOff = (uint32_t)((wm * 32 + (lane & 15)) * SST * 2 + (lane >> 4) * 16);
    const uint32_t bRowOff = (uint32_t)(((wn * 64 + ((lane >> 4) << 3) + (lane & 7)) * SST) * 2
                                        + ((lane >> 3) & 1) * 16);

    float acc[2][8][4];
#pragma unroll
    for (int i = 0; i < 2; i++)
#pragma unroll
        for (int j = 0; j < 8; j++)
#pragma unroll
            for (int q = 0; q < 4; q++) acc[i][j][q] = 0.f;

    const int nc = K >> 5;

    auto issue = [&](int c, int s) {
        const uint32_t sb = base + s * STAGE_B;
        const __half* p = Ah_p + c * 32;
        cp_async16(sb + soff, p);                 cp_async16(sb + soff + 16, p + 8);
        p = Bh_p + c * 32;
        cp_async16(sb + ARR_B + soff, p);         cp_async16(sb + ARR_B + soff + 16, p + 8);
        CP_COMMIT();
    };

    issue(0, 0);
    if (nc > 1) issue(1, 1);

    for (int c = 0; c < nc; c++) {
        if (c + 1 < nc) { CP_WAIT1(); }
        else            { CP_WAIT0(); }
        __syncthreads();
        if (c + 2 < nc) issue(c + 2, (c + 2) % 3);

        const uint32_t sb = base + (c % 3) * STAGE_B;
        const uint32_t aS = sb, bS = sb + ARR_B;

#pragma unroll
        for (int ks = 0; ks < 2; ks++) {
            const uint32_t kb = ks * 32;
            uint32_t A4[2][4];
#pragma unroll
            for (int mt = 0; mt < 2; mt++)
                ldmat_x4(A4[mt], aS + aRowOff + mt * (16 * SST * 2) + kb);
#pragma unroll
            for (int pr = 0; pr < 4; pr++) {
                uint32_t B4[4];
                ldmat_x4(B4, bS + bRowOff + pr * (16 * SST * 2) + kb);
#pragma unroll
                for (int sbb = 0; sbb < 2; sbb++) {
                    const int nt = pr * 2 + sbb;
#pragma unroll
                    for (int mt = 0; mt < 2; mt++)
                        mma16816h(acc[mt][nt], A4[mt], B4[sbb * 2], B4[sbb * 2 + 1]);
                }
            }
        }
    }
    __syncthreads();

    // ---- epilogue
    const int erow = lane >> 2;
    const int ecol = (lane & 3) * 2;
    const int relu = flags & 1;
#pragma unroll
    for (int mt = 0; mt < 2; mt++) {
        const int r = row0 + wm * 32 + mt * 16 + erow;
#pragma unroll
        for (int nt = 0; nt < 8; nt++) {
            const int cc = col0 + wn * 64 + nt * 8 + ecol;
            float2 bv = *(const float2*)(bias + cc);
            float2 v0, v1;
            v0.x = acc[mt][nt][0] + bv.x;  v0.y = acc[mt][nt][1] + bv.y;
            v1.x = acc[mt][nt][2] + bv.x;  v1.y = acc[mt][nt][3] + bv.y;
            if (relu) {
                v0.x = fmaxf(v0.x, 0.f); v0.y = fmaxf(v0.y, 0.f);
                v1.x = fmaxf(v1.x, 0.f); v1.y = fmaxf(v1.y, 0.f);
            }
            if (flags & 2) {
                *(float2*)(Cf + (size_t)r * ldc + cc)       = v0;
                *(float2*)(Cf + (size_t)(r + 8) * ldc + cc) = v1;
            }
            if (flags & 4) {
                uint32_t hv, lv;
                cvt_hilo2h(v0.x, v0.y, hv, lv);
                *(uint32_t*)(Chi + (size_t)r * ldc + cc) = hv;
                *(uint32_t*)(Clo + (size_t)r * ldc + cc) = lv;
                cvt_hilo2h(v1.x, v1.y, hv, lv);
                *(uint32_t*)(Chi + (size_t)(r + 8) * ldc + cc) = hv;
                *(uint32_t*)(Clo + (size_t)(r + 8) * ldc + cc) = lv;
            }
            if (flags & 8) {
                *(uint32_t*)(Chi + (size_t)r * ldc + cc)       = cvt_h2(v0.x, v0.y);
                *(uint32_t*)(Chi + (size_t)(r + 8) * ldc + cc) = cvt_h2(v1.x, v1.y);
            }
        }
    }
}

// ---------------------------------------------------------------------------
// Fused flash attention on pre-split fp16 hi/lo qkv (3-term fp16 MMAs).
// K/V via cp.async 3-stage ring. Output: single fp16 o.
// ---------------------------------------------------------------------------
namespace {
constexpr int KST   = 72;                 // smem row stride (fp16)
constexpr int ARR_F = 128 * KST * 2;      // 18432 bytes per array
constexpr int STAGE_F = 4 * ARR_F;        // Khi|Klo|Vhi|Vlo = 73728
}
static constexpr int FLASH_SMEM = 3 * STAGE_F;   // 221184

__global__ __launch_bounds__(256) void flash_attn_kernel(
    const __half* __restrict__ qkvhi, const __half* __restrict__ qkvlo,
    __half* __restrict__ oh)
{
    extern __shared__ __align__(16) char fsm[];
    const uint32_t fbase = smem_u32(fsm);

    const int tid  = threadIdx.x;
    const int lane = tid & 31;
    const int w    = tid >> 5;
    const int bh = blockIdx.y;
    const int b = bh >> 4, h = bh & 15;
    const int qrow0 = blockIdx.x * 128;

    const size_t hd_off = (size_t)b * Tk * D3k + h * HDk;

    float slope = 0.f;
#pragma unroll
    for (int i = 1; i <= Hk; i++) slope += exp2f(-0.5f * (float)i);
    slope *= (1.f / (float)Hk);
    const float scale = 0.125f;

    const int grow = tid >> 1;
    const int gcol = (tid & 1) * 32;
    const uint32_t gso = grow * (KST * 2) + gcol * 2;

    // ---- stage Q (hi/lo fp16) into stage-2 K slots
    {
        const uint32_t q_hi = fbase + 2 * STAGE_F;
        const uint32_t q_lo = q_hi + ARR_F;
        const __half* qh = qkvhi + hd_off + (size_t)(qrow0 + grow) * D3k + gcol;
        const __half* ql = qkvlo + hd_off + (size_t)(qrow0 + grow) * D3k + gcol;
#pragma unroll
        for (int j = 0; j < 4; j++) {
            sts128(q_hi + gso + j * 16, *(const uint4*)(qh + j * 8));
            sts128(q_lo + gso + j * 16, *(const uint4*)(ql + j * 8));
        }
    }
    __syncthreads();

    uint32_t Qh[4][4], Ql[4][4];
    {
        const uint32_t q_hi = fbase + 2 * STAGE_F;
        const uint32_t q_lo = q_hi + ARR_F;
        const uint32_t qOff = (w * 16 + (lane & 15)) * (KST * 2) + (lane >> 4) * 16;
#pragma unroll
        for (int kc = 0; kc < 4; kc++) {
            ldmat_x4(Qh[kc], q_hi + qOff + kc * 32);
            ldmat_x4(Ql[kc], q_lo + qOff + kc * 32);
        }
    }
    __syncthreads();   // Q reads done before stage-2 gets overwritten

    const __half* Khi_p = qkvhi + hd_off + Dk     + (size_t)grow * D3k + gcol;
    const __half* Klo_p = qkvlo + hd_off + Dk     + (size_t)grow * D3k + gcol;
    const __half* Vhi_p = qkvhi + hd_off + 2 * Dk + (size_t)grow * D3k + gcol;
    const __half* Vlo_p = qkvlo + hd_off + 2 * Dk + (size_t)grow * D3k + gcol;

    auto issueKV = [&](int kb, int s) {
        const uint32_t sb = fbase + s * STAGE_F;
        const size_t off = (size_t)(kb * 128) * D3k;
#pragma unroll
        for (int j = 0; j < 4; j++) {
            cp_async16(sb + gso + j * 16,               Khi_p + off + j * 8);
            cp_async16(sb + ARR_F + gso + j * 16,       Klo_p + off + j * 8);
            cp_async16(sb + 2 * ARR_F + gso + j * 16,   Vhi_p + off + j * 8);
            cp_async16(sb + 3 * ARR_F + gso + j * 16,   Vlo_p + off + j * 8);
        }
        CP_COMMIT();
    };

    const uint32_t bOff = (((lane >> 4) << 3) + (lane & 7)) * (KST * 2) + ((lane >> 3) & 1) * 16;
    const uint32_t vOff = ((lane & 7) + ((lane >> 3) & 1) * 8) * (KST * 2) + (lane >> 4) * 16;

    float Of[8][4];
#pragma unroll
    for (int i = 0; i < 8; i++)
#pragma unroll
        for (int q = 0; q < 4; q++) Of[i][q] = 0.f;
    float m0 = -1e30f, m1 = -1e30f, l0 = 0.f, l1 = 0.f;

    const float r0f = (float)(qrow0 + w * 16 + (lane >> 2));
    const float r1f = r0f + 8.f;

    constexpr int NKB = Tk / 128;   // 8
    issueKV(0, 0);
    issueKV(1, 1);

    for (int kb = 0; kb < NKB; kb++) {
        if (kb + 1 < NKB) { CP_WAIT1(); }
        else              { CP_WAIT0(); }
        __syncthreads();
        if (kb + 2 < NKB) issueKV(kb + 2, (kb + 2) % 3);

        const uint32_t sb  = fbase + (kb % 3) * STAGE_F;
        const uint32_t kHi = sb, kLo = sb + ARR_F, vHi = sb + 2 * ARR_F, vLo = sb + 3 * ARR_F;

        float Sf[16][4];
#pragma unroll
        for (int ntp = 0; ntp < 8; ntp++) {
#pragma unroll
            for (int q = 0; q < 4; q++) { Sf[2 * ntp][q] = 0.f; Sf[2 * ntp + 1][q] = 0.f; }
#pragma unroll
            for (int kc = 0; kc < 4; kc++) {
                uint32_t Bh4[4], Bl4[4];
                ldmat_x4(Bh4, kHi + bOff + ntp * (16 * KST * 2) + kc * 32);
                ldmat_x4(Bl4, kLo + bOff + ntp * (16 * KST * 2) + kc * 32);
                mma16816h(Sf[2 * ntp],     Qh[kc], Bh4[0], Bh4[1]);
                mma16816h(Sf[2 * ntp],     Qh[kc], Bl4[0], Bl4[1]);
                mma16816h(Sf[2 * ntp],     Ql[kc], Bh4[0], Bh4[1]);
                mma16816h(Sf[2 * ntp + 1], Qh[kc], Bh4[2], Bh4[3]);
                mma16816h(Sf[2 * ntp + 1], Qh[kc], Bl4[2], Bl4[3]);
                mma16816h(Sf[2 * ntp + 1], Ql[kc], Bh4[2], Bh4[3]);
            }
        }

        float bm0 = -1e30f, bm1 = -1e30f;
#pragma unroll
        for (int t = 0; t < 16; t++) {
            const float c0f = (float)(kb * 128 + t * 8 + (lane & 3) * 2);
            const float c1f = c0f + 1.f;
            Sf[t][0] = Sf[t][0] * scale - slope * fabsf(r0f - c0f);
            Sf[t][1] = Sf[t][1] * scale - slope * fabsf(r0f - c1f);
            Sf[t][2] = Sf[t][2] * scale - slope * fabsf(r1f - c0f);
            Sf[t][3] = Sf[t][3] * scale - slope * fabsf(r1f - c1f);
            bm0 = fmaxf(bm0, fmaxf(Sf[t][0], Sf[t][1]));
            bm1 = fmaxf(bm1, fmaxf(Sf[t][2], Sf[t][3]));
        }
        bm0 = fmaxf(bm0, __shfl_xor_sync(~0u, bm0, 1));
        bm0 = fmaxf(bm0, __shfl_xor_sync(~0u, bm0, 2));
        bm1 = fmaxf(bm1, __shfl_xor_sync(~0u, bm1, 1));
        bm1 = fmaxf(bm1, __shfl_xor_sync(~0u, bm1, 2));

        const float mn0 = fmaxf(m0, bm0), mn1 = fmaxf(m1, bm1);
        const float sc0 = __expf(m0 - mn0), sc1 = __expf(m1 - mn1);
        l0 *= sc0; l1 *= sc1;
#pragma unroll
        for (int nt = 0; nt < 8; nt++) {
            Of[nt][0] *= sc0; Of[nt][1] *= sc0;
            Of[nt][2] *= sc1; Of[nt][3] *= sc1;
        }
        m0 = mn0; m1 = mn1;

#pragma unroll
        for (int t = 0; t < 16; t++) {
            Sf[t][0] = __expf(Sf[t][0] - mn0);
            Sf[t][1] = __expf(Sf[t][1] - mn0);
            Sf[t][2] = __expf(Sf[t][2] - mn1);
            Sf[t][3] = __expf(Sf[t][3] - mn1);
            l0 += Sf[t][0] + Sf[t][1];
            l1 += Sf[t][2] + Sf[t][3];
        }

        uint32_t Ph[8][4], Pl[8][4];
#pragma unroll
        for (int kc = 0; kc < 8; kc++) {
            cvt_hilo2h(Sf[2 * kc][0],     Sf[2 * kc][1],     Ph[kc][0], Pl[kc][0]);
            cvt_hilo2h(Sf[2 * kc][2],     Sf[2 * kc][3],     Ph[kc][1], Pl[kc][1]);
            cvt_hilo2h(Sf[2 * kc + 1][0], Sf[2 * kc + 1][1], Ph[kc][2], Pl[kc][2]);
            cvt_hilo2h(Sf[2 * kc + 1][2], Sf[2 * kc + 1][3], Ph[kc][3], Pl[kc][3]);
        }

#pragma unroll
        for (int ntp = 0; ntp < 4; ntp++) {
#pragma unroll
            for (int kc = 0; kc < 8; kc++) {
                uint32_t Vh4[4], Vl4[4];
                ldmat_x4_t(Vh4, vHi + vOff + kc * (16 * KST * 2) + ntp * 32);
                ldmat_x4_t(Vl4, vLo + vOff + kc * (16 * KST * 2) + ntp * 32);
                mma16816h(Of[2 * ntp],     Ph[kc], Vh4[0], Vh4[1]);
                mma16816h(Of[2 * ntp],     Ph[kc], Vl4[0], Vl4[1]);
                mma16816h(Of[2 * ntp],     Pl[kc], Vh4[0], Vh4[1]);
                mma16816h(Of[2 * ntp + 1], Ph[kc], Vh4[2], Vh4[3]);
                mma16816h(Of[2 * ntp + 1], Ph[kc], Vl4[2], Vl4[3]);
                mma16816h(Of[2 * ntp + 1], Pl[kc], Vh4[2], Vh4[3]);
            }
        }
        __syncthreads();
    }

    l0 += __shfl_xor_sync(~0u, l0, 1);
    l0 += __shfl_xor_sync(~0u, l0, 2);
    l1 += __shfl_xor_sync(~0u, l1, 1);
    l1 += __shfl_xor_sync(~0u, l1, 2);
    const float inv0 = 1.f / l0, inv1 = 1.f / l1;

    const int row0 = qrow0 + w * 16 + (lane >> 2);
    __half* ohb = oh + (size_t)b * Tk * Dk + h * HDk;
#pragma unroll
    for (int nt = 0; nt < 8; nt++) {
        const int cc = nt * 8 + (lane & 3) * 2;
        *(uint32_t*)(ohb + (size_t)row0 * Dk + cc) =
            cvt_h2(Of[nt][0] * inv0, Of[nt][1] * inv0);
        *(uint32_t*)(ohb + (size_t)(row0 + 8) * Dk + cc) =
            cvt_h2(Of[nt][2] * inv1, Of[nt][3] * inv1);
    }
}

// ---------------------------------------------------------------------------
// h = LN(h + o) * g + b; also writes h as single fp16 for the next GEMM.
// ---------------------------------------------------------------------------
__global__ __launch_bounds__(256) void ln_residual_kernel(
    float* __restrict__ h, const float* __restrict__ o,
    const float* __restrict__ gam, const float* __restrict__ bet,
    __half* __restrict__ hh)
{
    __shared__ float rs[8], rs2[8];
    const size_t row = blockIdx.x;
    float* hp = h + row * Dk;
    const float* op = o + row * Dk;
    const int tid = threadIdx.x;

    float4 hv = ((const float4*)hp)[tid];
    float4 ov = ((const float4*)op)[tid];
    float r0 = hv.x + ov.x, r1 = hv.y + ov.y, r2 = hv.z + ov.z, r3 = hv.w + ov.w;

    float s  = r0 + r1 + r2 + r3;
    float s2 = r0 * r0 + r1 * r1 + r2 * r2 + r3 * r3;
#pragma unroll
    for (int of = 16; of; of >>= 1) {
        s  += __shfl_xor_sync(~0u, s,  of);
        s2 += __shfl_xor_sync(~0u, s2, of);
    }
    if ((tid & 31) == 0) { rs[tid >> 5] = s; rs2[tid >> 5] = s2; }
    __syncthreads();
    float S = 0.f, S2 = 0.f;
#pragma unroll
    for (int i = 0; i < 8; i++) { S += rs[i]; S2 += rs2[i]; }

    const float mu  = S * (1.f / (float)Dk);
    const float var = S2 * (1.f / (float)Dk) - mu * mu;
    const float inv = rsqrtf(var + EPSk);

    float4 gg = ((const float4*)gam)[tid];
    float4 bb = ((const float4*)bet)[tid];
    float4 out;
    out.x = (r0 - mu) * inv * gg.x + bb.x;
    out.y = (r1 - mu) * inv * gg.y + bb.y;
    out.z = (r2 - mu) * inv * gg.z + bb.z;
    out.w = (r3 - mu) * inv * gg.w + bb.w;
    ((float4*)hp)[tid] = out;

    *(uint2*)(hh + row * Dk + tid * 4) =
        make_uint2(cvt_h2(out.x, out.y), cvt_h2(out.z, out.w));
}

// ---------------------------------------------------------------------------
// head
// ---------------------------------------------------------------------------
__global__ void head_kernel(const float* __restrict__ h,
                            const float* __restrict__ hw,
                            const float* __restrict__ hb,
                            float* __restrict__ outp)
{
    const int idx = blockIdx.x;
    const int b = idx / Ck, c = idx % Ck;
    const float* hp = h + ((size_t)b * Tk + (Tk - 1)) * Dk;
    const float* wp = hw + (size_t)c * Dk;
    const int lane = threadIdx.x;
    float s = 0.f;
    for (int i = lane; i < Dk; i += 32) s += hp[i] * wp[i];
#pragma unroll
    for (int o = 16; o; o >>= 1) s += __shfl_xor_sync(~0u, s, o);
    if (lane == 0) outp[idx] = s + hb[c];
}

// ---------------------------------------------------------------------------
// Host orchestration
// ---------------------------------------------------------------------------
extern "C" void kernel_launch(void* const* d_in, const int* in_sizes, int n_in,
                              void* d_out, int out_size)
{
    (void)in_sizes; (void)n_in; (void)out_size;
    const float* x       = (const float*)d_in[0];
    const float* input_w = (const float*)d_in[1];
    const float* input_b = (const float*)d_in[2];
    const float* Wqkv    = (const float*)d_in[3];
    const float* bqkv    = (const float*)d_in[4];
    const float* Wo      = (const float*)d_in[5];
    const float* bo      = (const float*)d_in[6];
    const float* ln1_g   = (const float*)d_in[7];
    const float* ln1_b   = (const float*)d_in[8];
    const float* ln2_g   = (const float*)d_in[9];
    const float* ln2_b   = (const float*)d_in[10];
    const float* W1      = (const float*)d_in[11];
    const float* b1      = (const float*)d_in[12];
    const float* W2      = (const float*)d_in[13];
    const float* b2      = (const float*)d_in[14];
    const float* head_w  = (const float*)d_in[15];
    const float* head_b  = (const float*)d_in[16];
    float* outp = (float*)d_out;

    float *h, *tmp;
    __half *xh, *hh, *oh, *fh, *qhi, *qlo;
    __half *winh, *wqh, *woh, *w1h, *w2h;
    cudaGetSymbolAddress((void**)&h,    g_h);
    cudaGetSymbolAddress((void**)&tmp,  g_tmp);
    cudaGetSymbolAddress((void**)&xh,   g_x_h);
    cudaGetSymbolAddress((void**)&hh,   g_h_h);
    cudaGetSymbolAddress((void**)&oh,   g_o_h);
    cudaGetSymbolAddress((void**)&fh,   g_ff_h);
    cudaGetSymbolAddress((void**)&qhi,  g_qkv_hi); cudaGetSymbolAddress((void**)&qlo, g_qkv_lo);
    cudaGetSymbolAddress((void**)&winh, g_win_h);
    cudaGetSymbolAddress((void**)&wqh,  g_wqkv_h);
    cudaGetSymbolAddress((void**)&woh,  g_wo_h);
    cudaGetSymbolAddress((void**)&w1h,  g_w1_h);
    cudaGetSymbolAddress((void**)&w2h,  g_w2_h);

    cudaFuncSetAttribute(mma_gemm_f16_nt,
                         cudaFuncAttributeMaxDynamicSharedMemorySize, GEMM_SMEM);
    cudaFuncSetAttribute(flash_attn_kernel,
                         cudaFuncAttributeMaxDynamicSharedMemorySize, FLASH_SMEM);

    const int M = Bk * Tk;  // 4096
    dim3 blk(256);

    // ---- conversions: x, weights -> fp16
    cvt_h16_kernel<<<(Bk * Tk * INk) / 1024, 256>>>(x, xh, Bk * Tk * INk);
    cvt_h16_kernel<<<(Dk * INk) / 1024, 256>>>(input_w, winh, Dk * INk);
    cvt_h16_kernel<<<(Lk * D3k * Dk) / 1024, 256>>>(Wqkv, wqh, Lk * D3k * Dk);
    cvt_h16_kernel<<<(Lk * Dk * Dk) / 1024, 256>>>(Wo, woh, Lk * Dk * Dk);
    cvt_h16_kernel<<<(Lk * FFk * Dk) / 1024, 256>>>(W1, w1h, Lk * FFk * Dk);
    cvt_h16_kernel<<<(Lk * Dk * FFk) / 1024, 256>>>(W2, w2h, Lk * Dk * FFk);

    // ---- input projection: h (fp32) + h fp16
    mma_gemm_f16_nt<<<dim3(Dk / 128, M / 128), blk, GEMM_SMEM>>>(
        xh, INk, winh, INk, input_b, h, hh, nullptr, Dk, INk, 2 | 8);

    for (int l = 0; l < Lk; l++) {
        // qkv -> fp16 hi/lo (feeds 3-term flash)
        mma_gemm_f16_nt<<<dim3(D3k / 128, M / 128), blk, GEMM_SMEM>>>(
            hh, Dk, wqh + (size_t)l * D3k * Dk, Dk,
            bqkv + (size_t)l * D3k, nullptr, qhi, qlo, D3k, Dk, 4);
        // attention -> o fp16
        flash_attn_kernel<<<dim3(Tk / 128, Bk * Hk), blk, FLASH_SMEM>>>(qhi, qlo, oh);
        // Wo proj (fp32 out)
        mma_gemm_f16_nt<<<dim3(Dk / 128, M / 128), blk, GEMM_SMEM>>>(
            oh, Dk, woh + (size_t)l * Dk * Dk, Dk,
            bo + (size_t)l * Dk, tmp, nullptr, nullptr, Dk, Dk, 2);
        // LN1 -> h fp32 + h fp16
        ln_residual_kernel<<<M, 256>>>(h, tmp, ln1_g + (size_t)l * Dk, ln1_b + (size_t)l * Dk, hh);
        // FF1 (relu, fp16 out)
        mma_gemm_f16_nt<<<dim3(FFk / 128, M / 128), blk, GEMM_SMEM>>>(
            hh, Dk, w1h + (size_t)l * FFk * Dk, Dk,
            b1 + (size_t)l * FFk, nullptr, fh, nullptr, FFk, Dk, 1 | 8);
        // FF2 (fp32 out)
        mma_gemm_f16_nt<<<dim3(Dk / 128, M / 128), blk, GEMM_SMEM>>>(
            fh, FFk, w2h + (size_t)l * Dk * FFk, FFk,
            b2 + (size_t)l * Dk, tmp, nullptr, nullptr, Dk, FFk, 2);
        // LN2 -> h fp32 + h fp16
        ln_residual_kernel<<<M, 256>>>(h, tmp, ln2_g + (size_t)l * Dk, ln2_b + (size_t)l * Dk, hh);
    }

    head_kernel<<<Bk * Ck, 32>>>(h, head_w, head_b, outp);
}